// round 1
// baseline (speedup 1.0000x reference)
#include <cuda_runtime.h>
#include <math.h>

#define BB   8
#define SS   1024
#define DD   512
#define HH   8
#define WW   8
#define S2S  1040
#define DKK  64

// ---------------- scratch (device globals; no allocation) ----------------
__device__ float g_new_in[BB * S2S * DD];                 // (B,S2,D)
__device__ float g_ql[BB * S2S * DD];
__device__ float g_kl[BB * S2S * DD];
__device__ float g_vl[BB * S2S * DD];
__device__ float g_qr[BB * S2S * DD];
__device__ float g_kr[BB * S2S * DD];
__device__ float g_vr[BB * S2S * DD];
__device__ float g_attn0[BB * SS * DD];                   // left attn out (B,S,D)
__device__ float g_attn1[BB * SS * DD];                   // right attn out
__device__ float g_hx0[BB * SS * DD];                     // highway state left
__device__ float g_hx1[BB * SS * DD];                     // highway state right
__device__ float g_pr0[BB * SS * 2 * DD];                 // highway proj scratch left
__device__ float g_pr1[BB * SS * 2 * DD];                 // highway proj scratch right

// ---------------- build new_in = [left_pad | x | right_pad] ----------------
__global__ void build_new_in(const float* __restrict__ x,
                             const float* __restrict__ lp,
                             const float* __restrict__ rp) {
    int idx = blockIdx.x * blockDim.x + threadIdx.x;
    if (idx >= BB * S2S * DD) return;
    int d = idx & (DD - 1);
    int t = idx >> 9;                 // DD = 512
    int s = t % S2S;
    int b = t / S2S;
    float val;
    if (s < WW)                 val = lp[s * DD + d];
    else if (s < WW + SS)       val = x[((size_t)(b * SS + (s - WW))) * DD + d];
    else                        val = rp[(s - WW - SS) * DD + d];
    g_new_in[idx] = val;
}

// ---------------- SGEMM: C[M,N] = A[M,K] @ B[K,N] + bias[N] ----------------
// Requires M%128==0, N%128==0, K%8==0. BM=BN=128, BK=8, 256 threads, 8x8/thr.
__global__ __launch_bounds__(256) void sgemm128(
    const float* __restrict__ A, const float* __restrict__ Bw,
    const float* __restrict__ bias, float* __restrict__ C,
    int M, int N, int K)
{
    __shared__ float As[8][128];
    __shared__ float Bs[8][128];
    const int tid  = threadIdx.x;
    const int row0 = blockIdx.y * 128;
    const int col0 = blockIdx.x * 128;

    const int arow = tid >> 1;            // 0..127
    const int acol = (tid & 1) << 2;      // 0 or 4
    const int brow = tid >> 5;            // 0..7
    const int bcol = (tid & 31) << 2;     // 0..124

    const int ty = (tid >> 4) << 3;       // 0..120 step 8
    const int tx = (tid & 15) << 3;       // 0..120 step 8

    float acc[8][8];
#pragma unroll
    for (int i = 0; i < 8; i++)
#pragma unroll
        for (int j = 0; j < 8; j++) acc[i][j] = 0.f;

    const float* Aptr = A + (size_t)(row0 + arow) * K + acol;
    const float* Bptr = Bw + (size_t)brow * N + col0 + bcol;

    for (int k0 = 0; k0 < K; k0 += 8) {
        float4 av = *(const float4*)(Aptr + k0);
        As[acol + 0][arow] = av.x;
        As[acol + 1][arow] = av.y;
        As[acol + 2][arow] = av.z;
        As[acol + 3][arow] = av.w;
        float4 bv = *(const float4*)(Bptr + (size_t)k0 * N);
        *(float4*)(&Bs[brow][bcol]) = bv;
        __syncthreads();
#pragma unroll
        for (int kk = 0; kk < 8; kk++) {
            float a[8], bb[8];
            *(float4*)(a)     = *(const float4*)&As[kk][ty];
            *(float4*)(a + 4) = *(const float4*)&As[kk][ty + 4];
            *(float4*)(bb)     = *(const float4*)&Bs[kk][tx];
            *(float4*)(bb + 4) = *(const float4*)&Bs[kk][tx + 4];
#pragma unroll
            for (int i = 0; i < 8; i++)
#pragma unroll
                for (int j = 0; j < 8; j++)
                    acc[i][j] += a[i] * bb[j];
        }
        __syncthreads();
    }

#pragma unroll
    for (int i = 0; i < 8; i++) {
        int r = row0 + ty + i;
#pragma unroll
        for (int j = 0; j < 8; j += 4) {
            int c = col0 + tx + j;
            float4 o;
            o.x = acc[i][j + 0] + bias[c + 0];
            o.y = acc[i][j + 1] + bias[c + 1];
            o.z = acc[i][j + 2] + bias[c + 2];
            o.w = acc[i][j + 3] + bias[c + 3];
            *(float4*)&C[(size_t)r * N + c] = o;
        }
    }
}

// ---------------- banded attention (window = WIDTH+2 = 10 keys) ----------------
// dir=0: keys j in [qi-9, qi]; dir=1: keys j in [qi, qi+9]; qi = i + WIDTH.
// One warp per (b, i, h). Masked softmax over <=10 scores; masked exp underflows
// to exactly 0 (matching reference's -1e9 fill).
__global__ void banded_attn(const float* __restrict__ q, const float* __restrict__ k,
                            const float* __restrict__ v, float* __restrict__ out,
                            int dir)
{
    int gw = (blockIdx.x * blockDim.x + threadIdx.x) >> 5;
    if (gw >= BB * SS * HH) return;
    int lane = threadIdx.x & 31;
    int h = gw & (HH - 1);
    int t = gw >> 3;
    int i = t & (SS - 1);
    int b = t >> 10;
    int qi = i + WW;
    int jlo, jhi;
    if (dir == 0) { jlo = qi - (WW + 1); if (jlo < 0) jlo = 0; jhi = qi; }
    else          { jlo = qi; jhi = qi + (WW + 1); if (jhi > S2S - 1) jhi = S2S - 1; }

    const float* qp = q + ((size_t)(b * S2S + qi)) * DD + h * DKK;
    float q0 = qp[lane], q1 = qp[lane + 32];

    float sc[WW + 2];
#pragma unroll
    for (int jj = 0; jj < WW + 2; jj++) {
        int j = jlo + jj;
        bool valid = (j <= jhi);
        int jc = valid ? j : jlo;
        const float* kp = k + ((size_t)(b * S2S + jc)) * DD + h * DKK;
        float s = q0 * kp[lane] + q1 * kp[lane + 32];
#pragma unroll
        for (int o = 16; o; o >>= 1) s += __shfl_xor_sync(0xffffffffu, s, o);
        sc[jj] = valid ? s * 0.125f : -1e30f;
    }
    float m = sc[0];
#pragma unroll
    for (int jj = 1; jj < WW + 2; jj++) m = fmaxf(m, sc[jj]);
    float sum = 0.f;
#pragma unroll
    for (int jj = 0; jj < WW + 2; jj++) { sc[jj] = expf(sc[jj] - m); sum += sc[jj]; }
    float inv = 1.f / sum;
    float o0 = 0.f, o1 = 0.f;
#pragma unroll
    for (int jj = 0; jj < WW + 2; jj++) {
        int j = jlo + jj;
        int jc = (j <= jhi) ? j : jlo;       // weight is 0 when invalid
        const float* vp = v + ((size_t)(b * S2S + jc)) * DD + h * DKK;
        o0 += sc[jj] * vp[lane];
        o1 += sc[jj] * vp[lane + 32];
    }
    float* op = out + ((size_t)(b * SS + i)) * DD + h * DKK;
    op[lane]      = o0 * inv;
    op[lane + 32] = o1 * inv;
}

// ---------------- add relative-window embedding sum (in place) ----------------
// xio[b,i,d] += sum_{j=0..WIDTH} w[j] * new_in[b, base + i + j, d]
__global__ void add_rel(float* __restrict__ xio, const float* __restrict__ w, int base)
{
    int idx = blockIdx.x * blockDim.x + threadIdx.x;
    if (idx >= BB * SS * DD) return;
    int d = idx & (DD - 1);
    int t = idx >> 9;
    int i = t & (SS - 1);
    int b = t >> 10;
    float acc = xio[idx];
    const float* p = g_new_in + ((size_t)(b * S2S + base + i)) * DD + d;
#pragma unroll
    for (int j = 0; j <= WW; j++) acc += w[j] * p[(size_t)j * DD];
    xio[idx] = acc;
}

// ---------------- highway gate: dst = g*x + (1-g)*relu(nl) ----------------
// proj rows are 2D wide: [0:D)=nl, [D:2D)=gate logits. dst has leading dim ldd.
__global__ void hw_gate(const float* __restrict__ x, const float* __restrict__ proj,
                        float* __restrict__ dst, int ldd)
{
    int idx = blockIdx.x * blockDim.x + threadIdx.x;
    if (idx >= BB * SS * DD) return;
    int row = idx >> 9;
    int d = idx & (DD - 1);
    float nl = proj[(size_t)row * (2 * DD) + d];
    float gz = proj[(size_t)row * (2 * DD) + DD + d];
    nl = fmaxf(nl, 0.f);
    float g = 1.f / (1.f + expf(-gz));
    dst[(size_t)row * ldd + d] = g * x[idx] + (1.f - g) * nl;
}

// ---------------- launch ----------------
extern "C" void kernel_launch(void* const* d_in, const int* in_sizes, int n_in,
                              void* d_out, int out_size)
{
    const float* x    = (const float*)d_in[0];
    const float* lW   = (const float*)d_in[1];   // (4,D,D)
    const float* lb   = (const float*)d_in[2];   // (4,D)
    const float* rW   = (const float*)d_in[3];
    const float* rb   = (const float*)d_in[4];
    const float* lpad = (const float*)d_in[5];   // (WIDTH,D)
    const float* rpad = (const float*)d_in[6];
    const float* lw   = (const float*)d_in[7];   // (WIDTH+1,)
    const float* rw   = (const float*)d_in[8];
    const float* lhW  = (const float*)d_in[9];   // (2,D,2D)
    const float* lhb  = (const float*)d_in[10];  // (2,2D)
    const float* rhW  = (const float*)d_in[11];
    const float* rhb  = (const float*)d_in[12];
    float* out = (float*)d_out;                  // (1,B,S,2D)

    float *nin, *ql, *kl, *vl, *qr, *kr, *vr, *a0, *a1, *hx0, *hx1, *pr0, *pr1;
    cudaGetSymbolAddress((void**)&nin, g_new_in);
    cudaGetSymbolAddress((void**)&ql,  g_ql);
    cudaGetSymbolAddress((void**)&kl,  g_kl);
    cudaGetSymbolAddress((void**)&vl,  g_vl);
    cudaGetSymbolAddress((void**)&qr,  g_qr);
    cudaGetSymbolAddress((void**)&kr,  g_kr);
    cudaGetSymbolAddress((void**)&vr,  g_vr);
    cudaGetSymbolAddress((void**)&a0,  g_attn0);
    cudaGetSymbolAddress((void**)&a1,  g_attn1);
    cudaGetSymbolAddress((void**)&hx0, g_hx0);
    cudaGetSymbolAddress((void**)&hx1, g_hx1);
    cudaGetSymbolAddress((void**)&pr0, g_pr0);
    cudaGetSymbolAddress((void**)&pr1, g_pr1);

    const int DW = DD * DD;   // 262144

    // 1) pad-concat
    build_new_in<<<(BB * S2S * DD + 255) / 256, 256>>>(x, lpad, rpad);

    // 2) QKV projections (M = B*S2 = 8320)
    dim3 gqkv(DD / 128, (BB * S2S) / 128);    // (4, 65)
    sgemm128<<<gqkv, 256>>>(nin, lW + 0 * DW, lb + 0 * DD, ql, BB * S2S, DD, DD);
    sgemm128<<<gqkv, 256>>>(nin, lW + 1 * DW, lb + 1 * DD, kl, BB * S2S, DD, DD);
    sgemm128<<<gqkv, 256>>>(nin, lW + 2 * DW, lb + 2 * DD, vl, BB * S2S, DD, DD);
    sgemm128<<<gqkv, 256>>>(nin, rW + 0 * DW, rb + 0 * DD, qr, BB * S2S, DD, DD);
    sgemm128<<<gqkv, 256>>>(nin, rW + 1 * DW, rb + 1 * DD, kr, BB * S2S, DD, DD);
    sgemm128<<<gqkv, 256>>>(nin, rW + 2 * DW, rb + 2 * DD, vr, BB * S2S, DD, DD);

    // 3) banded attention (only central S queries), one warp per (b,i,h)
    int nwarps = BB * SS * HH;                 // 65536
    banded_attn<<<(nwarps * 32) / 256, 256>>>(ql, kl, vl, a0, 0);
    banded_attn<<<(nwarps * 32) / 256, 256>>>(qr, kr, vr, a1, 1);

    // 4) output projections (M = B*S = 8192)
    dim3 gpr(DD / 128, (BB * SS) / 128);       // (4, 64)
    sgemm128<<<gpr, 256>>>(a0, lW + 3 * DW, lb + 3 * DD, hx0, BB * SS, DD, DD);
    sgemm128<<<gpr, 256>>>(a1, rW + 3 * DW, rb + 3 * DD, hx1, BB * SS, DD, DD);

    // 5) add relative embedding sums
    int ne = BB * SS * DD;
    add_rel<<<(ne + 255) / 256, 256>>>(hx0, lw, 0);
    add_rel<<<(ne + 255) / 256, 256>>>(hx1, rw, WW);

    // 6) highway networks (2 layers each); last layer writes strided into d_out
    dim3 ghw((2 * DD) / 128, (BB * SS) / 128); // (8, 64)
    // left
    sgemm128<<<ghw, 256>>>(hx0, lhW + 0 * DD * 2 * DD, lhb + 0 * 2 * DD, pr0, BB * SS, 2 * DD, DD);
    hw_gate<<<(ne + 255) / 256, 256>>>(hx0, pr0, hx0, DD);
    sgemm128<<<ghw, 256>>>(hx0, lhW + 1 * DD * 2 * DD, lhb + 1 * 2 * DD, pr0, BB * SS, 2 * DD, DD);
    hw_gate<<<(ne + 255) / 256, 256>>>(hx0, pr0, out + 0, 2 * DD);
    // right
    sgemm128<<<ghw, 256>>>(hx1, rhW + 0 * DD * 2 * DD, rhb + 0 * 2 * DD, pr1, BB * SS, 2 * DD, DD);
    hw_gate<<<(ne + 255) / 256, 256>>>(hx1, pr1, hx1, DD);
    sgemm128<<<ghw, 256>>>(hx1, rhW + 1 * DD * 2 * DD, rhb + 1 * 2 * DD, pr1, BB * SS, 2 * DD, DD);
    hw_gate<<<(ne + 255) / 256, 256>>>(hx1, pr1, out + DD, 2 * DD);
}

// round 5
// speedup vs baseline: 1.7020x; 1.7020x over previous
#include <cuda_runtime.h>
#include <cuda_bf16.h>
#include <math.h>
#include <stdint.h>

#define BB   8
#define SS   1024
#define DD   512
#define HH   8
#define WW   8
#define S2S  1040
#define DKK  64

// ================= helpers =================
__device__ __forceinline__ uint32_t smem_u32(const void* p) {
    uint32_t a;
    asm("{ .reg .u64 t; cvta.to.shared.u64 t, %1; cvt.u32.u64 %0, t; }" : "=r"(a) : "l"(p));
    return a;
}
#define CP_A16(dst, src) \
    asm volatile("cp.async.cg.shared.global [%0], [%1], 16;" :: "r"((uint32_t)(dst)), "l"(src))
#define CP_COMMIT() asm volatile("cp.async.commit_group;" ::: "memory")
#define CP_WAIT(n)  asm volatile("cp.async.wait_group %0;" :: "n"(n) : "memory")

__device__ __forceinline__ void ldsm_x4(uint32_t& r0, uint32_t& r1, uint32_t& r2, uint32_t& r3, uint32_t addr) {
    asm volatile("ldmatrix.sync.aligned.m8n8.x4.shared.b16 {%0,%1,%2,%3}, [%4];"
                 : "=r"(r0), "=r"(r1), "=r"(r2), "=r"(r3) : "r"(addr));
}
__device__ __forceinline__ void ldsm_x2(uint32_t& r0, uint32_t& r1, uint32_t addr) {
    asm volatile("ldmatrix.sync.aligned.m8n8.x2.shared.b16 {%0,%1}, [%2];"
                 : "=r"(r0), "=r"(r1) : "r"(addr));
}
__device__ __forceinline__ void mma16816(float* d, const uint32_t* a, const uint32_t* b) {
    asm volatile("mma.sync.aligned.m16n8k16.row.col.f32.bf16.bf16.f32 "
                 "{%0,%1,%2,%3}, {%4,%5,%6,%7}, {%8,%9}, {%0,%1,%2,%3};"
                 : "+f"(d[0]), "+f"(d[1]), "+f"(d[2]), "+f"(d[3])
                 : "r"(a[0]), "r"(a[1]), "r"(a[2]), "r"(a[3]), "r"(b[0]), "r"(b[1]));
}

__device__ __forceinline__ void split2(float x, __nv_bfloat16& h, __nv_bfloat16& l) {
    h = __float2bfloat16(x);
    l = __float2bfloat16(x - __bfloat162float(h));
}

// ================= scratch (device globals) =================
__device__ float g_nin[BB * S2S * DD];
__device__ __nv_bfloat16 g_ninh[BB * S2S * DD];
__device__ __nv_bfloat16 g_ninl[BB * S2S * DD];
__device__ float g_q0[BB * S2S * DD], g_k0[BB * S2S * DD], g_v0[BB * S2S * DD];
__device__ float g_q1[BB * S2S * DD], g_k1[BB * S2S * DD], g_v1[BB * S2S * DD];
__device__ __nv_bfloat16 g_a0h[BB * SS * DD], g_a0l[BB * SS * DD];
__device__ __nv_bfloat16 g_a1h[BB * SS * DD], g_a1l[BB * SS * DD];
__device__ float g_hx0[BB * SS * DD], g_hx1[BB * SS * DD];
__device__ __nv_bfloat16 g_hx0h[BB * SS * DD], g_hx0l[BB * SS * DD];
__device__ __nv_bfloat16 g_hx1h[BB * SS * DD], g_hx1l[BB * SS * DD];
__device__ float g_pr0[BB * SS * 2 * DD], g_pr1[BB * SS * 2 * DD];
#define DW   (DD * DD)
#define DW2  (DD * 2 * DD)
#define HWO  (8 * DW)
__device__ __nv_bfloat16 g_wth[8 * DW + 4 * DW2];
__device__ __nv_bfloat16 g_wtl[8 * DW + 4 * DW2];

// ================= elementwise kernels =================
__global__ void build_new_in(const float* __restrict__ x,
                             const float* __restrict__ lp,
                             const float* __restrict__ rp) {
    int idx = blockIdx.x * blockDim.x + threadIdx.x;
    if (idx >= BB * S2S * DD) return;
    int d = idx & (DD - 1);
    int t = idx >> 9;
    int s = t % S2S;
    int b = t / S2S;
    float val;
    if (s < WW)            val = lp[s * DD + d];
    else if (s < WW + SS)  val = x[((size_t)(b * SS + (s - WW))) * DD + d];
    else                   val = rp[(s - WW - SS) * DD + d];
    g_nin[idx] = val;
    __nv_bfloat16 h, l; split2(val, h, l);
    g_ninh[idx] = h; g_ninl[idx] = l;
}

// W [K,N] fp32 -> Wt [N,K] bf16 hi/lo (tiled transpose)
__global__ void wsplit(const float* __restrict__ W,
                       __nv_bfloat16* __restrict__ th, __nv_bfloat16* __restrict__ tl,
                       int K, int N) {
    __shared__ float tile[32][33];
    int nb = blockIdx.x * 32, kb = blockIdx.y * 32;
    int tx = threadIdx.x, ty = threadIdx.y;
    for (int r = ty; r < 32; r += 8)
        tile[r][tx] = W[(size_t)(kb + r) * N + nb + tx];
    __syncthreads();
    for (int r = ty; r < 32; r += 8) {
        float v = tile[tx][r];
        __nv_bfloat16 h, l; split2(v, h, l);
        size_t o = (size_t)(nb + r) * K + kb + tx;
        th[o] = h; tl[o] = l;
    }
}

__global__ void banded_attn(const float* __restrict__ q, const float* __restrict__ k,
                            const float* __restrict__ v,
                            __nv_bfloat16* __restrict__ oh, __nv_bfloat16* __restrict__ ol,
                            int dir) {
    int gw = (blockIdx.x * blockDim.x + threadIdx.x) >> 5;
    if (gw >= BB * SS * HH) return;
    int lane = threadIdx.x & 31;
    int h = gw & (HH - 1);
    int t = gw >> 3;
    int i = t & (SS - 1);
    int b = t >> 10;
    int qi = i + WW;
    int jlo, jhi;
    if (dir == 0) { jlo = qi - (WW + 1); if (jlo < 0) jlo = 0; jhi = qi; }
    else          { jlo = qi; jhi = qi + (WW + 1); if (jhi > S2S - 1) jhi = S2S - 1; }

    const float* qp = q + ((size_t)(b * S2S + qi)) * DD + h * DKK;
    float q0 = qp[lane], q1 = qp[lane + 32];

    float sc[WW + 2];
#pragma unroll
    for (int jj = 0; jj < WW + 2; jj++) {
        int j = jlo + jj;
        bool valid = (j <= jhi);
        int jc = valid ? j : jlo;
        const float* kp = k + ((size_t)(b * S2S + jc)) * DD + h * DKK;
        float s = q0 * kp[lane] + q1 * kp[lane + 32];
#pragma unroll
        for (int o = 16; o; o >>= 1) s += __shfl_xor_sync(0xffffffffu, s, o);
        sc[jj] = valid ? s * 0.125f : -1e30f;
    }
    float m = sc[0];
#pragma unroll
    for (int jj = 1; jj < WW + 2; jj++) m = fmaxf(m, sc[jj]);
    float sum = 0.f;
#pragma unroll
    for (int jj = 0; jj < WW + 2; jj++) { sc[jj] = expf(sc[jj] - m); sum += sc[jj]; }
    float inv = 1.f / sum;
    float o0 = 0.f, o1 = 0.f;
#pragma unroll
    for (int jj = 0; jj < WW + 2; jj++) {
        int j = jlo + jj;
        int jc = (j <= jhi) ? j : jlo;
        const float* vp = v + ((size_t)(b * S2S + jc)) * DD + h * DKK;
        o0 += sc[jj] * vp[lane];
        o1 += sc[jj] * vp[lane + 32];
    }
    size_t op = ((size_t)(b * SS + i)) * DD + h * DKK;
    __nv_bfloat16 hh, ll;
    split2(o0 * inv, hh, ll); oh[op + lane] = hh; ol[op + lane] = ll;
    split2(o1 * inv, hh, ll); oh[op + lane + 32] = hh; ol[op + lane + 32] = ll;
}

__global__ void add_rel(float* __restrict__ xio, const float* __restrict__ w, int base,
                        __nv_bfloat16* __restrict__ oh, __nv_bfloat16* __restrict__ ol) {
    int idx = blockIdx.x * blockDim.x + threadIdx.x;
    if (idx >= BB * SS * DD) return;
    int d = idx & (DD - 1);
    int t = idx >> 9;
    int i = t & (SS - 1);
    int b = t >> 10;
    float acc = xio[idx];
    const float* p = g_nin + ((size_t)(b * S2S + base + i)) * DD + d;
#pragma unroll
    for (int j = 0; j <= WW; j++) acc += w[j] * p[(size_t)j * DD];
    xio[idx] = acc;
    __nv_bfloat16 h, l; split2(acc, h, l);
    oh[idx] = h; ol[idx] = l;
}

__global__ void hw_gate(const float* __restrict__ x, const float* __restrict__ proj,
                        float* __restrict__ dst, int ldd,
                        __nv_bfloat16* __restrict__ dh, __nv_bfloat16* __restrict__ dl) {
    int idx = blockIdx.x * blockDim.x + threadIdx.x;
    if (idx >= BB * SS * DD) return;
    int row = idx >> 9;
    int d = idx & (DD - 1);
    float nl = proj[(size_t)row * (2 * DD) + d];
    float gz = proj[(size_t)row * (2 * DD) + DD + d];
    nl = fmaxf(nl, 0.f);
    float g = 1.f / (1.f + expf(-gz));
    float y = g * x[idx] + (1.f - g) * nl;
    dst[(size_t)row * ldd + d] = y;
    if (dh) {
        __nv_bfloat16 h, l; split2(y, h, l);
        dh[idx] = h; dl[idx] = l;
    }
}

// ================= mma.sync split-bf16 GEMM =================
// C[M,N] = (Ah+Al)[M,K] @ Bt^T + bias where Bt = (Bh+Bl)[N,K] (K-major).
// Passes: Ah*Bh, Ah*Bl, Al*Bh. Tile 128x128, BK=32, 3-stage cp.async pipeline.
// smem rows padded to 40 bf16 (80B) -> conflict-free ldmatrix.
#define ROWP   40
#define STGB   (128 * ROWP * 2)        // 10240 bytes per operand-stage
#define GSMEM  (6 * STGB)              // 61440

__device__ __forceinline__ void load_stage(
    uint32_t sb, int stage,
    const __nv_bfloat16* __restrict__ A, const __nv_bfloat16* __restrict__ B,
    int row0, int col0, int K, int kb, int tid)
{
    uint32_t abase = sb + (uint32_t)stage * STGB;
    uint32_t bbase = sb + 3u * STGB + (uint32_t)stage * STGB;
#pragma unroll
    for (int t = 0; t < 2; t++) {
        int v = tid + t * 256;
        int r = v >> 2, kc = v & 3;
        CP_A16(abase + (uint32_t)(r * ROWP + kc * 8) * 2,
               A + (size_t)(row0 + r) * K + kb + kc * 8);
    }
#pragma unroll
    for (int t = 0; t < 2; t++) {
        int v = tid + t * 256;
        int r = v >> 2, kc = v & 3;
        CP_A16(bbase + (uint32_t)(r * ROWP + kc * 8) * 2,
               B + (size_t)(col0 + r) * K + kb + kc * 8);
    }
    CP_COMMIT();
}

__global__ __launch_bounds__(256, 2) void gemm_mma(
    const __nv_bfloat16* __restrict__ Ah, const __nv_bfloat16* __restrict__ Al,
    const __nv_bfloat16* __restrict__ Bh, const __nv_bfloat16* __restrict__ Bl,
    const float* __restrict__ bias, float* __restrict__ C,
    int M, int N, int K)
{
    extern __shared__ char smem[];
    uint32_t sb = smem_u32(smem);
    const int tid = threadIdx.x, wid = tid >> 5, lane = tid & 31;
    const int row0 = blockIdx.y * 128, col0 = blockIdx.x * 128;
    const int wm = (wid >> 2) * 64;      // 0 or 64
    const int wn = (wid & 3) * 32;       // 0,32,64,96

    const int nck = K >> 5;              // chunks per pass (16 for K=512)
    const int NC = 3 * nck;

    const __nv_bfloat16* Aps[3] = {Ah, Ah, Al};
    const __nv_bfloat16* Bps[3] = {Bh, Bl, Bh};

    // prologue: 3 chunks in flight
#pragma unroll
    for (int c = 0; c < 3; c++) {
        int pass = c / nck;
        int kb = (c - pass * nck) * 32;
        load_stage(sb, c % 3, Aps[pass], Bps[pass], row0, col0, K, kb, tid);
    }

    float d[16][4];
#pragma unroll
    for (int i = 0; i < 16; i++)
#pragma unroll
        for (int j = 0; j < 4; j++) d[i][j] = 0.f;

    for (int c = 0; c < NC; c++) {
        CP_WAIT(2);
        __syncthreads();
        int st = c % 3;
        uint32_t abase = sb + (uint32_t)st * STGB;
        uint32_t bbase = sb + 3u * STGB + (uint32_t)st * STGB;
#pragma unroll
        for (int ks = 0; ks < 2; ks++) {
            int k0 = ks * 16;
            uint32_t a[4][4], b[4][2];
#pragma unroll
            for (int im = 0; im < 4; im++) {
                int row = wm + im * 16 + (lane & 15);
                uint32_t addr = abase + (uint32_t)(row * ROWP + k0 + ((lane >> 4) << 3)) * 2;
                ldsm_x4(a[im][0], a[im][1], a[im][2], a[im][3], addr);
            }
#pragma unroll
            for (int in = 0; in < 4; in++) {
                int row = wn + in * 8 + (lane & 7);
                uint32_t addr = bbase + (uint32_t)(row * ROWP + k0 + (((lane >> 3) & 1) << 3)) * 2;
                ldsm_x2(b[in][0], b[in][1], addr);
            }
#pragma unroll
            for (int im = 0; im < 4; im++)
#pragma unroll
                for (int in = 0; in < 4; in++)
                    mma16816(d[im * 4 + in], a[im], b[in]);
        }
        __syncthreads();
        int nc2 = c + 3;
        if (nc2 < NC) {
            int pass = nc2 / nck;
            int kb = (nc2 - pass * nck) * 32;
            load_stage(sb, st, Aps[pass], Bps[pass], row0, col0, K, kb, tid);
        } else {
            CP_COMMIT();   // keep group count consistent
        }
    }

    // epilogue: registers -> global with bias
#pragma unroll
    for (int im = 0; im < 4; im++) {
#pragma unroll
        for (int in = 0; in < 4; in++) {
            float* dd = d[im * 4 + in];
            int m = row0 + wm + im * 16 + (lane >> 2);
            int n = col0 + wn + in * 8 + ((lane & 3) << 1);
            float b0 = bias[n], b1 = bias[n + 1];
            float2 v0 = make_float2(dd[0] + b0, dd[1] + b1);
            *(float2*)&C[(size_t)m * N + n] = v0;
            float2 v1 = make_float2(dd[2] + b0, dd[3] + b1);
            *(float2*)&C[(size_t)(m + 8) * N + n] = v1;
        }
    }
}

// ================= launch =================
extern "C" void kernel_launch(void* const* d_in, const int* in_sizes, int n_in,
                              void* d_out, int out_size)
{
    const float* x    = (const float*)d_in[0];
    const float* lW   = (const float*)d_in[1];
    const float* lb   = (const float*)d_in[2];
    const float* rW   = (const float*)d_in[3];
    const float* rb   = (const float*)d_in[4];
    const float* lpad = (const float*)d_in[5];
    const float* rpad = (const float*)d_in[6];
    const float* lw   = (const float*)d_in[7];
    const float* rw   = (const float*)d_in[8];
    const float* lhW  = (const float*)d_in[9];
    const float* lhb  = (const float*)d_in[10];
    const float* rhW  = (const float*)d_in[11];
    const float* rhb  = (const float*)d_in[12];
    float* out = (float*)d_out;

    cudaFuncSetAttribute(gemm_mma, cudaFuncAttributeMaxDynamicSharedMemorySize, GSMEM);

    float *q0, *k0, *v0, *q1, *k1, *v1, *hx0, *hx1, *pr0, *pr1;
    __nv_bfloat16 *ninh, *ninl, *a0h, *a0l, *a1h, *a1l;
    __nv_bfloat16 *hx0h, *hx0l, *hx1h, *hx1l, *wth, *wtl;
    cudaGetSymbolAddress((void**)&q0, g_q0);  cudaGetSymbolAddress((void**)&k0, g_k0);
    cudaGetSymbolAddress((void**)&v0, g_v0);  cudaGetSymbolAddress((void**)&q1, g_q1);
    cudaGetSymbolAddress((void**)&k1, g_k1);  cudaGetSymbolAddress((void**)&v1, g_v1);
    cudaGetSymbolAddress((void**)&hx0, g_hx0); cudaGetSymbolAddress((void**)&hx1, g_hx1);
    cudaGetSymbolAddress((void**)&pr0, g_pr0); cudaGetSymbolAddress((void**)&pr1, g_pr1);
    cudaGetSymbolAddress((void**)&ninh, g_ninh); cudaGetSymbolAddress((void**)&ninl, g_ninl);
    cudaGetSymbolAddress((void**)&a0h, g_a0h); cudaGetSymbolAddress((void**)&a0l, g_a0l);
    cudaGetSymbolAddress((void**)&a1h, g_a1h); cudaGetSymbolAddress((void**)&a1l, g_a1l);
    cudaGetSymbolAddress((void**)&hx0h, g_hx0h); cudaGetSymbolAddress((void**)&hx0l, g_hx0l);
    cudaGetSymbolAddress((void**)&hx1h, g_hx1h); cudaGetSymbolAddress((void**)&hx1l, g_hx1l);
    cudaGetSymbolAddress((void**)&wth, g_wth); cudaGetSymbolAddress((void**)&wtl, g_wtl);

    dim3 wsb(32, 8);
    for (int i = 0; i < 4; i++) {
        wsplit<<<dim3(16, 16), wsb>>>(lW + (size_t)i * DW, wth + (size_t)i * DW, wtl + (size_t)i * DW, 512, 512);
        wsplit<<<dim3(16, 16), wsb>>>(rW + (size_t)i * DW, wth + (size_t)(4 + i) * DW, wtl + (size_t)(4 + i) * DW, 512, 512);
    }
    for (int j = 0; j < 2; j++) {
        wsplit<<<dim3(32, 16), wsb>>>(lhW + (size_t)j * DW2, wth + HWO + (size_t)j * DW2, wtl + HWO + (size_t)j * DW2, 512, 1024);
        wsplit<<<dim3(32, 16), wsb>>>(rhW + (size_t)j * DW2, wth + HWO + (size_t)(2 + j) * DW2, wtl + HWO + (size_t)(2 + j) * DW2, 512, 1024);
    }

    build_new_in<<<(BB * S2S * DD + 255) / 256, 256>>>(x, lpad, rpad);

    // QKV projections: M=8320, N=512, K=512
    dim3 gq(4, 65);
    gemm_mma<<<gq, 256, GSMEM>>>(ninh, ninl, wth + 0 * DW, wtl + 0 * DW, lb + 0 * DD, q0, BB * S2S, DD, DD);
    gemm_mma<<<gq, 256, GSMEM>>>(ninh, ninl, wth + 1 * DW, wtl + 1 * DW, lb + 1 * DD, k0, BB * S2S, DD, DD);
    gemm_mma<<<gq, 256, GSMEM>>>(ninh, ninl, wth + 2 * DW, wtl + 2 * DW, lb + 2 * DD, v0, BB * S2S, DD, DD);
    gemm_mma<<<gq, 256, GSMEM>>>(ninh, ninl, wth + 4 * DW, wtl + 4 * DW, rb + 0 * DD, q1, BB * S2S, DD, DD);
    gemm_mma<<<gq, 256, GSMEM>>>(ninh, ninl, wth + 5 * DW, wtl + 5 * DW, rb + 1 * DD, k1, BB * S2S, DD, DD);
    gemm_mma<<<gq, 256, GSMEM>>>(ninh, ninl, wth + 6 * DW, wtl + 6 * DW, rb + 2 * DD, v1, BB * S2S, DD, DD);

    // banded attention -> bf16 hi/lo
    banded_attn<<<(BB * SS * HH * 32) / 256, 256>>>(q0, k0, v0, a0h, a0l, 0);
    banded_attn<<<(BB * SS * HH * 32) / 256, 256>>>(q1, k1, v1, a1h, a1l, 1);

    // output projections: M=8192, N=512
    dim3 gp(4, 64);
    gemm_mma<<<gp, 256, GSMEM>>>(a0h, a0l, wth + 3 * DW, wtl + 3 * DW, lb + 3 * DD, hx0, BB * SS, DD, DD);
    gemm_mma<<<gp, 256, GSMEM>>>(a1h, a1l, wth + 7 * DW, wtl + 7 * DW, rb + 3 * DD, hx1, BB * SS, DD, DD);

    int ne = BB * SS * DD;
    add_rel<<<(ne + 255) / 256, 256>>>(hx0, lw, 0, hx0h, hx0l);
    add_rel<<<(ne + 255) / 256, 256>>>(hx1, rw, WW, hx1h, hx1l);

    // highway: 2 layers each; M=8192, N=1024
    dim3 gh(8, 64);
    gemm_mma<<<gh, 256, GSMEM>>>(hx0h, hx0l, wth + HWO + 0 * DW2, wtl + HWO + 0 * DW2, lhb + 0, pr0, BB * SS, 2 * DD, DD);
    hw_gate<<<(ne + 255) / 256, 256>>>(hx0, pr0, hx0, DD, hx0h, hx0l);
    gemm_mma<<<gh, 256, GSMEM>>>(hx0h, hx0l, wth + HWO + 1 * DW2, wtl + HWO + 1 * DW2, lhb + 2 * DD, pr0, BB * SS, 2 * DD, DD);
    hw_gate<<<(ne + 255) / 256, 256>>>(hx0, pr0, out + 0, 2 * DD, nullptr, nullptr);

    gemm_mma<<<gh, 256, GSMEM>>>(hx1h, hx1l, wth + HWO + 2 * DW2, wtl + HWO + 2 * DW2, rhb + 0, pr1, BB * SS, 2 * DD, DD);
    hw_gate<<<(ne + 255) / 256, 256>>>(hx1, pr1, hx1, DD, hx1h, hx1l);
    gemm_mma<<<gh, 256, GSMEM>>>(hx1h, hx1l, wth + HWO + 3 * DW2, wtl + HWO + 3 * DW2, rhb + 2 * DD, pr1, BB * SS, 2 * DD, DD);
    hw_gate<<<(ne + 255) / 256, 256>>>(hx1, pr1, out + DD, 2 * DD, nullptr, nullptr);
}

// round 6
// speedup vs baseline: 2.0872x; 1.2263x over previous
#include <cuda_runtime.h>
#include <cuda_bf16.h>
#include <math.h>
#include <stdint.h>

#define BB   8
#define SS   1024
#define DD   512
#define HH   8
#define WW   8
#define S2S  1040
#define DKK  64

// ================= helpers =================
__device__ __forceinline__ uint32_t smem_u32(const void* p) {
    uint32_t a;
    asm("{ .reg .u64 t; cvta.to.shared.u64 t, %1; cvt.u32.u64 %0, t; }" : "=r"(a) : "l"(p));
    return a;
}
#define CP_A16(dst, src) \
    asm volatile("cp.async.cg.shared.global [%0], [%1], 16;" :: "r"((uint32_t)(dst)), "l"(src))
#define CP_COMMIT() asm volatile("cp.async.commit_group;" ::: "memory")
#define CP_WAIT(n)  asm volatile("cp.async.wait_group %0;" :: "n"(n) : "memory")

__device__ __forceinline__ void ldsm_x4(uint32_t& r0, uint32_t& r1, uint32_t& r2, uint32_t& r3, uint32_t addr) {
    asm volatile("ldmatrix.sync.aligned.m8n8.x4.shared.b16 {%0,%1,%2,%3}, [%4];"
                 : "=r"(r0), "=r"(r1), "=r"(r2), "=r"(r3) : "r"(addr));
}
__device__ __forceinline__ void mma16816(float* d, const uint32_t* a, const uint32_t* b) {
    asm volatile("mma.sync.aligned.m16n8k16.row.col.f32.bf16.bf16.f32 "
                 "{%0,%1,%2,%3}, {%4,%5,%6,%7}, {%8,%9}, {%0,%1,%2,%3};"
                 : "+f"(d[0]), "+f"(d[1]), "+f"(d[2]), "+f"(d[3])
                 : "r"(a[0]), "r"(a[1]), "r"(a[2]), "r"(a[3]), "r"(b[0]), "r"(b[1]));
}
__device__ __forceinline__ void split2(float x, __nv_bfloat16& h, __nv_bfloat16& l) {
    h = __float2bfloat16(x);
    l = __float2bfloat16(x - __bfloat162float(h));
}

// ================= scratch (device globals) =================
#define DW   (DD * DD)
#define DW2  (DD * 2 * DD)
#define HWO  (8 * DW)
__device__ float g_nin[BB * S2S * DD];
__device__ __nv_bfloat16 g_ninh[BB * S2S * DD];
__device__ __nv_bfloat16 g_ninl[BB * S2S * DD];
__device__ float g_qkv[BB * S2S * 6 * DD];                // fused QKV output (lda=3072)
__device__ float g_bqkv[6 * DD];
__device__ __nv_bfloat16 g_a0h[BB * SS * DD], g_a0l[BB * SS * DD];
__device__ __nv_bfloat16 g_a1h[BB * SS * DD], g_a1l[BB * SS * DD];
__device__ float g_hx0[BB * SS * DD], g_hx1[BB * SS * DD];
__device__ __nv_bfloat16 g_hx0h[BB * SS * DD], g_hx0l[BB * SS * DD];
__device__ __nv_bfloat16 g_hx1h[BB * SS * DD], g_hx1l[BB * SS * DD];
__device__ float g_pr0[BB * SS * 2 * DD], g_pr1[BB * SS * 2 * DD];
__device__ __nv_bfloat16 g_wth[8 * DW + 4 * DW2];
__device__ __nv_bfloat16 g_wtl[8 * DW + 4 * DW2];

// ================= weight transpose+split: ALL matrices, one launch =========
// slots 0-5: lW0-2, rW0-2 (fused QKV order); slot 6: lW3; slot 7: rW3;
// HWO + {0,1,2,3}*DW2: lh0, lh1, rh0, rh1.  All K=512.
__global__ void wsplit_all(const float* __restrict__ lW, const float* __restrict__ rW,
                           const float* __restrict__ lhW, const float* __restrict__ rhW) {
    __shared__ float tile[32][33];
    int blk = blockIdx.x;
    const float* W;
    __nv_bfloat16 *th, *tl;
    int nb, kb, N;
    if (blk < 2048) {
        int mat = blk >> 8;          // 0..7
        int t = blk & 255;
        N = 512;
        nb = (t & 15) * 32; kb = (t >> 4) * 32;
        int slot;
        if (mat < 4) { W = lW + (size_t)mat * DW; slot = (mat < 3) ? mat : 6; }
        else         { int i = mat - 4; W = rW + (size_t)i * DW; slot = (i < 3) ? 3 + i : 7; }
        th = g_wth + (size_t)slot * DW;
        tl = g_wtl + (size_t)slot * DW;
    } else {
        int bb = blk - 2048;
        int mat = bb >> 9;           // 0..3
        int t = bb & 511;
        N = 1024;
        nb = (t & 31) * 32; kb = (t >> 5) * 32;
        W = (mat < 2) ? lhW + (size_t)mat * DW2 : rhW + (size_t)(mat - 2) * DW2;
        th = g_wth + HWO + (size_t)mat * DW2;
        tl = g_wtl + HWO + (size_t)mat * DW2;
    }
    int tx = threadIdx.x, ty = threadIdx.y;
    for (int r = ty; r < 32; r += 8)
        tile[r][tx] = W[(size_t)(kb + r) * N + nb + tx];
    __syncthreads();
    for (int r = ty; r < 32; r += 8) {
        float v = tile[tx][r];
        __nv_bfloat16 h, l; split2(v, h, l);
        size_t o = (size_t)(nb + r) * 512 + kb + tx;
        th[o] = h; tl[o] = l;
    }
}

__global__ void pack_bias(const float* __restrict__ lb, const float* __restrict__ rb) {
    int n = blockIdx.x * blockDim.x + threadIdx.x;
    if (n >= 6 * DD) return;
    int slot = n >> 9, loc = n & 511;
    g_bqkv[n] = (slot < 3) ? lb[slot * DD + loc] : rb[(slot - 3) * DD + loc];
}

// ================= elementwise =================
__global__ void build_new_in(const float* __restrict__ x,
                             const float* __restrict__ lp,
                             const float* __restrict__ rp) {
    int idx = blockIdx.x * blockDim.x + threadIdx.x;
    if (idx >= BB * S2S * DD) return;
    int d = idx & (DD - 1);
    int t = idx >> 9;
    int s = t % S2S;
    int b = t / S2S;
    float val;
    if (s < WW)            val = lp[s * DD + d];
    else if (s < WW + SS)  val = x[((size_t)(b * SS + (s - WW))) * DD + d];
    else                   val = rp[(s - WW - SS) * DD + d];
    g_nin[idx] = val;
    __nv_bfloat16 h, l; split2(val, h, l);
    g_ninh[idx] = h; g_ninl[idx] = l;
}

// fused-QKV banded attention; blockIdx.z = dir
__global__ void banded_attn_f(const float* __restrict__ qkv,
                              __nv_bfloat16* __restrict__ o0h, __nv_bfloat16* __restrict__ o0l,
                              __nv_bfloat16* __restrict__ o1h, __nv_bfloat16* __restrict__ o1l) {
    int dir = blockIdx.z;
    __nv_bfloat16* oh = dir ? o1h : o0h;
    __nv_bfloat16* ol = dir ? o1l : o0l;
    int qoff = dir * 3 * DD;
    int gw = (blockIdx.x * blockDim.x + threadIdx.x) >> 5;
    if (gw >= BB * SS * HH) return;
    int lane = threadIdx.x & 31;
    int h = gw & (HH - 1);
    int t = gw >> 3;
    int i = t & (SS - 1);
    int b = t >> 10;
    int qi = i + WW;
    int jlo, jhi;
    if (dir == 0) { jlo = qi - (WW + 1); if (jlo < 0) jlo = 0; jhi = qi; }
    else          { jlo = qi; jhi = qi + (WW + 1); if (jhi > S2S - 1) jhi = S2S - 1; }

    const int LDA = 6 * DD;
    const float* qp = qkv + ((size_t)(b * S2S + qi)) * LDA + qoff + h * DKK;
    float q0 = qp[lane], q1 = qp[lane + 32];

    float sc[WW + 2];
#pragma unroll
    for (int jj = 0; jj < WW + 2; jj++) {
        int j = jlo + jj;
        bool valid = (j <= jhi);
        int jc = valid ? j : jlo;
        const float* kp = qkv + ((size_t)(b * S2S + jc)) * LDA + qoff + DD + h * DKK;
        float s = q0 * kp[lane] + q1 * kp[lane + 32];
#pragma unroll
        for (int o = 16; o; o >>= 1) s += __shfl_xor_sync(0xffffffffu, s, o);
        sc[jj] = valid ? s * 0.125f : -1e30f;
    }
    float m = sc[0];
#pragma unroll
    for (int jj = 1; jj < WW + 2; jj++) m = fmaxf(m, sc[jj]);
    float sum = 0.f;
#pragma unroll
    for (int jj = 0; jj < WW + 2; jj++) { sc[jj] = expf(sc[jj] - m); sum += sc[jj]; }
    float inv = 1.f / sum;
    float o0 = 0.f, o1 = 0.f;
#pragma unroll
    for (int jj = 0; jj < WW + 2; jj++) {
        int j = jlo + jj;
        int jc = (j <= jhi) ? j : jlo;
        const float* vp = qkv + ((size_t)(b * S2S + jc)) * LDA + qoff + 2 * DD + h * DKK;
        o0 += sc[jj] * vp[lane];
        o1 += sc[jj] * vp[lane + 32];
    }
    size_t op = ((size_t)(b * SS + i)) * DD + h * DKK;
    __nv_bfloat16 hh, ll;
    split2(o0 * inv, hh, ll); oh[op + lane] = hh; ol[op + lane] = ll;
    split2(o1 * inv, hh, ll); oh[op + lane + 32] = hh; ol[op + lane + 32] = ll;
}

// add relative sums, z = side
__global__ void add_rel2(float* __restrict__ x0, float* __restrict__ x1,
                         const float* __restrict__ w0, const float* __restrict__ w1,
                         __nv_bfloat16* __restrict__ oh0, __nv_bfloat16* __restrict__ ol0,
                         __nv_bfloat16* __restrict__ oh1, __nv_bfloat16* __restrict__ ol1) {
    int z = blockIdx.z;
    float* xio = z ? x1 : x0;
    const float* w = z ? w1 : w0;
    __nv_bfloat16* oh = z ? oh1 : oh0;
    __nv_bfloat16* ol = z ? ol1 : ol0;
    int base = z ? WW : 0;
    int idx = blockIdx.x * blockDim.x + threadIdx.x;
    if (idx >= BB * SS * DD) return;
    int d = idx & (DD - 1);
    int t = idx >> 9;
    int i = t & (SS - 1);
    int b = t >> 10;
    float acc = xio[idx];
    const float* p = g_nin + ((size_t)(b * S2S + base + i)) * DD + d;
#pragma unroll
    for (int j = 0; j <= WW; j++) acc += w[j] * p[(size_t)j * DD];
    xio[idx] = acc;
    __nv_bfloat16 h, l; split2(acc, h, l);
    oh[idx] = h; ol[idx] = l;
}

// highway gate, z = side
__global__ void hw_gate2(const float* __restrict__ x0, const float* __restrict__ x1,
                         const float* __restrict__ p0, const float* __restrict__ p1,
                         float* __restrict__ d0, float* __restrict__ d1, int ldd,
                         __nv_bfloat16* __restrict__ dh0, __nv_bfloat16* __restrict__ dl0,
                         __nv_bfloat16* __restrict__ dh1, __nv_bfloat16* __restrict__ dl1) {
    int z = blockIdx.z;
    const float* x = z ? x1 : x0;
    const float* proj = z ? p1 : p0;
    float* dst = z ? d1 : d0;
    __nv_bfloat16* dh = z ? dh1 : dh0;
    __nv_bfloat16* dl = z ? dl1 : dl0;
    int idx = blockIdx.x * blockDim.x + threadIdx.x;
    if (idx >= BB * SS * DD) return;
    int row = idx >> 9;
    int d = idx & (DD - 1);
    float nl = proj[(size_t)row * (2 * DD) + d];
    float gz = proj[(size_t)row * (2 * DD) + DD + d];
    nl = fmaxf(nl, 0.f);
    float g = 1.f / (1.f + expf(-gz));
    float y = g * x[idx] + (1.f - g) * nl;
    dst[(size_t)row * ldd + d] = y;
    if (dh) {
        __nv_bfloat16 h, l; split2(y, h, l);
        dh[idx] = h; dl[idx] = l;
    }
}

// ================= fused 3-pass split-bf16 GEMM =================
// Per k-chunk load Ah,Al,Bh,Bl tiles; compute Ah*Bh + Ah*Bl + Al*Bh from regs.
// Tile 128x128, BK=32, 3-stage cp.async, padded rows (40 bf16) conflict-free.
#define ROWP   40
#define TILEB  (128 * ROWP * 2)        // 10240 B per tile
#define STG4   (4 * TILEB)             // 40960 B per stage
#define GSMEM3 (3 * STG4)              // 122880 B

struct GArg {
    const __nv_bfloat16 *ah, *al, *bh, *bl;
    const float* bias;
    float* c;
};

__device__ __forceinline__ void load_stage4(uint32_t sb, int st, const GArg& g,
                                            int row0, int col0, int K, int kb, int tid) {
    uint32_t base = sb + (uint32_t)st * STG4;
#pragma unroll
    for (int t = 0; t < 2; t++) {
        int v = tid + t * 256;
        int r = v >> 2, kc = v & 3;
        uint32_t off = (uint32_t)(r * ROWP + kc * 8) * 2;
        size_t ga = (size_t)(row0 + r) * K + kb + kc * 8;
        size_t gb = (size_t)(col0 + r) * K + kb + kc * 8;
        CP_A16(base + off,             g.ah + ga);
        CP_A16(base + TILEB + off,     g.al + ga);
        CP_A16(base + 2 * TILEB + off, g.bh + gb);
        CP_A16(base + 3 * TILEB + off, g.bl + gb);
    }
    CP_COMMIT();
}

__global__ __launch_bounds__(256, 1) void gemm3(
    GArg ga0, GArg ga1, int M, int N, int K)
{
    extern __shared__ char smem[];
    uint32_t sb = smem_u32(smem);
    const GArg g = blockIdx.z ? ga1 : ga0;
    const int tid = threadIdx.x, wid = tid >> 5, lane = tid & 31;
    const int row0 = blockIdx.y * 128, col0 = blockIdx.x * 128;
    const int wm = (wid >> 2) * 64;      // 0 or 64
    const int wn = (wid & 3) * 32;       // 0,32,64,96

    const int NC = K >> 5;               // 16 for K=512

    load_stage4(sb, 0, g, row0, col0, K, 0, tid);
    load_stage4(sb, 1, g, row0, col0, K, 32, tid);
    load_stage4(sb, 2, g, row0, col0, K, 64, tid);

    float d[16][4];
#pragma unroll
    for (int i = 0; i < 16; i++)
#pragma unroll
        for (int j = 0; j < 4; j++) d[i][j] = 0.f;

    for (int c = 0; c < NC; c++) {
        CP_WAIT(2);
        __syncthreads();
        int st = c - (c / 3) * 3;
        uint32_t abh = sb + (uint32_t)st * STG4;
        uint32_t abl = abh + TILEB;
        uint32_t bbh = abh + 2 * TILEB;
        uint32_t bbl = abh + 3 * TILEB;
#pragma unroll
        for (int ks = 0; ks < 2; ks++) {
            int k0 = ks * 16;
            uint32_t ah[4][4], al[4][4], bh[4][2], bl[4][2];
#pragma unroll
            for (int im = 0; im < 4; im++) {
                int row = wm + im * 16 + (lane & 15);
                uint32_t off = (uint32_t)(row * ROWP + k0 + ((lane >> 4) << 3)) * 2;
                ldsm_x4(ah[im][0], ah[im][1], ah[im][2], ah[im][3], abh + off);
                ldsm_x4(al[im][0], al[im][1], al[im][2], al[im][3], abl + off);
            }
#pragma unroll
            for (int p = 0; p < 2; p++) {
                int m = lane >> 3;
                int row = wn + (2 * p + (m >> 1)) * 8 + (lane & 7);
                uint32_t off = (uint32_t)(row * ROWP + k0 + ((m & 1) << 3)) * 2;
                ldsm_x4(bh[2 * p][0], bh[2 * p][1], bh[2 * p + 1][0], bh[2 * p + 1][1], bbh + off);
                ldsm_x4(bl[2 * p][0], bl[2 * p][1], bl[2 * p + 1][0], bl[2 * p + 1][1], bbl + off);
            }
#pragma unroll
            for (int im = 0; im < 4; im++)
#pragma unroll
                for (int in = 0; in < 4; in++) {
                    float* dd = d[im * 4 + in];
                    mma16816(dd, ah[im], bh[in]);
                    mma16816(dd, ah[im], bl[in]);
                    mma16816(dd, al[im], bh[in]);
                }
        }
        __syncthreads();
        if (c + 3 < NC) load_stage4(sb, st, g, row0, col0, K, (c + 3) * 32, tid);
        else CP_COMMIT();
    }

    // epilogue: registers -> global with bias
#pragma unroll
    for (int im = 0; im < 4; im++) {
#pragma unroll
        for (int in = 0; in < 4; in++) {
            float* dd = d[im * 4 + in];
            int m = row0 + wm + im * 16 + (lane >> 2);
            int n = col0 + wn + in * 8 + ((lane & 3) << 1);
            float b0 = g.bias[n], b1 = g.bias[n + 1];
            float2 v0 = make_float2(dd[0] + b0, dd[1] + b1);
            *(float2*)&g.c[(size_t)m * N + n] = v0;
            float2 v1 = make_float2(dd[2] + b0, dd[3] + b1);
            *(float2*)&g.c[(size_t)(m + 8) * N + n] = v1;
        }
    }
}

// ================= launch =================
extern "C" void kernel_launch(void* const* d_in, const int* in_sizes, int n_in,
                              void* d_out, int out_size)
{
    const float* x    = (const float*)d_in[0];
    const float* lW   = (const float*)d_in[1];
    const float* lb   = (const float*)d_in[2];
    const float* rW   = (const float*)d_in[3];
    const float* rb   = (const float*)d_in[4];
    const float* lpad = (const float*)d_in[5];
    const float* rpad = (const float*)d_in[6];
    const float* lw   = (const float*)d_in[7];
    const float* rw   = (const float*)d_in[8];
    const float* lhW  = (const float*)d_in[9];
    const float* lhb  = (const float*)d_in[10];
    const float* rhW  = (const float*)d_in[11];
    const float* rhb  = (const float*)d_in[12];
    float* out = (float*)d_out;

    cudaFuncSetAttribute(gemm3, cudaFuncAttributeMaxDynamicSharedMemorySize, GSMEM3);

    float *qkv, *bqkv, *hx0, *hx1, *pr0, *pr1;
    __nv_bfloat16 *ninh, *ninl, *a0h, *a0l, *a1h, *a1l;
    __nv_bfloat16 *hx0h, *hx0l, *hx1h, *hx1l, *wth, *wtl;
    cudaGetSymbolAddress((void**)&qkv, g_qkv);
    cudaGetSymbolAddress((void**)&bqkv, g_bqkv);
    cudaGetSymbolAddress((void**)&hx0, g_hx0); cudaGetSymbolAddress((void**)&hx1, g_hx1);
    cudaGetSymbolAddress((void**)&pr0, g_pr0); cudaGetSymbolAddress((void**)&pr1, g_pr1);
    cudaGetSymbolAddress((void**)&ninh, g_ninh); cudaGetSymbolAddress((void**)&ninl, g_ninl);
    cudaGetSymbolAddress((void**)&a0h, g_a0h); cudaGetSymbolAddress((void**)&a0l, g_a0l);
    cudaGetSymbolAddress((void**)&a1h, g_a1h); cudaGetSymbolAddress((void**)&a1l, g_a1l);
    cudaGetSymbolAddress((void**)&hx0h, g_hx0h); cudaGetSymbolAddress((void**)&hx0l, g_hx0l);
    cudaGetSymbolAddress((void**)&hx1h, g_hx1h); cudaGetSymbolAddress((void**)&hx1l, g_hx1l);
    cudaGetSymbolAddress((void**)&wth, g_wth); cudaGetSymbolAddress((void**)&wtl, g_wtl);

    // weight prep: single launch + bias pack
    wsplit_all<<<4096, dim3(32, 8)>>>(lW, rW, lhW, rhW);
    pack_bias<<<12, 256>>>(lb, rb);
    build_new_in<<<(BB * S2S * DD + 255) / 256, 256>>>(x, lpad, rpad);

    // fused QKV: M=8320, N=3072, K=512
    {
        GArg a = {ninh, ninl, wth, wtl, bqkv, qkv};
        gemm3<<<dim3(24, 65, 1), 256, GSMEM3>>>(a, a, BB * S2S, 6 * DD, DD);
    }

    // banded attention (both dirs)
    banded_attn_f<<<dim3((BB * SS * HH * 32) / 256, 1, 2), 256>>>(qkv, a0h, a0l, a1h, a1l);

    // output projections: z=2
    {
        GArg p0 = {a0h, a0l, wth + 6 * (size_t)DW, wtl + 6 * (size_t)DW, lb + 3 * DD, hx0};
        GArg p1 = {a1h, a1l, wth + 7 * (size_t)DW, wtl + 7 * (size_t)DW, rb + 3 * DD, hx1};
        gemm3<<<dim3(4, 64, 2), 256, GSMEM3>>>(p0, p1, BB * SS, DD, DD);
    }

    int ne = BB * SS * DD;
    add_rel2<<<dim3((ne + 255) / 256, 1, 2), 256>>>(hx0, hx1, lw, rw, hx0h, hx0l, hx1h, hx1l);

    // highway layer 1
    {
        GArg h0 = {hx0h, hx0l, wth + HWO, wtl + HWO, lhb, pr0};
        GArg h1 = {hx1h, hx1l, wth + HWO + 2 * (size_t)DW2, wtl + HWO + 2 * (size_t)DW2, rhb, pr1};
        gemm3<<<dim3(8, 64, 2), 256, GSMEM3>>>(h0, h1, BB * SS, 2 * DD, DD);
    }
    hw_gate2<<<dim3((ne + 255) / 256, 1, 2), 256>>>(hx0, hx1, pr0, pr1, hx0, hx1, DD,
                                                    hx0h, hx0l, hx1h, hx1l);
    // highway layer 2 -> strided output
    {
        GArg h0 = {hx0h, hx0l, wth + HWO + (size_t)DW2, wtl + HWO + (size_t)DW2, lhb + 2 * DD, pr0};
        GArg h1 = {hx1h, hx1l, wth + HWO + 3 * (size_t)DW2, wtl + HWO + 3 * (size_t)DW2, rhb + 2 * DD, pr1};
        gemm3<<<dim3(8, 64, 2), 256, GSMEM3>>>(h0, h1, BB * SS, 2 * DD, DD);
    }
    hw_gate2<<<dim3((ne + 255) / 256, 1, 2), 256>>>(hx0, hx1, pr0, pr1, out + 0, out + DD, 2 * DD,
                                                    nullptr, nullptr, nullptr, nullptr);
}

// round 7
// speedup vs baseline: 2.3900x; 1.1451x over previous
#include <cuda_runtime.h>
#include <cuda_bf16.h>
#include <math.h>
#include <stdint.h>

#define BB   8
#define SS   1024
#define DD   512
#define HH   8
#define WW   8
#define S2S  1040
#define DKK  64

// ================= helpers =================
__device__ __forceinline__ uint32_t smem_u32(const void* p) {
    uint32_t a;
    asm("{ .reg .u64 t; cvta.to.shared.u64 t, %1; cvt.u32.u64 %0, t; }" : "=r"(a) : "l"(p));
    return a;
}
#define CP_A16(dst, src) \
    asm volatile("cp.async.cg.shared.global [%0], [%1], 16;" :: "r"((uint32_t)(dst)), "l"(src))
#define CP_COMMIT() asm volatile("cp.async.commit_group;" ::: "memory")
#define CP_WAIT(n)  asm volatile("cp.async.wait_group %0;" :: "n"(n) : "memory")

__device__ __forceinline__ void ldsm_x4(uint32_t& r0, uint32_t& r1, uint32_t& r2, uint32_t& r3, uint32_t addr) {
    asm volatile("ldmatrix.sync.aligned.m8n8.x4.shared.b16 {%0,%1,%2,%3}, [%4];"
                 : "=r"(r0), "=r"(r1), "=r"(r2), "=r"(r3) : "r"(addr));
}
__device__ __forceinline__ void mma16816(float* d, const uint32_t* a, const uint32_t* b) {
    asm volatile("mma.sync.aligned.m16n8k16.row.col.f32.bf16.bf16.f32 "
                 "{%0,%1,%2,%3}, {%4,%5,%6,%7}, {%8,%9}, {%0,%1,%2,%3};"
                 : "+f"(d[0]), "+f"(d[1]), "+f"(d[2]), "+f"(d[3])
                 : "r"(a[0]), "r"(a[1]), "r"(a[2]), "r"(a[3]), "r"(b[0]), "r"(b[1]));
}
__device__ __forceinline__ void split2(float x, __nv_bfloat16& h, __nv_bfloat16& l) {
    h = __float2bfloat16(x);
    l = __float2bfloat16(x - __bfloat162float(h));
}

// ================= scratch (device globals) =================
#define DW   (DD * DD)
#define DW2  (DD * 2 * DD)
#define HWO  (8 * DW)
__device__ float g_nin[BB * S2S * DD];
__device__ __nv_bfloat16 g_ninh[BB * S2S * DD];
__device__ __nv_bfloat16 g_ninl[BB * S2S * DD];
__device__ float g_qkv[BB * S2S * 6 * DD];                // fused QKV output (lda=3072)
__device__ float g_bqkv[6 * DD];
__device__ __nv_bfloat16 g_a0h[BB * SS * DD], g_a0l[BB * SS * DD];
__device__ __nv_bfloat16 g_a1h[BB * SS * DD], g_a1l[BB * SS * DD];
__device__ float g_hx0[BB * SS * DD], g_hx1[BB * SS * DD];
__device__ __nv_bfloat16 g_hx0h[BB * SS * DD], g_hx0l[BB * SS * DD];
__device__ __nv_bfloat16 g_hx1h[BB * SS * DD], g_hx1l[BB * SS * DD];
__device__ float g_pr0[BB * SS * 2 * DD], g_pr1[BB * SS * 2 * DD];
__device__ __nv_bfloat16 g_wth[8 * DW + 4 * DW2];
__device__ __nv_bfloat16 g_wtl[8 * DW + 4 * DW2];

// ================= weight transpose+split: ALL matrices, one launch =========
__global__ void wsplit_all(const float* __restrict__ lW, const float* __restrict__ rW,
                           const float* __restrict__ lhW, const float* __restrict__ rhW) {
    __shared__ float tile[32][33];
    int blk = blockIdx.x;
    const float* W;
    __nv_bfloat16 *th, *tl;
    int nb, kb, N;
    if (blk < 2048) {
        int mat = blk >> 8;          // 0..7
        int t = blk & 255;
        N = 512;
        nb = (t & 15) * 32; kb = (t >> 4) * 32;
        int slot;
        if (mat < 4) { W = lW + (size_t)mat * DW; slot = (mat < 3) ? mat : 6; }
        else         { int i = mat - 4; W = rW + (size_t)i * DW; slot = (i < 3) ? 3 + i : 7; }
        th = g_wth + (size_t)slot * DW;
        tl = g_wtl + (size_t)slot * DW;
    } else {
        int bb = blk - 2048;
        int mat = bb >> 9;           // 0..3
        int t = bb & 511;
        N = 1024;
        nb = (t & 31) * 32; kb = (t >> 5) * 32;
        W = (mat < 2) ? lhW + (size_t)mat * DW2 : rhW + (size_t)(mat - 2) * DW2;
        th = g_wth + HWO + (size_t)mat * DW2;
        tl = g_wtl + HWO + (size_t)mat * DW2;
    }
    int tx = threadIdx.x, ty = threadIdx.y;
    for (int r = ty; r < 32; r += 8)
        tile[r][tx] = W[(size_t)(kb + r) * N + nb + tx];
    __syncthreads();
    for (int r = ty; r < 32; r += 8) {
        float v = tile[tx][r];
        __nv_bfloat16 h, l; split2(v, h, l);
        size_t o = (size_t)(nb + r) * 512 + kb + tx;
        th[o] = h; tl[o] = l;
    }
}

__global__ void pack_bias(const float* __restrict__ lb, const float* __restrict__ rb) {
    int n = blockIdx.x * blockDim.x + threadIdx.x;
    if (n >= 6 * DD) return;
    int slot = n >> 9, loc = n & 511;
    g_bqkv[n] = (slot < 3) ? lb[slot * DD + loc] : rb[(slot - 3) * DD + loc];
}

// ================= elementwise =================
__global__ void build_new_in(const float* __restrict__ x,
                             const float* __restrict__ lp,
                             const float* __restrict__ rp) {
    int idx = blockIdx.x * blockDim.x + threadIdx.x;
    if (idx >= BB * S2S * DD) return;
    int d = idx & (DD - 1);
    int t = idx >> 9;
    int s = t % S2S;
    int b = t / S2S;
    float val;
    if (s < WW)            val = lp[s * DD + d];
    else if (s < WW + SS)  val = x[((size_t)(b * SS + (s - WW))) * DD + d];
    else                   val = rp[(s - WW - SS) * DD + d];
    g_nin[idx] = val;
    __nv_bfloat16 h, l; split2(val, h, l);
    g_ninh[idx] = h; g_ninl[idx] = l;
}

// fused-QKV banded attention; blockIdx.z = dir
__global__ void banded_attn_f(const float* __restrict__ qkv,
                              __nv_bfloat16* __restrict__ o0h, __nv_bfloat16* __restrict__ o0l,
                              __nv_bfloat16* __restrict__ o1h, __nv_bfloat16* __restrict__ o1l) {
    int dir = blockIdx.z;
    __nv_bfloat16* oh = dir ? o1h : o0h;
    __nv_bfloat16* ol = dir ? o1l : o0l;
    int qoff = dir * 3 * DD;
    int gw = (blockIdx.x * blockDim.x + threadIdx.x) >> 5;
    if (gw >= BB * SS * HH) return;
    int lane = threadIdx.x & 31;
    int h = gw & (HH - 1);
    int t = gw >> 3;
    int i = t & (SS - 1);
    int b = t >> 10;
    int qi = i + WW;
    int jlo, jhi;
    if (dir == 0) { jlo = qi - (WW + 1); if (jlo < 0) jlo = 0; jhi = qi; }
    else          { jlo = qi; jhi = qi + (WW + 1); if (jhi > S2S - 1) jhi = S2S - 1; }

    const int LDA = 6 * DD;
    const float* qp = qkv + ((size_t)(b * S2S + qi)) * LDA + qoff + h * DKK;
    float q0 = qp[lane], q1 = qp[lane + 32];

    float sc[WW + 2];
#pragma unroll
    for (int jj = 0; jj < WW + 2; jj++) {
        int j = jlo + jj;
        bool valid = (j <= jhi);
        int jc = valid ? j : jlo;
        const float* kp = qkv + ((size_t)(b * S2S + jc)) * LDA + qoff + DD + h * DKK;
        float s = q0 * kp[lane] + q1 * kp[lane + 32];
#pragma unroll
        for (int o = 16; o; o >>= 1) s += __shfl_xor_sync(0xffffffffu, s, o);
        sc[jj] = valid ? s * 0.125f : -1e30f;
    }
    float m = sc[0];
#pragma unroll
    for (int jj = 1; jj < WW + 2; jj++) m = fmaxf(m, sc[jj]);
    float sum = 0.f;
#pragma unroll
    for (int jj = 0; jj < WW + 2; jj++) { sc[jj] = expf(sc[jj] - m); sum += sc[jj]; }
    float inv = 1.f / sum;
    float o0 = 0.f, o1 = 0.f;
#pragma unroll
    for (int jj = 0; jj < WW + 2; jj++) {
        int j = jlo + jj;
        int jc = (j <= jhi) ? j : jlo;
        const float* vp = qkv + ((size_t)(b * S2S + jc)) * LDA + qoff + 2 * DD + h * DKK;
        o0 += sc[jj] * vp[lane];
        o1 += sc[jj] * vp[lane + 32];
    }
    size_t op = ((size_t)(b * SS + i)) * DD + h * DKK;
    __nv_bfloat16 hh, ll;
    split2(o0 * inv, hh, ll); oh[op + lane] = hh; ol[op + lane] = ll;
    split2(o1 * inv, hh, ll); oh[op + lane + 32] = hh; ol[op + lane + 32] = ll;
}

// add relative sums, z = side
__global__ void add_rel2(float* __restrict__ x0, float* __restrict__ x1,
                         const float* __restrict__ w0, const float* __restrict__ w1,
                         __nv_bfloat16* __restrict__ oh0, __nv_bfloat16* __restrict__ ol0,
                         __nv_bfloat16* __restrict__ oh1, __nv_bfloat16* __restrict__ ol1) {
    int z = blockIdx.z;
    float* xio = z ? x1 : x0;
    const float* w = z ? w1 : w0;
    __nv_bfloat16* oh = z ? oh1 : oh0;
    __nv_bfloat16* ol = z ? ol1 : ol0;
    int base = z ? WW : 0;
    int idx = blockIdx.x * blockDim.x + threadIdx.x;
    if (idx >= BB * SS * DD) return;
    int d = idx & (DD - 1);
    int t = idx >> 9;
    int i = t & (SS - 1);
    int b = t >> 10;
    float acc = xio[idx];
    const float* p = g_nin + ((size_t)(b * S2S + base + i)) * DD + d;
#pragma unroll
    for (int j = 0; j <= WW; j++) acc += w[j] * p[(size_t)j * DD];
    xio[idx] = acc;
    __nv_bfloat16 h, l; split2(acc, h, l);
    oh[idx] = h; ol[idx] = l;
}

// highway gate, z = side
__global__ void hw_gate2(const float* __restrict__ x0, const float* __restrict__ x1,
                         const float* __restrict__ p0, const float* __restrict__ p1,
                         float* __restrict__ d0, float* __restrict__ d1, int ldd,
                         __nv_bfloat16* __restrict__ dh0, __nv_bfloat16* __restrict__ dl0,
                         __nv_bfloat16* __restrict__ dh1, __nv_bfloat16* __restrict__ dl1) {
    int z = blockIdx.z;
    const float* x = z ? x1 : x0;
    const float* proj = z ? p1 : p0;
    float* dst = z ? d1 : d0;
    __nv_bfloat16* dh = z ? dh1 : dh0;
    __nv_bfloat16* dl = z ? dl1 : dl0;
    int idx = blockIdx.x * blockDim.x + threadIdx.x;
    if (idx >= BB * SS * DD) return;
    int row = idx >> 9;
    int d = idx & (DD - 1);
    float nl = proj[(size_t)row * (2 * DD) + d];
    float gz = proj[(size_t)row * (2 * DD) + DD + d];
    nl = fmaxf(nl, 0.f);
    float g = 1.f / (1.f + expf(-gz));
    float y = g * x[idx] + (1.f - g) * nl;
    dst[(size_t)row * ldd + d] = y;
    if (dh) {
        __nv_bfloat16 h, l; split2(y, h, l);
        dh[idx] = h; dl[idx] = l;
    }
}

// ================= fused 3-pass split-bf16 GEMM =================
// Per k-chunk load Ah,Al,Bh,Bl tiles; compute Ah*Bh + Ah*Bl + Al*Bh from regs.
// Tile 128x128, BK=32, 2-stage cp.async, 2 CTAs/SM (regs capped at 128).
#define ROWP   40
#define TILEB  (128 * ROWP * 2)        // 10240 B per tile
#define STG4   (4 * TILEB)             // 40960 B per stage
#define GSMEM3 (2 * STG4)              // 81920 B

struct GArg {
    const __nv_bfloat16 *ah, *al, *bh, *bl;
    const float* bias;
    float* c;
};

__device__ __forceinline__ void load_stage4(uint32_t sb, int st, const GArg& g,
                                            int row0, int col0, int K, int kb, int tid) {
    uint32_t base = sb + (uint32_t)st * STG4;
#pragma unroll
    for (int t = 0; t < 2; t++) {
        int v = tid + t * 256;
        int r = v >> 2, kc = v & 3;
        uint32_t off = (uint32_t)(r * ROWP + kc * 8) * 2;
        size_t ga = (size_t)(row0 + r) * K + kb + kc * 8;
        size_t gb = (size_t)(col0 + r) * K + kb + kc * 8;
        CP_A16(base + off,             g.ah + ga);
        CP_A16(base + TILEB + off,     g.al + ga);
        CP_A16(base + 2 * TILEB + off, g.bh + gb);
        CP_A16(base + 3 * TILEB + off, g.bl + gb);
    }
    CP_COMMIT();
}

__global__ __launch_bounds__(256, 2) void gemm3(
    GArg ga0, GArg ga1, int M, int N, int K)
{
    extern __shared__ char smem[];
    uint32_t sb = smem_u32(smem);
    const GArg g = blockIdx.z ? ga1 : ga0;
    const int tid = threadIdx.x, wid = tid >> 5, lane = tid & 31;
    const int row0 = blockIdx.y * 128, col0 = blockIdx.x * 128;
    const int wm = (wid >> 2) * 64;      // 0 or 64
    const int wn = (wid & 3) * 32;       // 0,32,64,96

    const int NC = K >> 5;               // 16 for K=512

    load_stage4(sb, 0, g, row0, col0, K, 0, tid);
    load_stage4(sb, 1, g, row0, col0, K, 32, tid);

    float d[16][4];
#pragma unroll
    for (int i = 0; i < 16; i++)
#pragma unroll
        for (int j = 0; j < 4; j++) d[i][j] = 0.f;

    for (int c = 0; c < NC; c++) {
        CP_WAIT(1);
        __syncthreads();
        int st = c & 1;
        uint32_t abh = sb + (uint32_t)st * STG4;
        uint32_t abl = abh + TILEB;
        uint32_t bbh = abh + 2 * TILEB;
        uint32_t bbl = abh + 3 * TILEB;
#pragma unroll
        for (int ks = 0; ks < 2; ks++) {
            int k0 = ks * 16;
            uint32_t ah[4][4], al[4][4], bh[4][2], bl[4][2];
#pragma unroll
            for (int im = 0; im < 4; im++) {
                int row = wm + im * 16 + (lane & 15);
                uint32_t off = (uint32_t)(row * ROWP + k0 + ((lane >> 4) << 3)) * 2;
                ldsm_x4(ah[im][0], ah[im][1], ah[im][2], ah[im][3], abh + off);
                ldsm_x4(al[im][0], al[im][1], al[im][2], al[im][3], abl + off);
            }
#pragma unroll
            for (int p = 0; p < 2; p++) {
                int m = lane >> 3;
                int row = wn + (2 * p + (m >> 1)) * 8 + (lane & 7);
                uint32_t off = (uint32_t)(row * ROWP + k0 + ((m & 1) << 3)) * 2;
                ldsm_x4(bh[2 * p][0], bh[2 * p][1], bh[2 * p + 1][0], bh[2 * p + 1][1], bbh + off);
                ldsm_x4(bl[2 * p][0], bl[2 * p][1], bl[2 * p + 1][0], bl[2 * p + 1][1], bbl + off);
            }
#pragma unroll
            for (int im = 0; im < 4; im++)
#pragma unroll
                for (int in = 0; in < 4; in++) {
                    float* dd = d[im * 4 + in];
                    mma16816(dd, ah[im], bh[in]);
                    mma16816(dd, ah[im], bl[in]);
                    mma16816(dd, al[im], bh[in]);
                }
        }
        __syncthreads();
        if (c + 2 < NC) load_stage4(sb, st, g, row0, col0, K, (c + 2) * 32, tid);
        else CP_COMMIT();
    }

    // epilogue: registers -> global with bias
#pragma unroll
    for (int im = 0; im < 4; im++) {
#pragma unroll
        for (int in = 0; in < 4; in++) {
            float* dd = d[im * 4 + in];
            int m = row0 + wm + im * 16 + (lane >> 2);
            int n = col0 + wn + in * 8 + ((lane & 3) << 1);
            float b0 = g.bias[n], b1 = g.bias[n + 1];
            float2 v0 = make_float2(dd[0] + b0, dd[1] + b1);
            *(float2*)&g.c[(size_t)m * N + n] = v0;
            float2 v1 = make_float2(dd[2] + b0, dd[3] + b1);
            *(float2*)&g.c[(size_t)(m + 8) * N + n] = v1;
        }
    }
}

// ================= launch =================
extern "C" void kernel_launch(void* const* d_in, const int* in_sizes, int n_in,
                              void* d_out, int out_size)
{
    const float* x    = (const float*)d_in[0];
    const float* lW   = (const float*)d_in[1];
    const float* lb   = (const float*)d_in[2];
    const float* rW   = (const float*)d_in[3];
    const float* rb   = (const float*)d_in[4];
    const float* lpad = (const float*)d_in[5];
    const float* rpad = (const float*)d_in[6];
    const float* lw   = (const float*)d_in[7];
    const float* rw   = (const float*)d_in[8];
    const float* lhW  = (const float*)d_in[9];
    const float* lhb  = (const float*)d_in[10];
    const float* rhW  = (const float*)d_in[11];
    const float* rhb  = (const float*)d_in[12];
    float* out = (float*)d_out;

    cudaFuncSetAttribute(gemm3, cudaFuncAttributeMaxDynamicSharedMemorySize, GSMEM3);

    float *qkv, *bqkv, *hx0, *hx1, *pr0, *pr1;
    __nv_bfloat16 *ninh, *ninl, *a0h, *a0l, *a1h, *a1l;
    __nv_bfloat16 *hx0h, *hx0l, *hx1h, *hx1l, *wth, *wtl;
    cudaGetSymbolAddress((void**)&qkv, g_qkv);
    cudaGetSymbolAddress((void**)&bqkv, g_bqkv);
    cudaGetSymbolAddress((void**)&hx0, g_hx0); cudaGetSymbolAddress((void**)&hx1, g_hx1);
    cudaGetSymbolAddress((void**)&pr0, g_pr0); cudaGetSymbolAddress((void**)&pr1, g_pr1);
    cudaGetSymbolAddress((void**)&ninh, g_ninh); cudaGetSymbolAddress((void**)&ninl, g_ninl);
    cudaGetSymbolAddress((void**)&a0h, g_a0h); cudaGetSymbolAddress((void**)&a0l, g_a0l);
    cudaGetSymbolAddress((void**)&a1h, g_a1h); cudaGetSymbolAddress((void**)&a1l, g_a1l);
    cudaGetSymbolAddress((void**)&hx0h, g_hx0h); cudaGetSymbolAddress((void**)&hx0l, g_hx0l);
    cudaGetSymbolAddress((void**)&hx1h, g_hx1h); cudaGetSymbolAddress((void**)&hx1l, g_hx1l);
    cudaGetSymbolAddress((void**)&wth, g_wth); cudaGetSymbolAddress((void**)&wtl, g_wtl);

    // weight prep: single launch + bias pack
    wsplit_all<<<4096, dim3(32, 8)>>>(lW, rW, lhW, rhW);
    pack_bias<<<12, 256>>>(lb, rb);
    build_new_in<<<(BB * S2S * DD + 255) / 256, 256>>>(x, lpad, rpad);

    // fused QKV: M=8320, N=3072, K=512
    {
        GArg a = {ninh, ninl, wth, wtl, bqkv, qkv};
        gemm3<<<dim3(24, 65, 1), 256, GSMEM3>>>(a, a, BB * S2S, 6 * DD, DD);
    }

    // banded attention (both dirs)
    banded_attn_f<<<dim3((BB * SS * HH * 32) / 256, 1, 2), 256>>>(qkv, a0h, a0l, a1h, a1l);

    // output projections: z=2
    {
        GArg p0 = {a0h, a0l, wth + 6 * (size_t)DW, wtl + 6 * (size_t)DW, lb + 3 * DD, hx0};
        GArg p1 = {a1h, a1l, wth + 7 * (size_t)DW, wtl + 7 * (size_t)DW, rb + 3 * DD, hx1};
        gemm3<<<dim3(4, 64, 2), 256, GSMEM3>>>(p0, p1, BB * SS, DD, DD);
    }

    int ne = BB * SS * DD;
    add_rel2<<<dim3((ne + 255) / 256, 1, 2), 256>>>(hx0, hx1, lw, rw, hx0h, hx0l, hx1h, hx1l);

    // highway layer 1
    {
        GArg h0 = {hx0h, hx0l, wth + HWO, wtl + HWO, lhb, pr0};
        GArg h1 = {hx1h, hx1l, wth + HWO + 2 * (size_t)DW2, wtl + HWO + 2 * (size_t)DW2, rhb, pr1};
        gemm3<<<dim3(8, 64, 2), 256, GSMEM3>>>(h0, h1, BB * SS, 2 * DD, DD);
    }
    hw_gate2<<<dim3((ne + 255) / 256, 1, 2), 256>>>(hx0, hx1, pr0, pr1, hx0, hx1, DD,
                                                    hx0h, hx0l, hx1h, hx1l);
    // highway layer 2 -> strided output
    {
        GArg h0 = {hx0h, hx0l, wth + HWO + (size_t)DW2, wtl + HWO + (size_t)DW2, lhb + 2 * DD, pr0};
        GArg h1 = {hx1h, hx1l, wth + HWO + 3 * (size_t)DW2, wtl + HWO + 3 * (size_t)DW2, rhb + 2 * DD, pr1};
        gemm3<<<dim3(8, 64, 2), 256, GSMEM3>>>(h0, h1, BB * SS, 2 * DD, DD);
    }
    hw_gate2<<<dim3((ne + 255) / 256, 1, 2), 256>>>(hx0, hx1, pr0, pr1, out + 0, out + DD, 2 * DD,
                                                    nullptr, nullptr, nullptr, nullptr);
}

// round 9
// speedup vs baseline: 2.4434x; 1.0223x over previous
#include <cuda_runtime.h>
#include <cuda_bf16.h>
#include <math.h>
#include <stdint.h>

#define BB   8
#define SS   1024
#define DD   512
#define HH   8
#define WW   8
#define S2S  1040
#define DKK  64

// ================= helpers =================
__device__ __forceinline__ uint32_t smem_u32(const void* p) {
    uint32_t a;
    asm("{ .reg .u64 t; cvta.to.shared.u64 t, %1; cvt.u32.u64 %0, t; }" : "=r"(a) : "l"(p));
    return a;
}
#define CP_A16(dst, src) \
    asm volatile("cp.async.cg.shared.global [%0], [%1], 16;" :: "r"((uint32_t)(dst)), "l"(src))
#define CP_COMMIT() asm volatile("cp.async.commit_group;" ::: "memory")
#define CP_WAIT(n)  asm volatile("cp.async.wait_group %0;" :: "n"(n) : "memory")

__device__ __forceinline__ void ldsm_x4(uint32_t& r0, uint32_t& r1, uint32_t& r2, uint32_t& r3, uint32_t addr) {
    asm volatile("ldmatrix.sync.aligned.m8n8.x4.shared.b16 {%0,%1,%2,%3}, [%4];"
                 : "=r"(r0), "=r"(r1), "=r"(r2), "=r"(r3) : "r"(addr));
}
__device__ __forceinline__ void mma16816(float* d, const uint32_t* a, const uint32_t* b) {
    asm volatile("mma.sync.aligned.m16n8k16.row.col.f32.bf16.bf16.f32 "
                 "{%0,%1,%2,%3}, {%4,%5,%6,%7}, {%8,%9}, {%0,%1,%2,%3};"
                 : "+f"(d[0]), "+f"(d[1]), "+f"(d[2]), "+f"(d[3])
                 : "r"(a[0]), "r"(a[1]), "r"(a[2]), "r"(a[3]), "r"(b[0]), "r"(b[1]));
}
__device__ __forceinline__ void split2(float x, __nv_bfloat16& h, __nv_bfloat16& l) {
    h = __float2bfloat16(x);
    l = __float2bfloat16(x - __bfloat162float(h));
}

// ================= scratch (device globals) =================
#define DW   (DD * DD)
#define DW2  (DD * 2 * DD)
#define HWO  (8 * DW)
__device__ float g_nin[BB * S2S * DD];
__device__ __nv_bfloat16 g_ninh[BB * S2S * DD];
__device__ __nv_bfloat16 g_ninl[BB * S2S * DD];
__device__ float g_qkv[BB * S2S * 6 * DD];                // fused QKV output (lda=3072)
__device__ float g_bqkv[6 * DD];
__device__ float g_bhw[4 * 2 * DD];                       // interleaved hw biases
__device__ __nv_bfloat16 g_a0h[BB * SS * DD], g_a0l[BB * SS * DD];
__device__ __nv_bfloat16 g_a1h[BB * SS * DD], g_a1l[BB * SS * DD];
__device__ float g_hx0[BB * SS * DD], g_hx1[BB * SS * DD];
__device__ __nv_bfloat16 g_hx0h[BB * SS * DD], g_hx0l[BB * SS * DD];
__device__ __nv_bfloat16 g_hx1h[BB * SS * DD], g_hx1l[BB * SS * DD];
__device__ __nv_bfloat16 g_hy0h[BB * SS * DD], g_hy0l[BB * SS * DD];
__device__ __nv_bfloat16 g_hy1h[BB * SS * DD], g_hy1l[BB * SS * DD];
__device__ __nv_bfloat16 g_wth[8 * DW + 4 * DW2];
__device__ __nv_bfloat16 g_wtl[8 * DW + 4 * DW2];

// ================= weight transpose+split, one launch ======================
// QKV/proj slots 0-7 unchanged. Highway matrices get column-interleaved rows:
// packed row p: p even -> nl col p/2, p odd -> gate col 512+p/2.
__global__ void wsplit_all(const float* __restrict__ lW, const float* __restrict__ rW,
                           const float* __restrict__ lhW, const float* __restrict__ rhW) {
    __shared__ float tile[32][33];
    int blk = blockIdx.x;
    const float* W;
    __nv_bfloat16 *th, *tl;
    int nb, kb, N;
    bool hw = false;
    if (blk < 2048) {
        int mat = blk >> 8;          // 0..7
        int t = blk & 255;
        N = 512;
        nb = (t & 15) * 32; kb = (t >> 4) * 32;
        int slot;
        if (mat < 4) { W = lW + (size_t)mat * DW; slot = (mat < 3) ? mat : 6; }
        else         { int i = mat - 4; W = rW + (size_t)i * DW; slot = (i < 3) ? 3 + i : 7; }
        th = g_wth + (size_t)slot * DW;
        tl = g_wtl + (size_t)slot * DW;
    } else {
        hw = true;
        int bb = blk - 2048;
        int mat = bb >> 9;           // 0..3  (lh0, lh1, rh0, rh1)
        int t = bb & 511;
        N = 1024;
        nb = (t & 31) * 32; kb = (t >> 5) * 32;
        W = (mat < 2) ? lhW + (size_t)mat * DW2 : rhW + (size_t)(mat - 2) * DW2;
        th = g_wth + HWO + (size_t)mat * DW2;
        tl = g_wtl + HWO + (size_t)mat * DW2;
    }
    int tx = threadIdx.x, ty = threadIdx.y;
    for (int r = ty; r < 32; r += 8)
        tile[r][tx] = W[(size_t)(kb + r) * N + nb + tx];
    __syncthreads();
    for (int r = ty; r < 32; r += 8) {
        float v = tile[tx][r];
        __nv_bfloat16 h, l; split2(v, h, l);
        int nrow = nb + r;
        int p = hw ? ((nrow < DD) ? 2 * nrow : 2 * (nrow - DD) + 1) : nrow;
        size_t o = (size_t)p * 512 + kb + tx;
        th[o] = h; tl[o] = l;
    }
}

// QKV packed bias + interleaved highway biases
__global__ void pack_bias(const float* __restrict__ lb, const float* __restrict__ rb,
                          const float* __restrict__ lhb, const float* __restrict__ rhb) {
    int n = blockIdx.x * blockDim.x + threadIdx.x;
    if (n < 6 * DD) {
        int slot = n >> 9, loc = n & 511;
        g_bqkv[n] = (slot < 3) ? lb[slot * DD + loc] : rb[(slot - 3) * DD + loc];
    } else if (n < 6 * DD + 4 * 2 * DD) {
        int j = n - 6 * DD;
        int mat = j >> 10, p = j & 1023;
        int orig = (p & 1) ? DD + (p >> 1) : (p >> 1);
        g_bhw[mat * 2 * DD + p] = (mat < 2) ? lhb[mat * 2 * DD + orig]
                                            : rhb[(mat - 2) * 2 * DD + orig];
    }
}

// ================= elementwise =================
__global__ void build_new_in(const float* __restrict__ x,
                             const float* __restrict__ lp,
                             const float* __restrict__ rp) {
    int idx = blockIdx.x * blockDim.x + threadIdx.x;
    if (idx >= BB * S2S * DD) return;
    int d = idx & (DD - 1);
    int t = idx >> 9;
    int s = t % S2S;
    int b = t / S2S;
    float val;
    if (s < WW)            val = lp[s * DD + d];
    else if (s < WW + SS)  val = x[((size_t)(b * SS + (s - WW))) * DD + d];
    else                   val = rp[(s - WW - SS) * DD + d];
    g_nin[idx] = val;
    __nv_bfloat16 h, l; split2(val, h, l);
    g_ninh[idx] = h; g_ninl[idx] = l;
}

// fused-QKV banded attention; blockIdx.z = dir
__global__ void banded_attn_f(const float* __restrict__ qkv,
                              __nv_bfloat16* __restrict__ o0h, __nv_bfloat16* __restrict__ o0l,
                              __nv_bfloat16* __restrict__ o1h, __nv_bfloat16* __restrict__ o1l) {
    int dir = blockIdx.z;
    __nv_bfloat16* oh = dir ? o1h : o0h;
    __nv_bfloat16* ol = dir ? o1l : o0l;
    int qoff = dir * 3 * DD;
    int gw = (blockIdx.x * blockDim.x + threadIdx.x) >> 5;
    if (gw >= BB * SS * HH) return;
    int lane = threadIdx.x & 31;
    int h = gw & (HH - 1);
    int t = gw >> 3;
    int i = t & (SS - 1);
    int b = t >> 10;
    int qi = i + WW;
    int jlo, jhi;
    if (dir == 0) { jlo = qi - (WW + 1); if (jlo < 0) jlo = 0; jhi = qi; }
    else          { jlo = qi; jhi = qi + (WW + 1); if (jhi > S2S - 1) jhi = S2S - 1; }

    const int LDA = 6 * DD;
    const float* qp = qkv + ((size_t)(b * S2S + qi)) * LDA + qoff + h * DKK;
    float q0 = qp[lane], q1 = qp[lane + 32];

    float sc[WW + 2];
#pragma unroll
    for (int jj = 0; jj < WW + 2; jj++) {
        int j = jlo + jj;
        bool valid = (j <= jhi);
        int jc = valid ? j : jlo;
        const float* kp = qkv + ((size_t)(b * S2S + jc)) * LDA + qoff + DD + h * DKK;
        float s = q0 * kp[lane] + q1 * kp[lane + 32];
#pragma unroll
        for (int o = 16; o; o >>= 1) s += __shfl_xor_sync(0xffffffffu, s, o);
        sc[jj] = valid ? s * 0.125f : -1e30f;
    }
    float m = sc[0];
#pragma unroll
    for (int jj = 1; jj < WW + 2; jj++) m = fmaxf(m, sc[jj]);
    float sum = 0.f;
#pragma unroll
    for (int jj = 0; jj < WW + 2; jj++) { sc[jj] = expf(sc[jj] - m); sum += sc[jj]; }
    float inv = 1.f / sum;
    float o0 = 0.f, o1 = 0.f;
#pragma unroll
    for (int jj = 0; jj < WW + 2; jj++) {
        int j = jlo + jj;
        int jc = (j <= jhi) ? j : jlo;
        const float* vp = qkv + ((size_t)(b * S2S + jc)) * LDA + qoff + 2 * DD + h * DKK;
        o0 += sc[jj] * vp[lane];
        o1 += sc[jj] * vp[lane + 32];
    }
    size_t op = ((size_t)(b * SS + i)) * DD + h * DKK;
    __nv_bfloat16 hh, ll;
    split2(o0 * inv, hh, ll); oh[op + lane] = hh; ol[op + lane] = ll;
    split2(o1 * inv, hh, ll); oh[op + lane + 32] = hh; ol[op + lane + 32] = ll;
}

// ================= fused split-bf16 GEMM with fused epilogues ==============
// mainloop: Ah*Bh + Ah*Bl + Al*Bh, 128x128 tile, BK=32, 2-stage, 2 CTAs/SM.
// epilogue modes:
//   0: C = acc + bias
//   1: highway gate. Weights column-interleaved (even=nl, odd=gate):
//      y = sig(gz)*x + (1-sig)*relu(nl); write c[m*lddc+u] (+ optional hi/lo)
//   2: rel-add. y = acc + bias + sum_j relw[j]*nin[b, base+i+j, n];
//      write c fp32 + hi/lo bf16
#define ROWP   40
#define TILEB  (128 * ROWP * 2)        // 10240 B per tile
#define STG4   (4 * TILEB)             // 40960 B per stage
#define GSMEM3 (2 * STG4)              // 81920 B

struct GArg {
    const __nv_bfloat16 *ah, *al, *bh, *bl;
    const float* bias;
    float* c;
    const float* xin;          // mode 1
    const float* relw;         // mode 2
    __nv_bfloat16 *dh, *dl;    // modes 1,2 (optional in 1)
    int mode, base, lddc;
};

__device__ __forceinline__ void load_stage4(uint32_t sb, int st, const GArg& g,
                                            int row0, int col0, int K, int kb, int tid) {
    uint32_t base = sb + (uint32_t)st * STG4;
#pragma unroll
    for (int t = 0; t < 2; t++) {
        int v = tid + t * 256;
        int r = v >> 2, kc = v & 3;
        uint32_t off = (uint32_t)(r * ROWP + kc * 8) * 2;
        size_t ga = (size_t)(row0 + r) * K + kb + kc * 8;
        size_t gb = (size_t)(col0 + r) * K + kb + kc * 8;
        CP_A16(base + off,             g.ah + ga);
        CP_A16(base + TILEB + off,     g.al + ga);
        CP_A16(base + 2 * TILEB + off, g.bh + gb);
        CP_A16(base + 3 * TILEB + off, g.bl + gb);
    }
    CP_COMMIT();
}

__global__ __launch_bounds__(256, 2) void gemm3(
    GArg ga0, GArg ga1, int M, int N, int K)
{
    extern __shared__ char smem[];
    uint32_t sb = smem_u32(smem);
    const GArg g = blockIdx.z ? ga1 : ga0;
    const int tid = threadIdx.x, wid = tid >> 5, lane = tid & 31;
    const int row0 = blockIdx.y * 128, col0 = blockIdx.x * 128;
    const int wm = (wid >> 2) * 64;      // 0 or 64
    const int wn = (wid & 3) * 32;       // 0,32,64,96

    const int NC = K >> 5;               // 16 for K=512

    load_stage4(sb, 0, g, row0, col0, K, 0, tid);
    load_stage4(sb, 1, g, row0, col0, K, 32, tid);

    float d[16][4];
#pragma unroll
    for (int i = 0; i < 16; i++)
#pragma unroll
        for (int j = 0; j < 4; j++) d[i][j] = 0.f;

    for (int c = 0; c < NC; c++) {
        CP_WAIT(1);
        __syncthreads();
        int st = c & 1;
        uint32_t abh = sb + (uint32_t)st * STG4;
        uint32_t abl = abh + TILEB;
        uint32_t bbh = abh + 2 * TILEB;
        uint32_t bbl = abh + 3 * TILEB;
#pragma unroll
        for (int ks = 0; ks < 2; ks++) {
            int k0 = ks * 16;
            uint32_t ah[4][4], al[4][4], bh[4][2], bl[4][2];
#pragma unroll
            for (int im = 0; im < 4; im++) {
                int row = wm + im * 16 + (lane & 15);
                uint32_t off = (uint32_t)(row * ROWP + k0 + ((lane >> 4) << 3)) * 2;
                ldsm_x4(ah[im][0], ah[im][1], ah[im][2], ah[im][3], abh + off);
                ldsm_x4(al[im][0], al[im][1], al[im][2], al[im][3], abl + off);
            }
#pragma unroll
            for (int p = 0; p < 2; p++) {
                int m = lane >> 3;
                int row = wn + (2 * p + (m >> 1)) * 8 + (lane & 7);
                uint32_t off = (uint32_t)(row * ROWP + k0 + ((m & 1) << 3)) * 2;
                ldsm_x4(bh[2 * p][0], bh[2 * p][1], bh[2 * p + 1][0], bh[2 * p + 1][1], bbh + off);
                ldsm_x4(bl[2 * p][0], bl[2 * p][1], bl[2 * p + 1][0], bl[2 * p + 1][1], bbl + off);
            }
#pragma unroll
            for (int im = 0; im < 4; im++)
#pragma unroll
                for (int in = 0; in < 4; in++) {
                    float* dd = d[im * 4 + in];
                    mma16816(dd, ah[im], bh[in]);
                    mma16816(dd, ah[im], bl[in]);
                    mma16816(dd, al[im], bh[in]);
                }
        }
        __syncthreads();
        if (c + 2 < NC) load_stage4(sb, st, g, row0, col0, K, (c + 2) * 32, tid);
        else CP_COMMIT();
    }

    // ================= epilogues =================
    if (g.mode == 0) {
#pragma unroll
        for (int im = 0; im < 4; im++)
#pragma unroll
            for (int in = 0; in < 4; in++) {
                float* dd = d[im * 4 + in];
                int m = row0 + wm + im * 16 + (lane >> 2);
                int n = col0 + wn + in * 8 + ((lane & 3) << 1);
                float b0 = g.bias[n], b1 = g.bias[n + 1];
                *(float2*)&g.c[(size_t)m * N + n] = make_float2(dd[0] + b0, dd[1] + b1);
                *(float2*)&g.c[(size_t)(m + 8) * N + n] = make_float2(dd[2] + b0, dd[3] + b1);
            }
    } else if (g.mode == 2) {
        float w[WW + 1];
#pragma unroll
        for (int j = 0; j <= WW; j++) w[j] = g.relw[j];
#pragma unroll
        for (int im = 0; im < 4; im++)
#pragma unroll
            for (int in = 0; in < 4; in++) {
                float* dd = d[im * 4 + in];
                int m = row0 + wm + im * 16 + (lane >> 2);
                int n = col0 + wn + in * 8 + ((lane & 3) << 1);
                int b = m >> 10, i = m & 1023;
                const float* np = g_nin + ((size_t)(b * S2S + g.base + i)) * DD + n;
                float b0 = g.bias[n], b1 = g.bias[n + 1];
                float y0 = dd[0] + b0, y1 = dd[1] + b1;
                float y2 = dd[2] + b0, y3 = dd[3] + b1;
#pragma unroll
                for (int j = 0; j <= WW; j++) {
                    float2 v = *(const float2*)(np + (size_t)j * DD);
                    float2 v2 = *(const float2*)(np + (size_t)(j + 8) * DD);
                    y0 += w[j] * v.x;  y1 += w[j] * v.y;
                    y2 += w[j] * v2.x; y3 += w[j] * v2.y;
                }
                *(float2*)&g.c[(size_t)m * DD + n] = make_float2(y0, y1);
                *(float2*)&g.c[(size_t)(m + 8) * DD + n] = make_float2(y2, y3);
                __nv_bfloat16 h0, l0, h1, l1;
                split2(y0, h0, l0); split2(y1, h1, l1);
                *(__nv_bfloat162*)&g.dh[(size_t)m * DD + n] = __nv_bfloat162(h0, h1);
                *(__nv_bfloat162*)&g.dl[(size_t)m * DD + n] = __nv_bfloat162(l0, l1);
                split2(y2, h0, l0); split2(y3, h1, l1);
                *(__nv_bfloat162*)&g.dh[(size_t)(m + 8) * DD + n] = __nv_bfloat162(h0, h1);
                *(__nv_bfloat162*)&g.dl[(size_t)(m + 8) * DD + n] = __nv_bfloat162(l0, l1);
            }
    } else {  // mode 1: highway gate
#pragma unroll
        for (int im = 0; im < 4; im++)
#pragma unroll
            for (int in = 0; in < 4; in++) {
                float* dd = d[im * 4 + in];
                int m = row0 + wm + im * 16 + (lane >> 2);
                int n = col0 + wn + in * 8 + ((lane & 3) << 1);
                int u = n >> 1;
                float b0 = g.bias[n], b1 = g.bias[n + 1];
                float nl0 = fmaxf(dd[0] + b0, 0.f);
                float gz0 = dd[1] + b1;
                float nl1 = fmaxf(dd[2] + b0, 0.f);
                float gz1 = dd[3] + b1;
                float x0 = g.xin[(size_t)m * DD + u];
                float x1 = g.xin[(size_t)(m + 8) * DD + u];
                float s0 = 1.f / (1.f + expf(-gz0));
                float s1 = 1.f / (1.f + expf(-gz1));
                float y0 = s0 * x0 + (1.f - s0) * nl0;
                float y1 = s1 * x1 + (1.f - s1) * nl1;
                g.c[(size_t)m * g.lddc + u] = y0;
                g.c[(size_t)(m + 8) * g.lddc + u] = y1;
                if (g.dh) {
                    __nv_bfloat16 h, l;
                    split2(y0, h, l);
                    g.dh[(size_t)m * DD + u] = h; g.dl[(size_t)m * DD + u] = l;
                    split2(y1, h, l);
                    g.dh[(size_t)(m + 8) * DD + u] = h; g.dl[(size_t)(m + 8) * DD + u] = l;
                }
            }
    }
}

// ================= launch =================
extern "C" void kernel_launch(void* const* d_in, const int* in_sizes, int n_in,
                              void* d_out, int out_size)
{
    const float* x    = (const float*)d_in[0];
    const float* lW   = (const float*)d_in[1];
    const float* lb   = (const float*)d_in[2];
    const float* rW   = (const float*)d_in[3];
    const float* rb   = (const float*)d_in[4];
    const float* lpad = (const float*)d_in[5];
    const float* rpad = (const float*)d_in[6];
    const float* lw   = (const float*)d_in[7];
    const float* rw   = (const float*)d_in[8];
    const float* lhW  = (const float*)d_in[9];
    const float* lhb  = (const float*)d_in[10];
    const float* rhW  = (const float*)d_in[11];
    const float* rhb  = (const float*)d_in[12];
    float* out = (float*)d_out;

    cudaFuncSetAttribute(gemm3, cudaFuncAttributeMaxDynamicSharedMemorySize, GSMEM3);

    float *qkv, *bqkv, *bhw, *hx0, *hx1;
    __nv_bfloat16 *ninh, *ninl, *a0h, *a0l, *a1h, *a1l;
    __nv_bfloat16 *hx0h, *hx0l, *hx1h, *hx1l;
    __nv_bfloat16 *hy0h, *hy0l, *hy1h, *hy1l, *wth, *wtl;
    cudaGetSymbolAddress((void**)&qkv, g_qkv);
    cudaGetSymbolAddress((void**)&bqkv, g_bqkv);
    cudaGetSymbolAddress((void**)&bhw, g_bhw);
    cudaGetSymbolAddress((void**)&hx0, g_hx0); cudaGetSymbolAddress((void**)&hx1, g_hx1);
    cudaGetSymbolAddress((void**)&ninh, g_ninh); cudaGetSymbolAddress((void**)&ninl, g_ninl);
    cudaGetSymbolAddress((void**)&a0h, g_a0h); cudaGetSymbolAddress((void**)&a0l, g_a0l);
    cudaGetSymbolAddress((void**)&a1h, g_a1h); cudaGetSymbolAddress((void**)&a1l, g_a1l);
    cudaGetSymbolAddress((void**)&hx0h, g_hx0h); cudaGetSymbolAddress((void**)&hx0l, g_hx0l);
    cudaGetSymbolAddress((void**)&hx1h, g_hx1h); cudaGetSymbolAddress((void**)&hx1l, g_hx1l);
    cudaGetSymbolAddress((void**)&hy0h, g_hy0h); cudaGetSymbolAddress((void**)&hy0l, g_hy0l);
    cudaGetSymbolAddress((void**)&hy1h, g_hy1h); cudaGetSymbolAddress((void**)&hy1l, g_hy1l);
    cudaGetSymbolAddress((void**)&wth, g_wth); cudaGetSymbolAddress((void**)&wtl, g_wtl);

    wsplit_all<<<4096, dim3(32, 8)>>>(lW, rW, lhW, rhW);
    pack_bias<<<28, 256>>>(lb, rb, lhb, rhb);
    build_new_in<<<(BB * S2S * DD + 255) / 256, 256>>>(x, lpad, rpad);

    // fused QKV: M=8320, N=3072, K=512 (mode 0)
    {
        GArg a = {ninh, ninl, wth, wtl, bqkv, qkv,
                  nullptr, nullptr, nullptr, nullptr, 0, 0, 0};
        gemm3<<<dim3(24, 65, 1), 256, GSMEM3>>>(a, a, BB * S2S, 6 * DD, DD);
    }

    // banded attention (both dirs)
    banded_attn_f<<<dim3((BB * SS * HH * 32) / 256, 1, 2), 256>>>(qkv, a0h, a0l, a1h, a1l);

    // output projections + fused rel-add (mode 2)
    {
        GArg p0 = {a0h, a0l, wth + 6 * (size_t)DW, wtl + 6 * (size_t)DW, lb + 3 * DD, hx0,
                   nullptr, lw, hx0h, hx0l, 2, 0, DD};
        GArg p1 = {a1h, a1l, wth + 7 * (size_t)DW, wtl + 7 * (size_t)DW, rb + 3 * DD, hx1,
                   nullptr, rw, hx1h, hx1l, 2, WW, DD};
        gemm3<<<dim3(4, 64, 2), 256, GSMEM3>>>(p0, p1, BB * SS, DD, DD);
    }

    // highway layer 1 (mode 1, gate fused): reads hx*h/l, writes hx* fp32 in-place + hy*h/l
    {
        GArg h0 = {hx0h, hx0l, wth + HWO, wtl + HWO, bhw + 0, hx0,
                   hx0, nullptr, hy0h, hy0l, 1, 0, DD};
        GArg h1 = {hx1h, hx1l, wth + HWO + 2 * (size_t)DW2, wtl + HWO + 2 * (size_t)DW2, bhw + 2 * 2 * DD, hx1,
                   hx1, nullptr, hy1h, hy1l, 1, 0, DD};
        gemm3<<<dim3(8, 64, 2), 256, GSMEM3>>>(h0, h1, BB * SS, 2 * DD, DD);
    }
    // highway layer 2 (mode 1) -> strided output
    {
        GArg h0 = {hy0h, hy0l, wth + HWO + (size_t)DW2, wtl + HWO + (size_t)DW2, bhw + 1 * 2 * DD, out + 0,
                   hx0, nullptr, nullptr, nullptr, 1, 0, 2 * DD};
        GArg h1 = {hy1h, hy1l, wth + HWO + 3 * (size_t)DW2, wtl + HWO + 3 * (size_t)DW2, bhw + 3 * 2 * DD, out + DD,
                   hx1, nullptr, nullptr, nullptr, 1, 0, 2 * DD};
        gemm3<<<dim3(8, 64, 2), 256, GSMEM3>>>(h0, h1, BB * SS, 2 * DD, DD);
    }
}

// round 10
// speedup vs baseline: 2.5618x; 1.0485x over previous
#include <cuda_runtime.h>
#include <cuda_bf16.h>
#include <math.h>
#include <stdint.h>

#define BB   8
#define SS   1024
#define DD   512
#define HH   8
#define WW   8
#define S2S  1040
#define DKK  64

// ================= helpers =================
__device__ __forceinline__ uint32_t smem_u32(const void* p) {
    uint32_t a;
    asm("{ .reg .u64 t; cvta.to.shared.u64 t, %1; cvt.u32.u64 %0, t; }" : "=r"(a) : "l"(p));
    return a;
}
#define CP_A16(dst, src) \
    asm volatile("cp.async.cg.shared.global [%0], [%1], 16;" :: "r"((uint32_t)(dst)), "l"(src))
#define CP_COMMIT() asm volatile("cp.async.commit_group;" ::: "memory")
#define CP_WAIT(n)  asm volatile("cp.async.wait_group %0;" :: "n"(n) : "memory")

__device__ __forceinline__ void ldsm_x4(uint32_t& r0, uint32_t& r1, uint32_t& r2, uint32_t& r3, uint32_t addr) {
    asm volatile("ldmatrix.sync.aligned.m8n8.x4.shared.b16 {%0,%1,%2,%3}, [%4];"
                 : "=r"(r0), "=r"(r1), "=r"(r2), "=r"(r3) : "r"(addr));
}
__device__ __forceinline__ void mma16816(float* d, const uint32_t* a, const uint32_t* b) {
    asm volatile("mma.sync.aligned.m16n8k16.row.col.f32.bf16.bf16.f32 "
                 "{%0,%1,%2,%3}, {%4,%5,%6,%7}, {%8,%9}, {%0,%1,%2,%3};"
                 : "+f"(d[0]), "+f"(d[1]), "+f"(d[2]), "+f"(d[3])
                 : "r"(a[0]), "r"(a[1]), "r"(a[2]), "r"(a[3]), "r"(b[0]), "r"(b[1]));
}
__device__ __forceinline__ void split2(float x, __nv_bfloat16& h, __nv_bfloat16& l) {
    h = __float2bfloat16(x);
    l = __float2bfloat16(x - __bfloat162float(h));
}

// ================= scratch (device globals) =================
#define DW   (DD * DD)
#define DW2  (DD * 2 * DD)
#define HWO  (8 * DW)
__device__ float g_nin[BB * S2S * DD];
__device__ __nv_bfloat16 g_ninh[BB * S2S * DD];
__device__ __nv_bfloat16 g_ninl[BB * S2S * DD];
__device__ float g_qkv[BB * S2S * 6 * DD];                // fused QKV output (lda=3072)
__device__ float g_bqkv[6 * DD];
__device__ float g_bhw[4 * 2 * DD];                       // interleaved hw biases
__device__ __nv_bfloat16 g_a0h[BB * SS * DD], g_a0l[BB * SS * DD];
__device__ __nv_bfloat16 g_a1h[BB * SS * DD], g_a1l[BB * SS * DD];
__device__ float g_hx0[BB * SS * DD], g_hx1[BB * SS * DD];
__device__ __nv_bfloat16 g_hx0h[BB * SS * DD], g_hx0l[BB * SS * DD];
__device__ __nv_bfloat16 g_hx1h[BB * SS * DD], g_hx1l[BB * SS * DD];
__device__ __nv_bfloat16 g_hy0h[BB * SS * DD], g_hy0l[BB * SS * DD];
__device__ __nv_bfloat16 g_hy1h[BB * SS * DD], g_hy1l[BB * SS * DD];
__device__ __nv_bfloat16 g_wth[8 * DW + 4 * DW2];
__device__ __nv_bfloat16 g_wtl[8 * DW + 4 * DW2];

// ================= weight transpose+split, one launch ======================
__global__ void wsplit_all(const float* __restrict__ lW, const float* __restrict__ rW,
                           const float* __restrict__ lhW, const float* __restrict__ rhW) {
    __shared__ float tile[32][33];
    int blk = blockIdx.x;
    const float* W;
    __nv_bfloat16 *th, *tl;
    int nb, kb, N;
    bool hw = false;
    if (blk < 2048) {
        int mat = blk >> 8;          // 0..7
        int t = blk & 255;
        N = 512;
        nb = (t & 15) * 32; kb = (t >> 4) * 32;
        int slot;
        if (mat < 4) { W = lW + (size_t)mat * DW; slot = (mat < 3) ? mat : 6; }
        else         { int i = mat - 4; W = rW + (size_t)i * DW; slot = (i < 3) ? 3 + i : 7; }
        th = g_wth + (size_t)slot * DW;
        tl = g_wtl + (size_t)slot * DW;
    } else {
        hw = true;
        int bb = blk - 2048;
        int mat = bb >> 9;           // 0..3  (lh0, lh1, rh0, rh1)
        int t = bb & 511;
        N = 1024;
        nb = (t & 31) * 32; kb = (t >> 5) * 32;
        W = (mat < 2) ? lhW + (size_t)mat * DW2 : rhW + (size_t)(mat - 2) * DW2;
        th = g_wth + HWO + (size_t)mat * DW2;
        tl = g_wtl + HWO + (size_t)mat * DW2;
    }
    int tx = threadIdx.x, ty = threadIdx.y;
    for (int r = ty; r < 32; r += 8)
        tile[r][tx] = W[(size_t)(kb + r) * N + nb + tx];
    __syncthreads();
    for (int r = ty; r < 32; r += 8) {
        float v = tile[tx][r];
        __nv_bfloat16 h, l; split2(v, h, l);
        int nrow = nb + r;
        int p = hw ? ((nrow < DD) ? 2 * nrow : 2 * (nrow - DD) + 1) : nrow;
        size_t o = (size_t)p * 512 + kb + tx;
        th[o] = h; tl[o] = l;
    }
}

// QKV packed bias + interleaved highway biases
__global__ void pack_bias(const float* __restrict__ lb, const float* __restrict__ rb,
                          const float* __restrict__ lhb, const float* __restrict__ rhb) {
    int n = blockIdx.x * blockDim.x + threadIdx.x;
    if (n < 6 * DD) {
        int slot = n >> 9, loc = n & 511;
        g_bqkv[n] = (slot < 3) ? lb[slot * DD + loc] : rb[(slot - 3) * DD + loc];
    } else if (n < 6 * DD + 4 * 2 * DD) {
        int j = n - 6 * DD;
        int mat = j >> 10, p = j & 1023;
        int orig = (p & 1) ? DD + (p >> 1) : (p >> 1);
        g_bhw[mat * 2 * DD + p] = (mat < 2) ? lhb[mat * 2 * DD + orig]
                                            : rhb[(mat - 2) * 2 * DD + orig];
    }
}

// ================= elementwise =================
__global__ void build_new_in(const float* __restrict__ x,
                             const float* __restrict__ lp,
                             const float* __restrict__ rp) {
    int idx = blockIdx.x * blockDim.x + threadIdx.x;
    if (idx >= BB * S2S * DD) return;
    int d = idx & (DD - 1);
    int t = idx >> 9;
    int s = t % S2S;
    int b = t / S2S;
    float val;
    if (s < WW)            val = lp[s * DD + d];
    else if (s < WW + SS)  val = x[((size_t)(b * SS + (s - WW))) * DD + d];
    else                   val = rp[(s - WW - SS) * DD + d];
    g_nin[idx] = val;
    __nv_bfloat16 h, l; split2(val, h, l);
    g_ninh[idx] = h; g_ninl[idx] = l;
}

// fused-QKV banded attention; blockIdx.z = dir
__global__ void banded_attn_f(const float* __restrict__ qkv,
                              __nv_bfloat16* __restrict__ o0h, __nv_bfloat16* __restrict__ o0l,
                              __nv_bfloat16* __restrict__ o1h, __nv_bfloat16* __restrict__ o1l) {
    int dir = blockIdx.z;
    __nv_bfloat16* oh = dir ? o1h : o0h;
    __nv_bfloat16* ol = dir ? o1l : o0l;
    int qoff = dir * 3 * DD;
    int gw = (blockIdx.x * blockDim.x + threadIdx.x) >> 5;
    if (gw >= BB * SS * HH) return;
    int lane = threadIdx.x & 31;
    int h = gw & (HH - 1);
    int t = gw >> 3;
    int i = t & (SS - 1);
    int b = t >> 10;
    int qi = i + WW;
    int jlo, jhi;
    if (dir == 0) { jlo = qi - (WW + 1); if (jlo < 0) jlo = 0; jhi = qi; }
    else          { jlo = qi; jhi = qi + (WW + 1); if (jhi > S2S - 1) jhi = S2S - 1; }

    const int LDA = 6 * DD;
    const float* qp = qkv + ((size_t)(b * S2S + qi)) * LDA + qoff + h * DKK;
    float q0 = qp[lane], q1 = qp[lane + 32];

    float sc[WW + 2];
#pragma unroll
    for (int jj = 0; jj < WW + 2; jj++) {
        int j = jlo + jj;
        bool valid = (j <= jhi);
        int jc = valid ? j : jlo;
        const float* kp = qkv + ((size_t)(b * S2S + jc)) * LDA + qoff + DD + h * DKK;
        float s = q0 * kp[lane] + q1 * kp[lane + 32];
#pragma unroll
        for (int o = 16; o; o >>= 1) s += __shfl_xor_sync(0xffffffffu, s, o);
        sc[jj] = valid ? s * 0.125f : -1e30f;
    }
    float m = sc[0];
#pragma unroll
    for (int jj = 1; jj < WW + 2; jj++) m = fmaxf(m, sc[jj]);
    float sum = 0.f;
#pragma unroll
    for (int jj = 0; jj < WW + 2; jj++) { sc[jj] = expf(sc[jj] - m); sum += sc[jj]; }
    float inv = 1.f / sum;
    float o0 = 0.f, o1 = 0.f;
#pragma unroll
    for (int jj = 0; jj < WW + 2; jj++) {
        int j = jlo + jj;
        int jc = (j <= jhi) ? j : jlo;
        const float* vp = qkv + ((size_t)(b * S2S + jc)) * LDA + qoff + 2 * DD + h * DKK;
        o0 += sc[jj] * vp[lane];
        o1 += sc[jj] * vp[lane + 32];
    }
    size_t op = ((size_t)(b * SS + i)) * DD + h * DKK;
    __nv_bfloat16 hh, ll;
    split2(o0 * inv, hh, ll); oh[op + lane] = hh; ol[op + lane] = ll;
    split2(o1 * inv, hh, ll); oh[op + lane + 32] = hh; ol[op + lane + 32] = ll;
}

// ================= fused split-bf16 GEMM with fused epilogues ==============
// mainloop: Ah*Bh + Ah*Bl + Al*Bh; 128x128 tile, BK=32, 3-stage cp.async
// with prefetch distance 2 (one __syncthreads per chunk), swizzled smem
// (64B rows, chunk' = chunk ^ ((row>>1)&3)) -> conflict-free ldmatrix, no pad.
// smem = 3 * 32768 = 96 KB -> 2 CTAs/SM.
#define TILEB  (128 * 64)              // 8192 B per tile (128 rows x 64 B)
#define STG4   (4 * TILEB)             // 32768 B per stage
#define GSMEM3 (3 * STG4)              // 98304 B
#define SWZOFF(row, chunk) ((uint32_t)((row) * 64 + (((chunk) ^ (((row) >> 1) & 3)) << 4)))

struct GArg {
    const __nv_bfloat16 *ah, *al, *bh, *bl;
    const float* bias;
    float* c;
    const float* xin;          // mode 1
    const float* relw;         // mode 2
    __nv_bfloat16 *dh, *dl;    // modes 1,2 (optional in 1)
    int mode, base, lddc;
};

__device__ __forceinline__ void load_stage4(uint32_t sb, int st, const GArg& g,
                                            int row0, int col0, int K, int kb, int tid) {
    uint32_t base = sb + (uint32_t)st * STG4;
#pragma unroll
    for (int t = 0; t < 2; t++) {
        int v = tid + t * 256;
        int r = v >> 2, kc = v & 3;
        uint32_t off = SWZOFF(r, kc);
        size_t ga = (size_t)(row0 + r) * K + kb + kc * 8;
        size_t gb = (size_t)(col0 + r) * K + kb + kc * 8;
        CP_A16(base + off,             g.ah + ga);
        CP_A16(base + TILEB + off,     g.al + ga);
        CP_A16(base + 2 * TILEB + off, g.bh + gb);
        CP_A16(base + 3 * TILEB + off, g.bl + gb);
    }
    CP_COMMIT();
}

__global__ __launch_bounds__(256, 2) void gemm3(
    GArg ga0, GArg ga1, int M, int N, int K)
{
    extern __shared__ char smem[];
    uint32_t sb = smem_u32(smem);
    const GArg g = blockIdx.z ? ga1 : ga0;
    const int tid = threadIdx.x, wid = tid >> 5, lane = tid & 31;
    const int row0 = blockIdx.y * 128, col0 = blockIdx.x * 128;
    const int wm = (wid >> 2) * 64;      // 0 or 64
    const int wn = (wid & 3) * 32;       // 0,32,64,96

    const int NC = K >> 5;               // 16 for K=512

    load_stage4(sb, 0, g, row0, col0, K, 0, tid);
    load_stage4(sb, 1, g, row0, col0, K, 32, tid);

    float d[16][4];
#pragma unroll
    for (int i = 0; i < 16; i++)
#pragma unroll
        for (int j = 0; j < 4; j++) d[i][j] = 0.f;

    int st = 0;
    for (int c = 0; c < NC; c++) {
        if (c + 1 < NC) { CP_WAIT(1); } else { CP_WAIT(0); }
        __syncthreads();
        // prefetch chunk c+2 into stage (st+2)%3 — its last readers finished
        // at iteration c-1, guaranteed by the sync above.
        if (c + 2 < NC) {
            int st2 = st + 2; if (st2 >= 3) st2 -= 3;
            load_stage4(sb, st2, g, row0, col0, K, (c + 2) * 32, tid);
        }
        uint32_t abh = sb + (uint32_t)st * STG4;
        uint32_t abl = abh + TILEB;
        uint32_t bbh = abh + 2 * TILEB;
        uint32_t bbl = abh + 3 * TILEB;
#pragma unroll
        for (int ks = 0; ks < 2; ks++) {
            int kc0 = ks * 2;                 // base 16B-chunk (k0 = ks*16 -> chunk ks*2)
            uint32_t ah[4][4], al[4][4], bh[4][2], bl[4][2];
#pragma unroll
            for (int im = 0; im < 4; im++) {
                int row = wm + im * 16 + (lane & 15);
                uint32_t off = SWZOFF(row, kc0 + (lane >> 4));
                ldsm_x4(ah[im][0], ah[im][1], ah[im][2], ah[im][3], abh + off);
                ldsm_x4(al[im][0], al[im][1], al[im][2], al[im][3], abl + off);
            }
#pragma unroll
            for (int p = 0; p < 2; p++) {
                int m = lane >> 3;
                int row = wn + (2 * p + (m >> 1)) * 8 + (lane & 7);
                uint32_t off = SWZOFF(row, kc0 + (m & 1));
                ldsm_x4(bh[2 * p][0], bh[2 * p][1], bh[2 * p + 1][0], bh[2 * p + 1][1], bbh + off);
                ldsm_x4(bl[2 * p][0], bl[2 * p][1], bl[2 * p + 1][0], bl[2 * p + 1][1], bbl + off);
            }
#pragma unroll
            for (int im = 0; im < 4; im++)
#pragma unroll
                for (int in = 0; in < 4; in++) {
                    float* dd = d[im * 4 + in];
                    mma16816(dd, ah[im], bh[in]);
                    mma16816(dd, ah[im], bl[in]);
                    mma16816(dd, al[im], bh[in]);
                }
        }
        st++; if (st >= 3) st = 0;
    }

    // ================= epilogues =================
    if (g.mode == 0) {
#pragma unroll
        for (int im = 0; im < 4; im++)
#pragma unroll
            for (int in = 0; in < 4; in++) {
                float* dd = d[im * 4 + in];
                int m = row0 + wm + im * 16 + (lane >> 2);
                int n = col0 + wn + in * 8 + ((lane & 3) << 1);
                float b0 = g.bias[n], b1 = g.bias[n + 1];
                *(float2*)&g.c[(size_t)m * N + n] = make_float2(dd[0] + b0, dd[1] + b1);
                *(float2*)&g.c[(size_t)(m + 8) * N + n] = make_float2(dd[2] + b0, dd[3] + b1);
            }
    } else if (g.mode == 2) {
        float w[WW + 1];
#pragma unroll
        for (int j = 0; j <= WW; j++) w[j] = g.relw[j];
#pragma unroll
        for (int im = 0; im < 4; im++)
#pragma unroll
            for (int in = 0; in < 4; in++) {
                float* dd = d[im * 4 + in];
                int m = row0 + wm + im * 16 + (lane >> 2);
                int n = col0 + wn + in * 8 + ((lane & 3) << 1);
                int b = m >> 10, i = m & 1023;
                const float* np = g_nin + ((size_t)(b * S2S + g.base + i)) * DD + n;
                float b0 = g.bias[n], b1 = g.bias[n + 1];
                float y0 = dd[0] + b0, y1 = dd[1] + b1;
                float y2 = dd[2] + b0, y3 = dd[3] + b1;
#pragma unroll
                for (int j = 0; j <= WW; j++) {
                    float2 v = *(const float2*)(np + (size_t)j * DD);
                    float2 v2 = *(const float2*)(np + (size_t)(j + 8) * DD);
                    y0 += w[j] * v.x;  y1 += w[j] * v.y;
                    y2 += w[j] * v2.x; y3 += w[j] * v2.y;
                }
                *(float2*)&g.c[(size_t)m * DD + n] = make_float2(y0, y1);
                *(float2*)&g.c[(size_t)(m + 8) * DD + n] = make_float2(y2, y3);
                __nv_bfloat16 h0, l0, h1, l1;
                split2(y0, h0, l0); split2(y1, h1, l1);
                *(__nv_bfloat162*)&g.dh[(size_t)m * DD + n] = __nv_bfloat162(h0, h1);
                *(__nv_bfloat162*)&g.dl[(size_t)m * DD + n] = __nv_bfloat162(l0, l1);
                split2(y2, h0, l0); split2(y3, h1, l1);
                *(__nv_bfloat162*)&g.dh[(size_t)(m + 8) * DD + n] = __nv_bfloat162(h0, h1);
                *(__nv_bfloat162*)&g.dl[(size_t)(m + 8) * DD + n] = __nv_bfloat162(l0, l1);
            }
    } else {  // mode 1: highway gate
#pragma unroll
        for (int im = 0; im < 4; im++)
#pragma unroll
            for (int in = 0; in < 4; in++) {
                float* dd = d[im * 4 + in];
                int m = row0 + wm + im * 16 + (lane >> 2);
                int n = col0 + wn + in * 8 + ((lane & 3) << 1);
                int u = n >> 1;
                float b0 = g.bias[n], b1 = g.bias[n + 1];
                float nl0 = fmaxf(dd[0] + b0, 0.f);
                float gz0 = dd[1] + b1;
                float nl1 = fmaxf(dd[2] + b0, 0.f);
                float gz1 = dd[3] + b1;
                float x0 = g.xin[(size_t)m * DD + u];
                float x1 = g.xin[(size_t)(m + 8) * DD + u];
                float s0 = 1.f / (1.f + expf(-gz0));
                float s1 = 1.f / (1.f + expf(-gz1));
                float y0 = s0 * x0 + (1.f - s0) * nl0;
                float y1 = s1 * x1 + (1.f - s1) * nl1;
                g.c[(size_t)m * g.lddc + u] = y0;
                g.c[(size_t)(m + 8) * g.lddc + u] = y1;
                if (g.dh) {
                    __nv_bfloat16 h, l;
                    split2(y0, h, l);
                    g.dh[(size_t)m * DD + u] = h; g.dl[(size_t)m * DD + u] = l;
                    split2(y1, h, l);
                    g.dh[(size_t)(m + 8) * DD + u] = h; g.dl[(size_t)(m + 8) * DD + u] = l;
                }
            }
    }
}

// ================= launch =================
extern "C" void kernel_launch(void* const* d_in, const int* in_sizes, int n_in,
                              void* d_out, int out_size)
{
    const float* x    = (const float*)d_in[0];
    const float* lW   = (const float*)d_in[1];
    const float* lb   = (const float*)d_in[2];
    const float* rW   = (const float*)d_in[3];
    const float* rb   = (const float*)d_in[4];
    const float* lpad = (const float*)d_in[5];
    const float* rpad = (const float*)d_in[6];
    const float* lw   = (const float*)d_in[7];
    const float* rw   = (const float*)d_in[8];
    const float* lhW  = (const float*)d_in[9];
    const float* lhb  = (const float*)d_in[10];
    const float* rhW  = (const float*)d_in[11];
    const float* rhb  = (const float*)d_in[12];
    float* out = (float*)d_out;

    cudaFuncSetAttribute(gemm3, cudaFuncAttributeMaxDynamicSharedMemorySize, GSMEM3);

    float *qkv, *bqkv, *bhw, *hx0, *hx1;
    __nv_bfloat16 *ninh, *ninl, *a0h, *a0l, *a1h, *a1l;
    __nv_bfloat16 *hx0h, *hx0l, *hx1h, *hx1l;
    __nv_bfloat16 *hy0h, *hy0l, *hy1h, *hy1l, *wth, *wtl;
    cudaGetSymbolAddress((void**)&qkv, g_qkv);
    cudaGetSymbolAddress((void**)&bqkv, g_bqkv);
    cudaGetSymbolAddress((void**)&bhw, g_bhw);
    cudaGetSymbolAddress((void**)&hx0, g_hx0); cudaGetSymbolAddress((void**)&hx1, g_hx1);
    cudaGetSymbolAddress((void**)&ninh, g_ninh); cudaGetSymbolAddress((void**)&ninl, g_ninl);
    cudaGetSymbolAddress((void**)&a0h, g_a0h); cudaGetSymbolAddress((void**)&a0l, g_a0l);
    cudaGetSymbolAddress((void**)&a1h, g_a1h); cudaGetSymbolAddress((void**)&a1l, g_a1l);
    cudaGetSymbolAddress((void**)&hx0h, g_hx0h); cudaGetSymbolAddress((void**)&hx0l, g_hx0l);
    cudaGetSymbolAddress((void**)&hx1h, g_hx1h); cudaGetSymbolAddress((void**)&hx1l, g_hx1l);
    cudaGetSymbolAddress((void**)&hy0h, g_hy0h); cudaGetSymbolAddress((void**)&hy0l, g_hy0l);
    cudaGetSymbolAddress((void**)&hy1h, g_hy1h); cudaGetSymbolAddress((void**)&hy1l, g_hy1l);
    cudaGetSymbolAddress((void**)&wth, g_wth); cudaGetSymbolAddress((void**)&wtl, g_wtl);

    wsplit_all<<<4096, dim3(32, 8)>>>(lW, rW, lhW, rhW);
    pack_bias<<<28, 256>>>(lb, rb, lhb, rhb);
    build_new_in<<<(BB * S2S * DD + 255) / 256, 256>>>(x, lpad, rpad);

    // fused QKV: M=8320, N=3072, K=512 (mode 0)
    {
        GArg a = {ninh, ninl, wth, wtl, bqkv, qkv,
                  nullptr, nullptr, nullptr, nullptr, 0, 0, 0};
        gemm3<<<dim3(24, 65, 1), 256, GSMEM3>>>(a, a, BB * S2S, 6 * DD, DD);
    }

    // banded attention (both dirs)
    banded_attn_f<<<dim3((BB * SS * HH * 32) / 256, 1, 2), 256>>>(qkv, a0h, a0l, a1h, a1l);

    // output projections + fused rel-add (mode 2)
    {
        GArg p0 = {a0h, a0l, wth + 6 * (size_t)DW, wtl + 6 * (size_t)DW, lb + 3 * DD, hx0,
                   nullptr, lw, hx0h, hx0l, 2, 0, DD};
        GArg p1 = {a1h, a1l, wth + 7 * (size_t)DW, wtl + 7 * (size_t)DW, rb + 3 * DD, hx1,
                   nullptr, rw, hx1h, hx1l, 2, WW, DD};
        gemm3<<<dim3(4, 64, 2), 256, GSMEM3>>>(p0, p1, BB * SS, DD, DD);
    }

    // highway layer 1 (mode 1, gate fused)
    {
        GArg h0 = {hx0h, hx0l, wth + HWO, wtl + HWO, bhw + 0, hx0,
                   hx0, nullptr, hy0h, hy0l, 1, 0, DD};
        GArg h1 = {hx1h, hx1l, wth + HWO + 2 * (size_t)DW2, wtl + HWO + 2 * (size_t)DW2, bhw + 2 * 2 * DD, hx1,
                   hx1, nullptr, hy1h, hy1l, 1, 0, DD};
        gemm3<<<dim3(8, 64, 2), 256, GSMEM3>>>(h0, h1, BB * SS, 2 * DD, DD);
    }
    // highway layer 2 (mode 1) -> strided output
    {
        GArg h0 = {hy0h, hy0l, wth + HWO + (size_t)DW2, wtl + HWO + (size_t)DW2, bhw + 1 * 2 * DD, out + 0,
                   hx0, nullptr, nullptr, nullptr, 1, 0, 2 * DD};
        GArg h1 = {hy1h, hy1l, wth + HWO + 3 * (size_t)DW2, wtl + HWO + 3 * (size_t)DW2, bhw + 3 * 2 * DD, out + DD,
                   hx1, nullptr, nullptr, nullptr, 1, 0, 2 * DD};
        gemm3<<<dim3(8, 64, 2), 256, GSMEM3>>>(h0, h1, BB * SS, 2 * DD, DD);
    }
}

// round 11
// speedup vs baseline: 2.7577x; 1.0765x over previous
#include <cuda_runtime.h>
#include <cuda_bf16.h>
#include <math.h>
#include <stdint.h>

#define BB   8
#define SS   1024
#define DD   512
#define HH   8
#define WW   8
#define S2S  1040
#define DKK  64

// ================= helpers =================
__device__ __forceinline__ uint32_t smem_u32(const void* p) {
    uint32_t a;
    asm("{ .reg .u64 t; cvta.to.shared.u64 t, %1; cvt.u32.u64 %0, t; }" : "=r"(a) : "l"(p));
    return a;
}
#define CP_A16(dst, src) \
    asm volatile("cp.async.cg.shared.global [%0], [%1], 16;" :: "r"((uint32_t)(dst)), "l"(src))
#define CP_COMMIT() asm volatile("cp.async.commit_group;" ::: "memory")
#define CP_WAIT(n)  asm volatile("cp.async.wait_group %0;" :: "n"(n) : "memory")

__device__ __forceinline__ void ldsm_x4(uint32_t& r0, uint32_t& r1, uint32_t& r2, uint32_t& r3, uint32_t addr) {
    asm volatile("ldmatrix.sync.aligned.m8n8.x4.shared.b16 {%0,%1,%2,%3}, [%4];"
                 : "=r"(r0), "=r"(r1), "=r"(r2), "=r"(r3) : "r"(addr));
}
__device__ __forceinline__ void mma16816(float* d, const uint32_t* a, const uint32_t* b) {
    asm volatile("mma.sync.aligned.m16n8k16.row.col.f32.bf16.bf16.f32 "
                 "{%0,%1,%2,%3}, {%4,%5,%6,%7}, {%8,%9}, {%0,%1,%2,%3};"
                 : "+f"(d[0]), "+f"(d[1]), "+f"(d[2]), "+f"(d[3])
                 : "r"(a[0]), "r"(a[1]), "r"(a[2]), "r"(a[3]), "r"(b[0]), "r"(b[1]));
}
__device__ __forceinline__ void split2(float x, __nv_bfloat16& h, __nv_bfloat16& l) {
    h = __float2bfloat16(x);
    l = __float2bfloat16(x - __bfloat162float(h));
}

// ================= scratch (device globals) =================
#define DW   (DD * DD)
#define DW2  (DD * 2 * DD)
#define HWO  (8 * DW)
__device__ float g_nin[BB * S2S * DD];
__device__ __nv_bfloat16 g_ninh[BB * S2S * DD];
__device__ __nv_bfloat16 g_ninl[BB * S2S * DD];
__device__ float g_qkv[BB * S2S * 6 * DD];                // fused QKV output (lda=3072)
__device__ float g_bqkv[6 * DD];
__device__ float g_bhw[4 * 2 * DD];                       // interleaved hw biases
__device__ __nv_bfloat16 g_a0h[BB * SS * DD], g_a0l[BB * SS * DD];
__device__ __nv_bfloat16 g_a1h[BB * SS * DD], g_a1l[BB * SS * DD];
__device__ float g_hx0[BB * SS * DD], g_hx1[BB * SS * DD];
__device__ __nv_bfloat16 g_hx0h[BB * SS * DD], g_hx0l[BB * SS * DD];
__device__ __nv_bfloat16 g_hx1h[BB * SS * DD], g_hx1l[BB * SS * DD];
__device__ __nv_bfloat16 g_hy0h[BB * SS * DD], g_hy0l[BB * SS * DD];
__device__ __nv_bfloat16 g_hy1h[BB * SS * DD], g_hy1l[BB * SS * DD];
__device__ __nv_bfloat16 g_wth[8 * DW + 4 * DW2];
__device__ __nv_bfloat16 g_wtl[8 * DW + 4 * DW2];

// ================= weight transpose+split, one launch ======================
__global__ void wsplit_all(const float* __restrict__ lW, const float* __restrict__ rW,
                           const float* __restrict__ lhW, const float* __restrict__ rhW) {
    __shared__ float tile[32][33];
    int blk = blockIdx.x;
    const float* W;
    __nv_bfloat16 *th, *tl;
    int nb, kb, N;
    bool hw = false;
    if (blk < 2048) {
        int mat = blk >> 8;          // 0..7
        int t = blk & 255;
        N = 512;
        nb = (t & 15) * 32; kb = (t >> 4) * 32;
        int slot;
        if (mat < 4) { W = lW + (size_t)mat * DW; slot = (mat < 3) ? mat : 6; }
        else         { int i = mat - 4; W = rW + (size_t)i * DW; slot = (i < 3) ? 3 + i : 7; }
        th = g_wth + (size_t)slot * DW;
        tl = g_wtl + (size_t)slot * DW;
    } else {
        hw = true;
        int bb = blk - 2048;
        int mat = bb >> 9;           // 0..3  (lh0, lh1, rh0, rh1)
        int t = bb & 511;
        N = 1024;
        nb = (t & 31) * 32; kb = (t >> 5) * 32;
        W = (mat < 2) ? lhW + (size_t)mat * DW2 : rhW + (size_t)(mat - 2) * DW2;
        th = g_wth + HWO + (size_t)mat * DW2;
        tl = g_wtl + HWO + (size_t)mat * DW2;
    }
    int tx = threadIdx.x, ty = threadIdx.y;
    for (int r = ty; r < 32; r += 8)
        tile[r][tx] = W[(size_t)(kb + r) * N + nb + tx];
    __syncthreads();
    for (int r = ty; r < 32; r += 8) {
        float v = tile[tx][r];
        __nv_bfloat16 h, l; split2(v, h, l);
        int nrow = nb + r;
        int p = hw ? ((nrow < DD) ? 2 * nrow : 2 * (nrow - DD) + 1) : nrow;
        size_t o = (size_t)p * 512 + kb + tx;
        th[o] = h; tl[o] = l;
    }
}

// QKV packed bias + interleaved highway biases
__global__ void pack_bias(const float* __restrict__ lb, const float* __restrict__ rb,
                          const float* __restrict__ lhb, const float* __restrict__ rhb) {
    int n = blockIdx.x * blockDim.x + threadIdx.x;
    if (n < 6 * DD) {
        int slot = n >> 9, loc = n & 511;
        g_bqkv[n] = (slot < 3) ? lb[slot * DD + loc] : rb[(slot - 3) * DD + loc];
    } else if (n < 6 * DD + 4 * 2 * DD) {
        int j = n - 6 * DD;
        int mat = j >> 10, p = j & 1023;
        int orig = (p & 1) ? DD + (p >> 1) : (p >> 1);
        g_bhw[mat * 2 * DD + p] = (mat < 2) ? lhb[mat * 2 * DD + orig]
                                            : rhb[(mat - 2) * 2 * DD + orig];
    }
}

// ================= elementwise =================
__global__ void build_new_in(const float* __restrict__ x,
                             const float* __restrict__ lp,
                             const float* __restrict__ rp) {
    int idx = blockIdx.x * blockDim.x + threadIdx.x;
    if (idx >= BB * S2S * DD) return;
    int d = idx & (DD - 1);
    int t = idx >> 9;
    int s = t % S2S;
    int b = t / S2S;
    float val;
    if (s < WW)            val = lp[s * DD + d];
    else if (s < WW + SS)  val = x[((size_t)(b * SS + (s - WW))) * DD + d];
    else                   val = rp[(s - WW - SS) * DD + d];
    g_nin[idx] = val;
    __nv_bfloat16 h, l; split2(val, h, l);
    g_ninh[idx] = h; g_ninl[idx] = l;
}

// fused-QKV banded attention; blockIdx.z = dir.
// warp->work mapping is i-fastest so the 8 warps of a block cover 8
// consecutive i of one (b,h): their 10-key windows overlap 9/10 -> L1 reuse.
__global__ void banded_attn_f(const float* __restrict__ qkv,
                              __nv_bfloat16* __restrict__ o0h, __nv_bfloat16* __restrict__ o0l,
                              __nv_bfloat16* __restrict__ o1h, __nv_bfloat16* __restrict__ o1l) {
    int dir = blockIdx.z;
    __nv_bfloat16* oh = dir ? o1h : o0h;
    __nv_bfloat16* ol = dir ? o1l : o0l;
    int qoff = dir * 3 * DD;
    int gw = (blockIdx.x * blockDim.x + threadIdx.x) >> 5;
    if (gw >= BB * SS * HH) return;
    int lane = threadIdx.x & 31;
    int i = gw & (SS - 1);
    int h = (gw >> 10) & (HH - 1);
    int b = gw >> 13;
    int qi = i + WW;
    int jlo, jhi;
    if (dir == 0) { jlo = qi - (WW + 1); if (jlo < 0) jlo = 0; jhi = qi; }
    else          { jlo = qi; jhi = qi + (WW + 1); if (jhi > S2S - 1) jhi = S2S - 1; }

    const int LDA = 6 * DD;
    const float* qp = qkv + ((size_t)(b * S2S + qi)) * LDA + qoff + h * DKK;
    float q0 = qp[lane], q1 = qp[lane + 32];

    float sc[WW + 2];
#pragma unroll
    for (int jj = 0; jj < WW + 2; jj++) {
        int j = jlo + jj;
        bool valid = (j <= jhi);
        int jc = valid ? j : jlo;
        const float* kp = qkv + ((size_t)(b * S2S + jc)) * LDA + qoff + DD + h * DKK;
        float s = q0 * kp[lane] + q1 * kp[lane + 32];
#pragma unroll
        for (int o = 16; o; o >>= 1) s += __shfl_xor_sync(0xffffffffu, s, o);
        sc[jj] = valid ? s * 0.125f : -1e30f;
    }
    float m = sc[0];
#pragma unroll
    for (int jj = 1; jj < WW + 2; jj++) m = fmaxf(m, sc[jj]);
    float sum = 0.f;
#pragma unroll
    for (int jj = 0; jj < WW + 2; jj++) { sc[jj] = expf(sc[jj] - m); sum += sc[jj]; }
    float inv = 1.f / sum;
    float o0 = 0.f, o1 = 0.f;
#pragma unroll
    for (int jj = 0; jj < WW + 2; jj++) {
        int j = jlo + jj;
        int jc = (j <= jhi) ? j : jlo;
        const float* vp = qkv + ((size_t)(b * S2S + jc)) * LDA + qoff + 2 * DD + h * DKK;
        o0 += sc[jj] * vp[lane];
        o1 += sc[jj] * vp[lane + 32];
    }
    size_t op = ((size_t)(b * SS + i)) * DD + h * DKK;
    __nv_bfloat16 hh, ll;
    split2(o0 * inv, hh, ll); oh[op + lane] = hh; ol[op + lane] = ll;
    split2(o1 * inv, hh, ll); oh[op + lane + 32] = hh; ol[op + lane + 32] = ll;
}

// ================= fused split-bf16 GEMM with fused epilogues ==============
// mainloop: Ah*Bh + Ah*Bl + Al*Bh; 128x128 tile, BK=32, 3-stage cp.async
// with prefetch distance 2, swizzled smem (64B rows, chunk' = chunk ^
// ((row>>1)&3)). All smem offsets + global load indices hoisted out of the
// mainloop (ks=1 ldsm offset = ks=0 offset ^ 32). 96KB smem -> 2 CTAs/SM.
#define TILEB  (128 * 64)              // 8192 B per tile (128 rows x 64 B)
#define STG4   (4 * TILEB)             // 32768 B per stage
#define GSMEM3 (3 * STG4)              // 98304 B
#define SWZOFF(row, chunk) ((uint32_t)((row) * 64 + (((chunk) ^ (((row) >> 1) & 3)) << 4)))

struct GArg {
    const __nv_bfloat16 *ah, *al, *bh, *bl;
    const float* bias;
    float* c;
    const float* xin;          // mode 1
    const float* relw;         // mode 2
    __nv_bfloat16 *dh, *dl;    // modes 1,2 (optional in 1)
    int mode, base, lddc;
};

__global__ __launch_bounds__(256, 2) void gemm3(
    GArg ga0, GArg ga1, int M, int N, int K)
{
    extern __shared__ char smem[];
    uint32_t sb = smem_u32(smem);
    const GArg g = blockIdx.z ? ga1 : ga0;
    const int tid = threadIdx.x, wid = tid >> 5, lane = tid & 31;
    const int row0 = blockIdx.y * 128, col0 = blockIdx.x * 128;
    const int wm = (wid >> 2) * 64;      // 0 or 64
    const int wn = (wid & 3) * 32;       // 0,32,64,96

    const int NC = K >> 5;               // 16 for K=512

    // ---- load-side precompute (affine in kb) ----
    const int lr = tid >> 2, lkc = tid & 3;
    const uint32_t s0 = SWZOFF(lr, lkc);
    const uint32_t s1 = SWZOFF(lr + 64, lkc);
    const uint32_t aIdx0 = (uint32_t)(row0 + lr) * (uint32_t)K + lkc * 8;
    const uint32_t aIdx1 = aIdx0 + (uint32_t)(64 * K);
    const uint32_t bIdx0 = (uint32_t)(col0 + lr) * (uint32_t)K + lkc * 8;
    const uint32_t bIdx1 = bIdx0 + (uint32_t)(64 * K);

    // ---- compute-side ldsm offsets (loop-invariant; ks=1 -> ^32) ----
    uint32_t offA[4], offB[2];
#pragma unroll
    for (int im = 0; im < 4; im++) {
        int row = wm + im * 16 + (lane & 15);
        offA[im] = SWZOFF(row, (lane >> 4));
    }
    {
        int m = lane >> 3;
#pragma unroll
        for (int p = 0; p < 2; p++) {
            int row = wn + (2 * p + (m >> 1)) * 8 + (lane & 7);
            offB[p] = SWZOFF(row, (m & 1));
        }
    }

#define LOAD_STAGE(st, kb) do {                                        \
        uint32_t _b = sb + (uint32_t)(st) * STG4;                      \
        uint32_t _k = (uint32_t)(kb);                                  \
        CP_A16(_b + s0,             g.ah + aIdx0 + _k);                \
        CP_A16(_b + s1,             g.ah + aIdx1 + _k);                \
        CP_A16(_b + TILEB + s0,     g.al + aIdx0 + _k);                \
        CP_A16(_b + TILEB + s1,     g.al + aIdx1 + _k);                \
        CP_A16(_b + 2 * TILEB + s0, g.bh + bIdx0 + _k);                \
        CP_A16(_b + 2 * TILEB + s1, g.bh + bIdx1 + _k);                \
        CP_A16(_b + 3 * TILEB + s0, g.bl + bIdx0 + _k);                \
        CP_A16(_b + 3 * TILEB + s1, g.bl + bIdx1 + _k);                \
        CP_COMMIT();                                                   \
    } while (0)

    LOAD_STAGE(0, 0);
    LOAD_STAGE(1, 32);

    float d[16][4];
#pragma unroll
    for (int i = 0; i < 16; i++)
#pragma unroll
        for (int j = 0; j < 4; j++) d[i][j] = 0.f;

    int st = 0;
    for (int c = 0; c < NC; c++) {
        if (c + 1 < NC) { CP_WAIT(1); } else { CP_WAIT(0); }
        __syncthreads();
        if (c + 2 < NC) {
            int st2 = st + 2; if (st2 >= 3) st2 -= 3;
            LOAD_STAGE(st2, (c + 2) * 32);
        } else {
            CP_COMMIT();
        }
        uint32_t abh = sb + (uint32_t)st * STG4;
        uint32_t abl = abh + TILEB;
        uint32_t bbh = abh + 2 * TILEB;
        uint32_t bbl = abh + 3 * TILEB;
#pragma unroll
        for (int ks = 0; ks < 2; ks++) {
            const uint32_t kx = (uint32_t)(ks << 5);
            uint32_t ah[4][4], al[4][4], bh[4][2], bl[4][2];
#pragma unroll
            for (int im = 0; im < 4; im++) {
                uint32_t off = offA[im] ^ kx;
                ldsm_x4(ah[im][0], ah[im][1], ah[im][2], ah[im][3], abh + off);
                ldsm_x4(al[im][0], al[im][1], al[im][2], al[im][3], abl + off);
            }
#pragma unroll
            for (int p = 0; p < 2; p++) {
                uint32_t off = offB[p] ^ kx;
                ldsm_x4(bh[2 * p][0], bh[2 * p][1], bh[2 * p + 1][0], bh[2 * p + 1][1], bbh + off);
                ldsm_x4(bl[2 * p][0], bl[2 * p][1], bl[2 * p + 1][0], bl[2 * p + 1][1], bbl + off);
            }
#pragma unroll
            for (int im = 0; im < 4; im++)
#pragma unroll
                for (int in = 0; in < 4; in++) {
                    float* dd = d[im * 4 + in];
                    mma16816(dd, ah[im], bh[in]);
                    mma16816(dd, ah[im], bl[in]);
                    mma16816(dd, al[im], bh[in]);
                }
        }
        st++; if (st >= 3) st = 0;
    }
#undef LOAD_STAGE

    // ================= epilogues =================
    if (g.mode == 0) {
#pragma unroll
        for (int im = 0; im < 4; im++)
#pragma unroll
            for (int in = 0; in < 4; in++) {
                float* dd = d[im * 4 + in];
                int m = row0 + wm + im * 16 + (lane >> 2);
                int n = col0 + wn + in * 8 + ((lane & 3) << 1);
                float b0 = g.bias[n], b1 = g.bias[n + 1];
                *(float2*)&g.c[(size_t)m * N + n] = make_float2(dd[0] + b0, dd[1] + b1);
                *(float2*)&g.c[(size_t)(m + 8) * N + n] = make_float2(dd[2] + b0, dd[3] + b1);
            }
    } else if (g.mode == 2) {
        float w[WW + 1];
#pragma unroll
        for (int j = 0; j <= WW; j++) w[j] = g.relw[j];
#pragma unroll
        for (int im = 0; im < 4; im++)
#pragma unroll
            for (int in = 0; in < 4; in++) {
                float* dd = d[im * 4 + in];
                int m = row0 + wm + im * 16 + (lane >> 2);
                int n = col0 + wn + in * 8 + ((lane & 3) << 1);
                int b = m >> 10, i = m & 1023;
                const float* np = g_nin + ((size_t)(b * S2S + g.base + i)) * DD + n;
                float b0 = g.bias[n], b1 = g.bias[n + 1];
                float y0 = dd[0] + b0, y1 = dd[1] + b1;
                float y2 = dd[2] + b0, y3 = dd[3] + b1;
#pragma unroll
                for (int j = 0; j <= WW; j++) {
                    float2 v = *(const float2*)(np + (size_t)j * DD);
                    float2 v2 = *(const float2*)(np + (size_t)(j + 8) * DD);
                    y0 += w[j] * v.x;  y1 += w[j] * v.y;
                    y2 += w[j] * v2.x; y3 += w[j] * v2.y;
                }
                *(float2*)&g.c[(size_t)m * DD + n] = make_float2(y0, y1);
                *(float2*)&g.c[(size_t)(m + 8) * DD + n] = make_float2(y2, y3);
                __nv_bfloat16 h0, l0, h1, l1;
                split2(y0, h0, l0); split2(y1, h1, l1);
                *(__nv_bfloat162*)&g.dh[(size_t)m * DD + n] = __nv_bfloat162(h0, h1);
                *(__nv_bfloat162*)&g.dl[(size_t)m * DD + n] = __nv_bfloat162(l0, l1);
                split2(y2, h0, l0); split2(y3, h1, l1);
                *(__nv_bfloat162*)&g.dh[(size_t)(m + 8) * DD + n] = __nv_bfloat162(h0, h1);
                *(__nv_bfloat162*)&g.dl[(size_t)(m + 8) * DD + n] = __nv_bfloat162(l0, l1);
            }
    } else {  // mode 1: highway gate
#pragma unroll
        for (int im = 0; im < 4; im++)
#pragma unroll
            for (int in = 0; in < 4; in++) {
                float* dd = d[im * 4 + in];
                int m = row0 + wm + im * 16 + (lane >> 2);
                int n = col0 + wn + in * 8 + ((lane & 3) << 1);
                int u = n >> 1;
                float b0 = g.bias[n], b1 = g.bias[n + 1];
                float nl0 = fmaxf(dd[0] + b0, 0.f);
                float gz0 = dd[1] + b1;
                float nl1 = fmaxf(dd[2] + b0, 0.f);
                float gz1 = dd[3] + b1;
                float x0 = g.xin[(size_t)m * DD + u];
                float x1 = g.xin[(size_t)(m + 8) * DD + u];
                float s0g = 1.f / (1.f + expf(-gz0));
                float s1g = 1.f / (1.f + expf(-gz1));
                float y0 = s0g * x0 + (1.f - s0g) * nl0;
                float y1 = s1g * x1 + (1.f - s1g) * nl1;
                g.c[(size_t)m * g.lddc + u] = y0;
                g.c[(size_t)(m + 8) * g.lddc + u] = y1;
                if (g.dh) {
                    __nv_bfloat16 h, l;
                    split2(y0, h, l);
                    g.dh[(size_t)m * DD + u] = h; g.dl[(size_t)m * DD + u] = l;
                    split2(y1, h, l);
                    g.dh[(size_t)(m + 8) * DD + u] = h; g.dl[(size_t)(m + 8) * DD + u] = l;
                }
            }
    }
}

// ================= launch =================
extern "C" void kernel_launch(void* const* d_in, const int* in_sizes, int n_in,
                              void* d_out, int out_size)
{
    const float* x    = (const float*)d_in[0];
    const float* lW   = (const float*)d_in[1];
    const float* lb   = (const float*)d_in[2];
    const float* rW   = (const float*)d_in[3];
    const float* rb   = (const float*)d_in[4];
    const float* lpad = (const float*)d_in[5];
    const float* rpad = (const float*)d_in[6];
    const float* lw   = (const float*)d_in[7];
    const float* rw   = (const float*)d_in[8];
    const float* lhW  = (const float*)d_in[9];
    const float* lhb  = (const float*)d_in[10];
    const float* rhW  = (const float*)d_in[11];
    const float* rhb  = (const float*)d_in[12];
    float* out = (float*)d_out;

    cudaFuncSetAttribute(gemm3, cudaFuncAttributeMaxDynamicSharedMemorySize, GSMEM3);

    float *qkv, *bqkv, *bhw, *hx0, *hx1;
    __nv_bfloat16 *ninh, *ninl, *a0h, *a0l, *a1h, *a1l;
    __nv_bfloat16 *hx0h, *hx0l, *hx1h, *hx1l;
    __nv_bfloat16 *hy0h, *hy0l, *hy1h, *hy1l, *wth, *wtl;
    cudaGetSymbolAddress((void**)&qkv, g_qkv);
    cudaGetSymbolAddress((void**)&bqkv, g_bqkv);
    cudaGetSymbolAddress((void**)&bhw, g_bhw);
    cudaGetSymbolAddress((void**)&hx0, g_hx0); cudaGetSymbolAddress((void**)&hx1, g_hx1);
    cudaGetSymbolAddress((void**)&ninh, g_ninh); cudaGetSymbolAddress((void**)&ninl, g_ninl);
    cudaGetSymbolAddress((void**)&a0h, g_a0h); cudaGetSymbolAddress((void**)&a0l, g_a0l);
    cudaGetSymbolAddress((void**)&a1h, g_a1h); cudaGetSymbolAddress((void**)&a1l, g_a1l);
    cudaGetSymbolAddress((void**)&hx0h, g_hx0h); cudaGetSymbolAddress((void**)&hx0l, g_hx0l);
    cudaGetSymbolAddress((void**)&hx1h, g_hx1h); cudaGetSymbolAddress((void**)&hx1l, g_hx1l);
    cudaGetSymbolAddress((void**)&hy0h, g_hy0h); cudaGetSymbolAddress((void**)&hy0l, g_hy0l);
    cudaGetSymbolAddress((void**)&hy1h, g_hy1h); cudaGetSymbolAddress((void**)&hy1l, g_hy1l);
    cudaGetSymbolAddress((void**)&wth, g_wth); cudaGetSymbolAddress((void**)&wtl, g_wtl);

    wsplit_all<<<4096, dim3(32, 8)>>>(lW, rW, lhW, rhW);
    pack_bias<<<28, 256>>>(lb, rb, lhb, rhb);
    build_new_in<<<(BB * S2S * DD + 255) / 256, 256>>>(x, lpad, rpad);

    // fused QKV: M=8320, N=3072, K=512 (mode 0)
    {
        GArg a = {ninh, ninl, wth, wtl, bqkv, qkv,
                  nullptr, nullptr, nullptr, nullptr, 0, 0, 0};
        gemm3<<<dim3(24, 65, 1), 256, GSMEM3>>>(a, a, BB * S2S, 6 * DD, DD);
    }

    // banded attention (both dirs)
    banded_attn_f<<<dim3((BB * SS * HH * 32) / 256, 1, 2), 256>>>(qkv, a0h, a0l, a1h, a1l);

    // output projections + fused rel-add (mode 2)
    {
        GArg p0 = {a0h, a0l, wth + 6 * (size_t)DW, wtl + 6 * (size_t)DW, lb + 3 * DD, hx0,
                   nullptr, lw, hx0h, hx0l, 2, 0, DD};
        GArg p1 = {a1h, a1l, wth + 7 * (size_t)DW, wtl + 7 * (size_t)DW, rb + 3 * DD, hx1,
                   nullptr, rw, hx1h, hx1l, 2, WW, DD};
        gemm3<<<dim3(4, 64, 2), 256, GSMEM3>>>(p0, p1, BB * SS, DD, DD);
    }

    // highway layer 1 (mode 1, gate fused)
    {
        GArg h0 = {hx0h, hx0l, wth + HWO, wtl + HWO, bhw + 0, hx0,
                   hx0, nullptr, hy0h, hy0l, 1, 0, DD};
        GArg h1 = {hx1h, hx1l, wth + HWO + 2 * (size_t)DW2, wtl + HWO + 2 * (size_t)DW2, bhw + 2 * 2 * DD, hx1,
                   hx1, nullptr, hy1h, hy1l, 1, 0, DD};
        gemm3<<<dim3(8, 64, 2), 256, GSMEM3>>>(h0, h1, BB * SS, 2 * DD, DD);
    }
    // highway layer 2 (mode 1) -> strided output
    {
        GArg h0 = {hy0h, hy0l, wth + HWO + (size_t)DW2, wtl + HWO + (size_t)DW2, bhw + 1 * 2 * DD, out + 0,
                   hx0, nullptr, nullptr, nullptr, 1, 0, 2 * DD};
        GArg h1 = {hy1h, hy1l, wth + HWO + 3 * (size_t)DW2, wtl + HWO + 3 * (size_t)DW2, bhw + 3 * 2 * DD, out + DD,
                   hx1, nullptr, nullptr, nullptr, 1, 0, 2 * DD};
        gemm3<<<dim3(8, 64, 2), 256, GSMEM3>>>(h0, h1, BB * SS, 2 * DD, DD);
    }
}

// round 14
// speedup vs baseline: 2.8227x; 1.0236x over previous
#include <cuda_runtime.h>
#include <cuda_bf16.h>
#include <math.h>
#include <stdint.h>

#define BB   8
#define SS   1024
#define DD   512
#define HH   8
#define WW   8
#define S2S  1040
#define DKK  64

// ================= helpers =================
__device__ __forceinline__ uint32_t smem_u32(const void* p) {
    uint32_t a;
    asm("{ .reg .u64 t; cvta.to.shared.u64 t, %1; cvt.u32.u64 %0, t; }" : "=r"(a) : "l"(p));
    return a;
}
#define CP_A16(dst, src) \
    asm volatile("cp.async.cg.shared.global [%0], [%1], 16;" :: "r"((uint32_t)(dst)), "l"(src))
#define CP_COMMIT() asm volatile("cp.async.commit_group;" ::: "memory")
#define CP_WAIT(n)  asm volatile("cp.async.wait_group %0;" :: "n"(n) : "memory")

__device__ __forceinline__ void ldsm_x4(uint32_t& r0, uint32_t& r1, uint32_t& r2, uint32_t& r3, uint32_t addr) {
    asm volatile("ldmatrix.sync.aligned.m8n8.x4.shared.b16 {%0,%1,%2,%3}, [%4];"
                 : "=r"(r0), "=r"(r1), "=r"(r2), "=r"(r3) : "r"(addr));
}
__device__ __forceinline__ void mma16816(float* d, const uint32_t* a, const uint32_t* b) {
    asm volatile("mma.sync.aligned.m16n8k16.row.col.f32.bf16.bf16.f32 "
                 "{%0,%1,%2,%3}, {%4,%5,%6,%7}, {%8,%9}, {%0,%1,%2,%3};"
                 : "+f"(d[0]), "+f"(d[1]), "+f"(d[2]), "+f"(d[3])
                 : "r"(a[0]), "r"(a[1]), "r"(a[2]), "r"(a[3]), "r"(b[0]), "r"(b[1]));
}
__device__ __forceinline__ void split2(float x, __nv_bfloat16& h, __nv_bfloat16& l) {
    h = __float2bfloat16(x);
    l = __float2bfloat16(x - __bfloat162float(h));
}

// ================= scratch (device globals) =================
#define DW   (DD * DD)
#define DW2  (DD * 2 * DD)
#define HWO  (8 * DW)
__device__ float g_nin[BB * S2S * DD];
__device__ __nv_bfloat16 g_ninh[BB * S2S * DD];
__device__ __nv_bfloat16 g_ninl[BB * S2S * DD];
__device__ float g_qkv[BB * S2S * 6 * DD];                // fused QKV output (lda=3072)
__device__ float g_bqkv[6 * DD];
__device__ float g_bhw[4 * 2 * DD];                       // interleaved hw biases
__device__ __nv_bfloat16 g_a0h[BB * SS * DD], g_a0l[BB * SS * DD];
__device__ __nv_bfloat16 g_a1h[BB * SS * DD], g_a1l[BB * SS * DD];
__device__ float g_hx0[BB * SS * DD], g_hx1[BB * SS * DD];
__device__ __nv_bfloat16 g_hx0h[BB * SS * DD], g_hx0l[BB * SS * DD];
__device__ __nv_bfloat16 g_hx1h[BB * SS * DD], g_hx1l[BB * SS * DD];
__device__ __nv_bfloat16 g_hy0h[BB * SS * DD], g_hy0l[BB * SS * DD];
__device__ __nv_bfloat16 g_hy1h[BB * SS * DD], g_hy1l[BB * SS * DD];
__device__ __nv_bfloat16 g_wth[8 * DW + 4 * DW2];
__device__ __nv_bfloat16 g_wtl[8 * DW + 4 * DW2];

// ================= weight transpose+split, one launch ======================
__global__ void wsplit_all(const float* __restrict__ lW, const float* __restrict__ rW,
                           const float* __restrict__ lhW, const float* __restrict__ rhW) {
    __shared__ float tile[32][33];
    int blk = blockIdx.x;
    const float* W;
    __nv_bfloat16 *th, *tl;
    int nb, kb, N;
    bool hw = false;
    if (blk < 2048) {
        int mat = blk >> 8;          // 0..7
        int t = blk & 255;
        N = 512;
        nb = (t & 15) * 32; kb = (t >> 4) * 32;
        int slot;
        if (mat < 4) { W = lW + (size_t)mat * DW; slot = (mat < 3) ? mat : 6; }
        else         { int i = mat - 4; W = rW + (size_t)i * DW; slot = (i < 3) ? 3 + i : 7; }
        th = g_wth + (size_t)slot * DW;
        tl = g_wtl + (size_t)slot * DW;
    } else {
        hw = true;
        int bb = blk - 2048;
        int mat = bb >> 9;           // 0..3  (lh0, lh1, rh0, rh1)
        int t = bb & 511;
        N = 1024;
        nb = (t & 31) * 32; kb = (t >> 5) * 32;
        W = (mat < 2) ? lhW + (size_t)mat * DW2 : rhW + (size_t)(mat - 2) * DW2;
        th = g_wth + HWO + (size_t)mat * DW2;
        tl = g_wtl + HWO + (size_t)mat * DW2;
    }
    int tx = threadIdx.x, ty = threadIdx.y;
    for (int r = ty; r < 32; r += 8)
        tile[r][tx] = W[(size_t)(kb + r) * N + nb + tx];
    __syncthreads();
    for (int r = ty; r < 32; r += 8) {
        float v = tile[tx][r];
        __nv_bfloat16 h, l; split2(v, h, l);
        int nrow = nb + r;
        int p = hw ? ((nrow < DD) ? 2 * nrow : 2 * (nrow - DD) + 1) : nrow;
        size_t o = (size_t)p * 512 + kb + tx;
        th[o] = h; tl[o] = l;
    }
}

// QKV packed bias + interleaved highway biases
__global__ void pack_bias(const float* __restrict__ lb, const float* __restrict__ rb,
                          const float* __restrict__ lhb, const float* __restrict__ rhb) {
    int n = blockIdx.x * blockDim.x + threadIdx.x;
    if (n < 6 * DD) {
        int slot = n >> 9, loc = n & 511;
        g_bqkv[n] = (slot < 3) ? lb[slot * DD + loc] : rb[(slot - 3) * DD + loc];
    } else if (n < 6 * DD + 4 * 2 * DD) {
        int j = n - 6 * DD;
        int mat = j >> 10, p = j & 1023;
        int orig = (p & 1) ? DD + (p >> 1) : (p >> 1);
        g_bhw[mat * 2 * DD + p] = (mat < 2) ? lhb[mat * 2 * DD + orig]
                                            : rhb[(mat - 2) * 2 * DD + orig];
    }
}

// ================= elementwise =================
__global__ void build_new_in(const float* __restrict__ x,
                             const float* __restrict__ lp,
                             const float* __restrict__ rp) {
    int idx = blockIdx.x * blockDim.x + threadIdx.x;
    if (idx >= BB * S2S * DD) return;
    int d = idx & (DD - 1);
    int t = idx >> 9;
    int s = t % S2S;
    int b = t / S2S;
    float val;
    if (s < WW)            val = lp[s * DD + d];
    else if (s < WW + SS)  val = x[((size_t)(b * SS + (s - WW))) * DD + d];
    else                   val = rp[(s - WW - SS) * DD + d];
    g_nin[idx] = val;
    __nv_bfloat16 h, l; split2(val, h, l);
    g_ninh[idx] = h; g_ninl[idx] = l;
}

// fused-QKV banded attention; blockIdx.z = dir. i-fastest warp mapping.
__global__ void banded_attn_f(const float* __restrict__ qkv,
                              __nv_bfloat16* __restrict__ o0h, __nv_bfloat16* __restrict__ o0l,
                              __nv_bfloat16* __restrict__ o1h, __nv_bfloat16* __restrict__ o1l) {
    int dir = blockIdx.z;
    __nv_bfloat16* oh = dir ? o1h : o0h;
    __nv_bfloat16* ol = dir ? o1l : o0l;
    int qoff = dir * 3 * DD;
    int gw = (blockIdx.x * blockDim.x + threadIdx.x) >> 5;
    if (gw >= BB * SS * HH) return;
    int lane = threadIdx.x & 31;
    int i = gw & (SS - 1);
    int h = (gw >> 10) & (HH - 1);
    int b = gw >> 13;
    int qi = i + WW;
    int jlo, jhi;
    if (dir == 0) { jlo = qi - (WW + 1); if (jlo < 0) jlo = 0; jhi = qi; }
    else          { jlo = qi; jhi = qi + (WW + 1); if (jhi > S2S - 1) jhi = S2S - 1; }

    const int LDA = 6 * DD;
    const float* qp = qkv + ((size_t)(b * S2S + qi)) * LDA + qoff + h * DKK;
    float q0 = qp[lane], q1 = qp[lane + 32];

    float sc[WW + 2];
#pragma unroll
    for (int jj = 0; jj < WW + 2; jj++) {
        int j = jlo + jj;
        bool valid = (j <= jhi);
        int jc = valid ? j : jlo;
        const float* kp = qkv + ((size_t)(b * S2S + jc)) * LDA + qoff + DD + h * DKK;
        float s = q0 * kp[lane] + q1 * kp[lane + 32];
#pragma unroll
        for (int o = 16; o; o >>= 1) s += __shfl_xor_sync(0xffffffffu, s, o);
        sc[jj] = valid ? s * 0.125f : -1e30f;
    }
    float m = sc[0];
#pragma unroll
    for (int jj = 1; jj < WW + 2; jj++) m = fmaxf(m, sc[jj]);
    float sum = 0.f;
#pragma unroll
    for (int jj = 0; jj < WW + 2; jj++) { sc[jj] = expf(sc[jj] - m); sum += sc[jj]; }
    float inv = 1.f / sum;
    float o0 = 0.f, o1 = 0.f;
#pragma unroll
    for (int jj = 0; jj < WW + 2; jj++) {
        int j = jlo + jj;
        int jc = (j <= jhi) ? j : jlo;
        const float* vp = qkv + ((size_t)(b * S2S + jc)) * LDA + qoff + 2 * DD + h * DKK;
        o0 += sc[jj] * vp[lane];
        o1 += sc[jj] * vp[lane + 32];
    }
    size_t op = ((size_t)(b * SS + i)) * DD + h * DKK;
    __nv_bfloat16 hh, ll;
    split2(o0 * inv, hh, ll); oh[op + lane] = hh; ol[op + lane] = ll;
    split2(o1 * inv, hh, ll); oh[op + lane + 32] = hh; ol[op + lane + 32] = ll;
}

// ================= fused split-bf16 GEMM with fused epilogues ==============
// mainloop: Ah*Bh + Ah*Bl + Al*Bh; 128x128 tile, BK=32, K=512 fixed (NC=16),
// 3-stage cp.async distance-2. Mainloop order (visibility-correct):
//   CP_WAIT(1) -> __syncthreads -> prefetch(t+2) -> compute(t)
// Co-resident CTAs start the circular K loop at chunk parity*8 (de-phase).
// 96KB smem -> 2 CTAs/SM.
#define KK     512
#define NCK    16                      // KK/32
#define TILEB  (128 * 64)              // 8192 B per tile (128 rows x 64 B)
#define STG4   (4 * TILEB)             // 32768 B per stage
#define GSMEM3 (3 * STG4)              // 98304 B
#define SWZOFF(row, chunk) ((uint32_t)((row) * 64 + (((chunk) ^ (((row) >> 1) & 3)) << 4)))

struct GArg {
    const __nv_bfloat16 *ah, *al, *bh, *bl;
    const float* bias;
    float* c;
    const float* xin;          // mode 1
    const float* relw;         // mode 2
    __nv_bfloat16 *dh, *dl;    // modes 1,2 (optional in 1)
    int mode, base, lddc;
};

__global__ __launch_bounds__(256, 2) void gemm3(
    GArg ga0, GArg ga1, int M, int N)
{
    extern __shared__ char smem[];
    uint32_t sb = smem_u32(smem);
    const GArg g = blockIdx.z ? ga1 : ga0;
    const int tid = threadIdx.x, wid = tid >> 5, lane = tid & 31;
    const int row0 = blockIdx.y * 128, col0 = blockIdx.x * 128;
    const int wm = (wid >> 2) * 64;      // 0 or 64
    const int wn = (wid & 3) * 32;       // 0,32,64,96

    // de-phase co-resident CTAs: start circular K loop at chunk 0 or 8
    const int c0 = ((blockIdx.x + blockIdx.y + blockIdx.z) & 1) * (NCK / 2);

    // ---- load-side precompute (affine in kb) ----
    const int lr = tid >> 2, lkc = tid & 3;
    const uint32_t s0 = SWZOFF(lr, lkc);
    const uint32_t s1 = SWZOFF(lr + 64, lkc);
    const uint32_t aIdx0 = (uint32_t)(row0 + lr) * (uint32_t)KK + lkc * 8;
    const uint32_t aIdx1 = aIdx0 + (uint32_t)(64 * KK);
    const uint32_t bIdx0 = (uint32_t)(col0 + lr) * (uint32_t)KK + lkc * 8;
    const uint32_t bIdx1 = bIdx0 + (uint32_t)(64 * KK);

    // ---- compute-side ldsm offsets (loop-invariant; ks=1 -> ^32) ----
    uint32_t offA[4], offB[2];
#pragma unroll
    for (int im = 0; im < 4; im++) {
        int row = wm + im * 16 + (lane & 15);
        offA[im] = SWZOFF(row, (lane >> 4));
    }
    {
        int m = lane >> 3;
#pragma unroll
        for (int p = 0; p < 2; p++) {
            int row = wn + (2 * p + (m >> 1)) * 8 + (lane & 7);
            offB[p] = SWZOFF(row, (m & 1));
        }
    }

#define KB_OF(t) ((uint32_t)(((t) + c0) & (NCK - 1)) << 5)
#define LOAD_STAGE(st, kb) do {                                        \
        uint32_t _b = sb + (uint32_t)(st) * STG4;                      \
        uint32_t _k = (uint32_t)(kb);                                  \
        CP_A16(_b + s0,             g.ah + aIdx0 + _k);                \
        CP_A16(_b + s1,             g.ah + aIdx1 + _k);                \
        CP_A16(_b + TILEB + s0,     g.al + aIdx0 + _k);                \
        CP_A16(_b + TILEB + s1,     g.al + aIdx1 + _k);                \
        CP_A16(_b + 2 * TILEB + s0, g.bh + bIdx0 + _k);                \
        CP_A16(_b + 2 * TILEB + s1, g.bh + bIdx1 + _k);                \
        CP_A16(_b + 3 * TILEB + s0, g.bl + bIdx0 + _k);                \
        CP_A16(_b + 3 * TILEB + s1, g.bl + bIdx1 + _k);                \
        CP_COMMIT();                                                   \
    } while (0)

    LOAD_STAGE(0, KB_OF(0));
    LOAD_STAGE(1, KB_OF(1));

    float d[16][4];
#pragma unroll
    for (int i = 0; i < 16; i++)
#pragma unroll
        for (int j = 0; j < 4; j++) d[i][j] = 0.f;

    int st = 0;
    for (int t = 0; t < NCK; t++) {
        if (t + 1 < NCK) { CP_WAIT(1); } else { CP_WAIT(0); }
        __syncthreads();                 // all threads' group-t data visible
        if (t + 2 < NCK) {
            int st2 = st + 2; if (st2 >= 3) st2 -= 3;
            LOAD_STAGE(st2, KB_OF(t + 2));
        } else {
            CP_COMMIT();                 // keep group count consistent
        }
        uint32_t abh = sb + (uint32_t)st * STG4;
        uint32_t abl = abh + TILEB;
        uint32_t bbh = abh + 2 * TILEB;
        uint32_t bbl = abh + 3 * TILEB;
#pragma unroll
        for (int ks = 0; ks < 2; ks++) {
            const uint32_t kx = (uint32_t)(ks << 5);
            uint32_t ah[4][4], al[4][4], bh[4][2], bl[4][2];
#pragma unroll
            for (int im = 0; im < 4; im++) {
                uint32_t off = offA[im] ^ kx;
                ldsm_x4(ah[im][0], ah[im][1], ah[im][2], ah[im][3], abh + off);
                ldsm_x4(al[im][0], al[im][1], al[im][2], al[im][3], abl + off);
            }
#pragma unroll
            for (int p = 0; p < 2; p++) {
                uint32_t off = offB[p] ^ kx;
                ldsm_x4(bh[2 * p][0], bh[2 * p][1], bh[2 * p + 1][0], bh[2 * p + 1][1], bbh + off);
                ldsm_x4(bl[2 * p][0], bl[2 * p][1], bl[2 * p + 1][0], bl[2 * p + 1][1], bbl + off);
            }
#pragma unroll
            for (int im = 0; im < 4; im++)
#pragma unroll
                for (int in = 0; in < 4; in++) {
                    float* dd = d[im * 4 + in];
                    mma16816(dd, ah[im], bh[in]);
                    mma16816(dd, ah[im], bl[in]);
                    mma16816(dd, al[im], bh[in]);
                }
        }
        st++; if (st >= 3) st = 0;
    }
#undef LOAD_STAGE
#undef KB_OF

    // ================= epilogues =================
    if (g.mode == 0) {
#pragma unroll
        for (int im = 0; im < 4; im++)
#pragma unroll
            for (int in = 0; in < 4; in++) {
                float* dd = d[im * 4 + in];
                int m = row0 + wm + im * 16 + (lane >> 2);
                int n = col0 + wn + in * 8 + ((lane & 3) << 1);
                float b0 = g.bias[n], b1 = g.bias[n + 1];
                *(float2*)&g.c[(size_t)m * N + n] = make_float2(dd[0] + b0, dd[1] + b1);
                *(float2*)&g.c[(size_t)(m + 8) * N + n] = make_float2(dd[2] + b0, dd[3] + b1);
            }
    } else if (g.mode == 2) {
        float w[WW + 1];
#pragma unroll
        for (int j = 0; j <= WW; j++) w[j] = g.relw[j];
#pragma unroll
        for (int im = 0; im < 4; im++)
#pragma unroll
            for (int in = 0; in < 4; in++) {
                float* dd = d[im * 4 + in];
                int m = row0 + wm + im * 16 + (lane >> 2);
                int n = col0 + wn + in * 8 + ((lane & 3) << 1);
                int b = m >> 10, i = m & 1023;
                const float* np = g_nin + ((size_t)(b * S2S + g.base + i)) * DD + n;
                float b0 = g.bias[n], b1 = g.bias[n + 1];
                float y0 = dd[0] + b0, y1 = dd[1] + b1;
                float y2 = dd[2] + b0, y3 = dd[3] + b1;
#pragma unroll
                for (int j = 0; j <= WW; j++) {
                    float2 v = *(const float2*)(np + (size_t)j * DD);
                    float2 v2 = *(const float2*)(np + (size_t)(j + 8) * DD);
                    y0 += w[j] * v.x;  y1 += w[j] * v.y;
                    y2 += w[j] * v2.x; y3 += w[j] * v2.y;
                }
                *(float2*)&g.c[(size_t)m * DD + n] = make_float2(y0, y1);
                *(float2*)&g.c[(size_t)(m + 8) * DD + n] = make_float2(y2, y3);
                __nv_bfloat16 h0, l0, h1, l1;
                split2(y0, h0, l0); split2(y1, h1, l1);
                *(__nv_bfloat162*)&g.dh[(size_t)m * DD + n] = __nv_bfloat162(h0, h1);
                *(__nv_bfloat162*)&g.dl[(size_t)m * DD + n] = __nv_bfloat162(l0, l1);
                split2(y2, h0, l0); split2(y3, h1, l1);
                *(__nv_bfloat162*)&g.dh[(size_t)(m + 8) * DD + n] = __nv_bfloat162(h0, h1);
                *(__nv_bfloat162*)&g.dl[(size_t)(m + 8) * DD + n] = __nv_bfloat162(l0, l1);
            }
    } else {  // mode 1: highway gate
#pragma unroll
        for (int im = 0; im < 4; im++)
#pragma unroll
            for (int in = 0; in < 4; in++) {
                float* dd = d[im * 4 + in];
                int m = row0 + wm + im * 16 + (lane >> 2);
                int n = col0 + wn + in * 8 + ((lane & 3) << 1);
                int u = n >> 1;
                float b0 = g.bias[n], b1 = g.bias[n + 1];
                float nl0 = fmaxf(dd[0] + b0, 0.f);
                float gz0 = dd[1] + b1;
                float nl1 = fmaxf(dd[2] + b0, 0.f);
                float gz1 = dd[3] + b1;
                float x0 = g.xin[(size_t)m * DD + u];
                float x1 = g.xin[(size_t)(m + 8) * DD + u];
                float s0g = 1.f / (1.f + expf(-gz0));
                float s1g = 1.f / (1.f + expf(-gz1));
                float y0 = s0g * x0 + (1.f - s0g) * nl0;
                float y1 = s1g * x1 + (1.f - s1g) * nl1;
                g.c[(size_t)m * g.lddc + u] = y0;
                g.c[(size_t)(m + 8) * g.lddc + u] = y1;
                if (g.dh) {
                    __nv_bfloat16 h, l;
                    split2(y0, h, l);
                    g.dh[(size_t)m * DD + u] = h; g.dl[(size_t)m * DD + u] = l;
                    split2(y1, h, l);
                    g.dh[(size_t)(m + 8) * DD + u] = h; g.dl[(size_t)(m + 8) * DD + u] = l;
                }
            }
    }
}

// ================= launch =================
extern "C" void kernel_launch(void* const* d_in, const int* in_sizes, int n_in,
                              void* d_out, int out_size)
{
    const float* x    = (const float*)d_in[0];
    const float* lW   = (const float*)d_in[1];
    const float* lb   = (const float*)d_in[2];
    const float* rW   = (const float*)d_in[3];
    const float* rb   = (const float*)d_in[4];
    const float* lpad = (const float*)d_in[5];
    const float* rpad = (const float*)d_in[6];
    const float* lw   = (const float*)d_in[7];
    const float* rw   = (const float*)d_in[8];
    const float* lhW  = (const float*)d_in[9];
    const float* lhb  = (const float*)d_in[10];
    const float* rhW  = (const float*)d_in[11];
    const float* rhb  = (const float*)d_in[12];
    float* out = (float*)d_out;

    cudaFuncSetAttribute(gemm3, cudaFuncAttributeMaxDynamicSharedMemorySize, GSMEM3);

    float *qkv, *bqkv, *bhw, *hx0, *hx1;
    __nv_bfloat16 *ninh, *ninl, *a0h, *a0l, *a1h, *a1l;
    __nv_bfloat16 *hx0h, *hx0l, *hx1h, *hx1l;
    __nv_bfloat16 *hy0h, *hy0l, *hy1h, *hy1l, *wth, *wtl;
    cudaGetSymbolAddress((void**)&qkv, g_qkv);
    cudaGetSymbolAddress((void**)&bqkv, g_bqkv);
    cudaGetSymbolAddress((void**)&bhw, g_bhw);
    cudaGetSymbolAddress((void**)&hx0, g_hx0); cudaGetSymbolAddress((void**)&hx1, g_hx1);
    cudaGetSymbolAddress((void**)&ninh, g_ninh); cudaGetSymbolAddress((void**)&ninl, g_ninl);
    cudaGetSymbolAddress((void**)&a0h, g_a0h); cudaGetSymbolAddress((void**)&a0l, g_a0l);
    cudaGetSymbolAddress((void**)&a1h, g_a1h); cudaGetSymbolAddress((void**)&a1l, g_a1l);
    cudaGetSymbolAddress((void**)&hx0h, g_hx0h); cudaGetSymbolAddress((void**)&hx0l, g_hx0l);
    cudaGetSymbolAddress((void**)&hx1h, g_hx1h); cudaGetSymbolAddress((void**)&hx1l, g_hx1l);
    cudaGetSymbolAddress((void**)&hy0h, g_hy0h); cudaGetSymbolAddress((void**)&hy0l, g_hy0l);
    cudaGetSymbolAddress((void**)&hy1h, g_hy1h); cudaGetSymbolAddress((void**)&hy1l, g_hy1l);
    cudaGetSymbolAddress((void**)&wth, g_wth); cudaGetSymbolAddress((void**)&wtl, g_wtl);

    wsplit_all<<<4096, dim3(32, 8)>>>(lW, rW, lhW, rhW);
    pack_bias<<<28, 256>>>(lb, rb, lhb, rhb);
    build_new_in<<<(BB * S2S * DD + 255) / 256, 256>>>(x, lpad, rpad);

    // fused QKV: M=8320, N=3072, K=512 (mode 0)
    {
        GArg a = {ninh, ninl, wth, wtl, bqkv, qkv,
                  nullptr, nullptr, nullptr, nullptr, 0, 0, 0};
        gemm3<<<dim3(24, 65, 1), 256, GSMEM3>>>(a, a, BB * S2S, 6 * DD);
    }

    // banded attention (both dirs)
    banded_attn_f<<<dim3((BB * SS * HH * 32) / 256, 1, 2), 256>>>(qkv, a0h, a0l, a1h, a1l);

    // output projections + fused rel-add (mode 2)
    {
        GArg p0 = {a0h, a0l, wth + 6 * (size_t)DW, wtl + 6 * (size_t)DW, lb + 3 * DD, hx0,
                   nullptr, lw, hx0h, hx0l, 2, 0, DD};
        GArg p1 = {a1h, a1l, wth + 7 * (size_t)DW, wtl + 7 * (size_t)DW, rb + 3 * DD, hx1,
                   nullptr, rw, hx1h, hx1l, 2, WW, DD};
        gemm3<<<dim3(4, 64, 2), 256, GSMEM3>>>(p0, p1, BB * SS, DD);
    }

    // highway layer 1 (mode 1, gate fused)
    {
        GArg h0 = {hx0h, hx0l, wth + HWO, wtl + HWO, bhw + 0, hx0,
                   hx0, nullptr, hy0h, hy0l, 1, 0, DD};
        GArg h1 = {hx1h, hx1l, wth + HWO + 2 * (size_t)DW2, wtl + HWO + 2 * (size_t)DW2, bhw + 2 * 2 * DD, hx1,
                   hx1, nullptr, hy1h, hy1l, 1, 0, DD};
        gemm3<<<dim3(8, 64, 2), 256, GSMEM3>>>(h0, h1, BB * SS, 2 * DD);
    }
    // highway layer 2 (mode 1) -> strided output
    {
        GArg h0 = {hy0h, hy0l, wth + HWO + (size_t)DW2, wtl + HWO + (size_t)DW2, bhw + 1 * 2 * DD, out + 0,
                   hx0, nullptr, nullptr, nullptr, 1, 0, 2 * DD};
        GArg h1 = {hy1h, hy1l, wth + HWO + 3 * (size_t)DW2, wtl + HWO + 3 * (size_t)DW2, bhw + 3 * 2 * DD, out + DD,
                   hx1, nullptr, nullptr, nullptr, 1, 0, 2 * DD};
        gemm3<<<dim3(8, 64, 2), 256, GSMEM3>>>(h0, h1, BB * SS, 2 * DD);
    }
}

// round 15
// speedup vs baseline: 2.8667x; 1.0156x over previous
#include <cuda_runtime.h>
#include <cuda_bf16.h>
#include <math.h>
#include <stdint.h>

#define BB   8
#define SS   1024
#define DD   512
#define HH   8
#define WW   8
#define S2S  1040
#define DKK  64

// ================= helpers =================
__device__ __forceinline__ uint32_t smem_u32(const void* p) {
    uint32_t a;
    asm("{ .reg .u64 t; cvta.to.shared.u64 t, %1; cvt.u32.u64 %0, t; }" : "=r"(a) : "l"(p));
    return a;
}
#define CP_A16(dst, src) \
    asm volatile("cp.async.cg.shared.global [%0], [%1], 16;" :: "r"((uint32_t)(dst)), "l"(src))
#define CP_COMMIT() asm volatile("cp.async.commit_group;" ::: "memory")
#define CP_WAIT(n)  asm volatile("cp.async.wait_group %0;" :: "n"(n) : "memory")

__device__ __forceinline__ void ldsm_x4(uint32_t& r0, uint32_t& r1, uint32_t& r2, uint32_t& r3, uint32_t addr) {
    asm volatile("ldmatrix.sync.aligned.m8n8.x4.shared.b16 {%0,%1,%2,%3}, [%4];"
                 : "=r"(r0), "=r"(r1), "=r"(r2), "=r"(r3) : "r"(addr));
}
__device__ __forceinline__ void mma16816(float* d, const uint32_t* a, const uint32_t* b) {
    asm volatile("mma.sync.aligned.m16n8k16.row.col.f32.bf16.bf16.f32 "
                 "{%0,%1,%2,%3}, {%4,%5,%6,%7}, {%8,%9}, {%0,%1,%2,%3};"
                 : "+f"(d[0]), "+f"(d[1]), "+f"(d[2]), "+f"(d[3])
                 : "r"(a[0]), "r"(a[1]), "r"(a[2]), "r"(a[3]), "r"(b[0]), "r"(b[1]));
}
__device__ __forceinline__ void split2(float x, __nv_bfloat16& h, __nv_bfloat16& l) {
    h = __float2bfloat16(x);
    l = __float2bfloat16(x - __bfloat162float(h));
}

// ================= scratch (device globals) =================
#define DW   (DD * DD)
#define DW2  (DD * 2 * DD)
#define HWO  (8 * DW)
__device__ float g_nin[BB * S2S * DD];
__device__ __nv_bfloat16 g_ninh[BB * S2S * DD];
__device__ __nv_bfloat16 g_ninl[BB * S2S * DD];
__device__ float g_qkv[BB * S2S * 6 * DD];                // fused QKV output (lda=3072)
__device__ float g_bqkv[6 * DD];
__device__ float g_bhw[4 * 2 * DD];                       // interleaved hw biases
__device__ __nv_bfloat16 g_a0h[BB * SS * DD], g_a0l[BB * SS * DD];
__device__ __nv_bfloat16 g_a1h[BB * SS * DD], g_a1l[BB * SS * DD];
__device__ float g_hx0[BB * SS * DD], g_hx1[BB * SS * DD];
__device__ __nv_bfloat16 g_hx0h[BB * SS * DD], g_hx0l[BB * SS * DD];
__device__ __nv_bfloat16 g_hx1h[BB * SS * DD], g_hx1l[BB * SS * DD];
__device__ __nv_bfloat16 g_hy0h[BB * SS * DD], g_hy0l[BB * SS * DD];
__device__ __nv_bfloat16 g_hy1h[BB * SS * DD], g_hy1l[BB * SS * DD];
__device__ __nv_bfloat16 g_wth[8 * DW + 4 * DW2];
__device__ __nv_bfloat16 g_wtl[8 * DW + 4 * DW2];

// ================= single prep launch: wsplit + bias pack + new_in =========
// blocks [0,4096): weight transpose+split (256 thr; tx=tid&31, ty=tid>>5)
// blocks [4096,4124): bias packing (28 * 256 = 7168 elements)
// blocks [4124,20764): new_in build (16640 * 256 = BB*S2S*DD elements)
#define PREP_W    4096
#define PREP_B    28
#define PREP_N    16640
__global__ void prep_all(const float* __restrict__ lW, const float* __restrict__ rW,
                         const float* __restrict__ lhW, const float* __restrict__ rhW,
                         const float* __restrict__ lb, const float* __restrict__ rb,
                         const float* __restrict__ lhb, const float* __restrict__ rhb,
                         const float* __restrict__ x, const float* __restrict__ lp,
                         const float* __restrict__ rp) {
    __shared__ float tile[32][33];
    int blk = blockIdx.x;
    int tid = threadIdx.x;
    if (blk < PREP_W) {
        const float* W;
        __nv_bfloat16 *th, *tl;
        int nb, kb, N;
        bool hw = false;
        if (blk < 2048) {
            int mat = blk >> 8;          // 0..7
            int t = blk & 255;
            N = 512;
            nb = (t & 15) * 32; kb = (t >> 4) * 32;
            int slot;
            if (mat < 4) { W = lW + (size_t)mat * DW; slot = (mat < 3) ? mat : 6; }
            else         { int i = mat - 4; W = rW + (size_t)i * DW; slot = (i < 3) ? 3 + i : 7; }
            th = g_wth + (size_t)slot * DW;
            tl = g_wtl + (size_t)slot * DW;
        } else {
            hw = true;
            int bb = blk - 2048;
            int mat = bb >> 9;           // 0..3  (lh0, lh1, rh0, rh1)
            int t = bb & 511;
            N = 1024;
            nb = (t & 31) * 32; kb = (t >> 5) * 32;
            W = (mat < 2) ? lhW + (size_t)mat * DW2 : rhW + (size_t)(mat - 2) * DW2;
            th = g_wth + HWO + (size_t)mat * DW2;
            tl = g_wtl + HWO + (size_t)mat * DW2;
        }
        int tx = tid & 31, ty = tid >> 5;
        for (int r = ty; r < 32; r += 8)
            tile[r][tx] = W[(size_t)(kb + r) * N + nb + tx];
        __syncthreads();
        for (int r = ty; r < 32; r += 8) {
            float v = tile[tx][r];
            __nv_bfloat16 h, l; split2(v, h, l);
            int nrow = nb + r;
            int p = hw ? ((nrow < DD) ? 2 * nrow : 2 * (nrow - DD) + 1) : nrow;
            size_t o = (size_t)p * 512 + kb + tx;
            th[o] = h; tl[o] = l;
        }
    } else if (blk < PREP_W + PREP_B) {
        int n = (blk - PREP_W) * 256 + tid;
        if (n < 6 * DD) {
            int slot = n >> 9, loc = n & 511;
            g_bqkv[n] = (slot < 3) ? lb[slot * DD + loc] : rb[(slot - 3) * DD + loc];
        } else if (n < 6 * DD + 4 * 2 * DD) {
            int j = n - 6 * DD;
            int mat = j >> 10, p = j & 1023;
            int orig = (p & 1) ? DD + (p >> 1) : (p >> 1);
            g_bhw[mat * 2 * DD + p] = (mat < 2) ? lhb[mat * 2 * DD + orig]
                                                : rhb[(mat - 2) * 2 * DD + orig];
        }
    } else {
        int idx = (blk - PREP_W - PREP_B) * 256 + tid;
        int d = idx & (DD - 1);
        int t = idx >> 9;
        int s = t % S2S;
        int b = t / S2S;
        float val;
        if (s < WW)            val = lp[s * DD + d];
        else if (s < WW + SS)  val = x[((size_t)(b * SS + (s - WW))) * DD + d];
        else                   val = rp[(s - WW - SS) * DD + d];
        g_nin[idx] = val;
        __nv_bfloat16 h, l; split2(val, h, l);
        g_ninh[idx] = h; g_ninl[idx] = l;
    }
}

// fused-QKV banded attention; blockIdx.z = dir. i-fastest warp mapping.
__global__ void banded_attn_f(const float* __restrict__ qkv,
                              __nv_bfloat16* __restrict__ o0h, __nv_bfloat16* __restrict__ o0l,
                              __nv_bfloat16* __restrict__ o1h, __nv_bfloat16* __restrict__ o1l) {
    int dir = blockIdx.z;
    __nv_bfloat16* oh = dir ? o1h : o0h;
    __nv_bfloat16* ol = dir ? o1l : o0l;
    int qoff = dir * 3 * DD;
    int gw = (blockIdx.x * blockDim.x + threadIdx.x) >> 5;
    if (gw >= BB * SS * HH) return;
    int lane = threadIdx.x & 31;
    int i = gw & (SS - 1);
    int h = (gw >> 10) & (HH - 1);
    int b = gw >> 13;
    int qi = i + WW;
    int jlo, jhi;
    if (dir == 0) { jlo = qi - (WW + 1); if (jlo < 0) jlo = 0; jhi = qi; }
    else          { jlo = qi; jhi = qi + (WW + 1); if (jhi > S2S - 1) jhi = S2S - 1; }

    const int LDA = 6 * DD;
    const float* qp = qkv + ((size_t)(b * S2S + qi)) * LDA + qoff + h * DKK;
    float q0 = qp[lane], q1 = qp[lane + 32];

    float sc[WW + 2];
#pragma unroll
    for (int jj = 0; jj < WW + 2; jj++) {
        int j = jlo + jj;
        bool valid = (j <= jhi);
        int jc = valid ? j : jlo;
        const float* kp = qkv + ((size_t)(b * S2S + jc)) * LDA + qoff + DD + h * DKK;
        float s = q0 * kp[lane] + q1 * kp[lane + 32];
#pragma unroll
        for (int o = 16; o; o >>= 1) s += __shfl_xor_sync(0xffffffffu, s, o);
        sc[jj] = valid ? s * 0.125f : -1e30f;
    }
    float m = sc[0];
#pragma unroll
    for (int jj = 1; jj < WW + 2; jj++) m = fmaxf(m, sc[jj]);
    float sum = 0.f;
#pragma unroll
    for (int jj = 0; jj < WW + 2; jj++) { sc[jj] = expf(sc[jj] - m); sum += sc[jj]; }
    float inv = 1.f / sum;
    float o0 = 0.f, o1 = 0.f;
#pragma unroll
    for (int jj = 0; jj < WW + 2; jj++) {
        int j = jlo + jj;
        int jc = (j <= jhi) ? j : jlo;
        const float* vp = qkv + ((size_t)(b * S2S + jc)) * LDA + qoff + 2 * DD + h * DKK;
        o0 += sc[jj] * vp[lane];
        o1 += sc[jj] * vp[lane + 32];
    }
    size_t op = ((size_t)(b * SS + i)) * DD + h * DKK;
    __nv_bfloat16 hh, ll;
    split2(o0 * inv, hh, ll); oh[op + lane] = hh; ol[op + lane] = ll;
    split2(o1 * inv, hh, ll); oh[op + lane + 32] = hh; ol[op + lane + 32] = ll;
}

// ================= fused split-bf16 GEMM with fused epilogues ==============
// mainloop: Ah*Bh + Ah*Bl + Al*Bh; 128x128 tile, BK=32, K=512 fixed (NC=16),
// 3-stage cp.async distance-2; CP_WAIT(1) -> sync -> prefetch -> compute.
// MMA passes issued as three full (im,in) sweeps: each accumulator's reuse
// is spaced by 15 independent MMAs (per-accumulator FP order unchanged).
// Co-resident CTAs start the circular K loop at chunk parity*8 (de-phase).
// 96KB smem -> 2 CTAs/SM.
#define KK     512
#define NCK    16                      // KK/32
#define TILEB  (128 * 64)              // 8192 B per tile (128 rows x 64 B)
#define STG4   (4 * TILEB)             // 32768 B per stage
#define GSMEM3 (3 * STG4)              // 98304 B
#define SWZOFF(row, chunk) ((uint32_t)((row) * 64 + (((chunk) ^ (((row) >> 1) & 3)) << 4)))

struct GArg {
    const __nv_bfloat16 *ah, *al, *bh, *bl;
    const float* bias;
    float* c;
    const float* xin;          // mode 1
    const float* relw;         // mode 2
    __nv_bfloat16 *dh, *dl;    // modes 1,2 (optional in 1)
    int mode, base, lddc;
};

__global__ __launch_bounds__(256, 2) void gemm3(
    GArg ga0, GArg ga1, int M, int N)
{
    extern __shared__ char smem[];
    uint32_t sb = smem_u32(smem);
    const GArg g = blockIdx.z ? ga1 : ga0;
    const int tid = threadIdx.x, wid = tid >> 5, lane = tid & 31;
    const int row0 = blockIdx.y * 128, col0 = blockIdx.x * 128;
    const int wm = (wid >> 2) * 64;      // 0 or 64
    const int wn = (wid & 3) * 32;       // 0,32,64,96

    // de-phase co-resident CTAs: start circular K loop at chunk 0 or 8
    const int c0 = ((blockIdx.x + blockIdx.y + blockIdx.z) & 1) * (NCK / 2);

    // ---- load-side precompute (affine in kb) ----
    const int lr = tid >> 2, lkc = tid & 3;
    const uint32_t s0 = SWZOFF(lr, lkc);
    const uint32_t s1 = SWZOFF(lr + 64, lkc);
    const uint32_t aIdx0 = (uint32_t)(row0 + lr) * (uint32_t)KK + lkc * 8;
    const uint32_t aIdx1 = aIdx0 + (uint32_t)(64 * KK);
    const uint32_t bIdx0 = (uint32_t)(col0 + lr) * (uint32_t)KK + lkc * 8;
    const uint32_t bIdx1 = bIdx0 + (uint32_t)(64 * KK);

    // ---- compute-side ldsm offsets (loop-invariant; ks=1 -> ^32) ----
    uint32_t offA[4], offB[2];
#pragma unroll
    for (int im = 0; im < 4; im++) {
        int row = wm + im * 16 + (lane & 15);
        offA[im] = SWZOFF(row, (lane >> 4));
    }
    {
        int m = lane >> 3;
#pragma unroll
        for (int p = 0; p < 2; p++) {
            int row = wn + (2 * p + (m >> 1)) * 8 + (lane & 7);
            offB[p] = SWZOFF(row, (m & 1));
        }
    }

#define KB_OF(t) ((uint32_t)(((t) + c0) & (NCK - 1)) << 5)
#define LOAD_STAGE(st, kb) do {                                        \
        uint32_t _b = sb + (uint32_t)(st) * STG4;                      \
        uint32_t _k = (uint32_t)(kb);                                  \
        CP_A16(_b + s0,             g.ah + aIdx0 + _k);                \
        CP_A16(_b + s1,             g.ah + aIdx1 + _k);                \
        CP_A16(_b + TILEB + s0,     g.al + aIdx0 + _k);                \
        CP_A16(_b + TILEB + s1,     g.al + aIdx1 + _k);                \
        CP_A16(_b + 2 * TILEB + s0, g.bh + bIdx0 + _k);                \
        CP_A16(_b + 2 * TILEB + s1, g.bh + bIdx1 + _k);                \
        CP_A16(_b + 3 * TILEB + s0, g.bl + bIdx0 + _k);                \
        CP_A16(_b + 3 * TILEB + s1, g.bl + bIdx1 + _k);                \
        CP_COMMIT();                                                   \
    } while (0)

    LOAD_STAGE(0, KB_OF(0));
    LOAD_STAGE(1, KB_OF(1));

    float d[16][4];
#pragma unroll
    for (int i = 0; i < 16; i++)
#pragma unroll
        for (int j = 0; j < 4; j++) d[i][j] = 0.f;

    int st = 0;
    for (int t = 0; t < NCK; t++) {
        if (t + 1 < NCK) { CP_WAIT(1); } else { CP_WAIT(0); }
        __syncthreads();                 // all threads' group-t data visible
        if (t + 2 < NCK) {
            int st2 = st + 2; if (st2 >= 3) st2 -= 3;
            LOAD_STAGE(st2, KB_OF(t + 2));
        } else {
            CP_COMMIT();                 // keep group count consistent
        }
        uint32_t abh = sb + (uint32_t)st * STG4;
        uint32_t abl = abh + TILEB;
        uint32_t bbh = abh + 2 * TILEB;
        uint32_t bbl = abh + 3 * TILEB;
#pragma unroll
        for (int ks = 0; ks < 2; ks++) {
            const uint32_t kx = (uint32_t)(ks << 5);
            uint32_t ah[4][4], al[4][4], bh[4][2], bl[4][2];
#pragma unroll
            for (int im = 0; im < 4; im++) {
                uint32_t off = offA[im] ^ kx;
                ldsm_x4(ah[im][0], ah[im][1], ah[im][2], ah[im][3], abh + off);
                ldsm_x4(al[im][0], al[im][1], al[im][2], al[im][3], abl + off);
            }
#pragma unroll
            for (int p = 0; p < 2; p++) {
                uint32_t off = offB[p] ^ kx;
                ldsm_x4(bh[2 * p][0], bh[2 * p][1], bh[2 * p + 1][0], bh[2 * p + 1][1], bbh + off);
                ldsm_x4(bl[2 * p][0], bl[2 * p][1], bl[2 * p + 1][0], bl[2 * p + 1][1], bbl + off);
            }
            // three sweeps: accumulator reuse spaced by 15 independent MMAs;
            // per-accumulator order is still bh -> bl -> al*bh (FP-identical)
#pragma unroll
            for (int im = 0; im < 4; im++)
#pragma unroll
                for (int in = 0; in < 4; in++)
                    mma16816(d[im * 4 + in], ah[im], bh[in]);
#pragma unroll
            for (int im = 0; im < 4; im++)
#pragma unroll
                for (int in = 0; in < 4; in++)
                    mma16816(d[im * 4 + in], ah[im], bl[in]);
#pragma unroll
            for (int im = 0; im < 4; im++)
#pragma unroll
                for (int in = 0; in < 4; in++)
                    mma16816(d[im * 4 + in], al[im], bh[in]);
        }
        st++; if (st >= 3) st = 0;
    }
#undef LOAD_STAGE
#undef KB_OF

    // ================= epilogues =================
    if (g.mode == 0) {
#pragma unroll
        for (int im = 0; im < 4; im++)
#pragma unroll
            for (int in = 0; in < 4; in++) {
                float* dd = d[im * 4 + in];
                int m = row0 + wm + im * 16 + (lane >> 2);
                int n = col0 + wn + in * 8 + ((lane & 3) << 1);
                float b0 = g.bias[n], b1 = g.bias[n + 1];
                *(float2*)&g.c[(size_t)m * N + n] = make_float2(dd[0] + b0, dd[1] + b1);
                *(float2*)&g.c[(size_t)(m + 8) * N + n] = make_float2(dd[2] + b0, dd[3] + b1);
            }
    } else if (g.mode == 2) {
        float w[WW + 1];
#pragma unroll
        for (int j = 0; j <= WW; j++) w[j] = g.relw[j];
#pragma unroll
        for (int im = 0; im < 4; im++)
#pragma unroll
            for (int in = 0; in < 4; in++) {
                float* dd = d[im * 4 + in];
                int m = row0 + wm + im * 16 + (lane >> 2);
                int n = col0 + wn + in * 8 + ((lane & 3) << 1);
                int b = m >> 10, i = m & 1023;
                const float* np = g_nin + ((size_t)(b * S2S + g.base + i)) * DD + n;
                float b0 = g.bias[n], b1 = g.bias[n + 1];
                float y0 = dd[0] + b0, y1 = dd[1] + b1;
                float y2 = dd[2] + b0, y3 = dd[3] + b1;
#pragma unroll
                for (int j = 0; j <= WW; j++) {
                    float2 v = *(const float2*)(np + (size_t)j * DD);
                    float2 v2 = *(const float2*)(np + (size_t)(j + 8) * DD);
                    y0 += w[j] * v.x;  y1 += w[j] * v.y;
                    y2 += w[j] * v2.x; y3 += w[j] * v2.y;
                }
                *(float2*)&g.c[(size_t)m * DD + n] = make_float2(y0, y1);
                *(float2*)&g.c[(size_t)(m + 8) * DD + n] = make_float2(y2, y3);
                __nv_bfloat16 h0, l0, h1, l1;
                split2(y0, h0, l0); split2(y1, h1, l1);
                *(__nv_bfloat162*)&g.dh[(size_t)m * DD + n] = __nv_bfloat162(h0, h1);
                *(__nv_bfloat162*)&g.dl[(size_t)m * DD + n] = __nv_bfloat162(l0, l1);
                split2(y2, h0, l0); split2(y3, h1, l1);
                *(__nv_bfloat162*)&g.dh[(size_t)(m + 8) * DD + n] = __nv_bfloat162(h0, h1);
                *(__nv_bfloat162*)&g.dl[(size_t)(m + 8) * DD + n] = __nv_bfloat162(l0, l1);
            }
    } else {  // mode 1: highway gate
#pragma unroll
        for (int im = 0; im < 4; im++)
#pragma unroll
            for (int in = 0; in < 4; in++) {
                float* dd = d[im * 4 + in];
                int m = row0 + wm + im * 16 + (lane >> 2);
                int n = col0 + wn + in * 8 + ((lane & 3) << 1);
                int u = n >> 1;
                float b0 = g.bias[n], b1 = g.bias[n + 1];
                float nl0 = fmaxf(dd[0] + b0, 0.f);
                float gz0 = dd[1] + b1;
                float nl1 = fmaxf(dd[2] + b0, 0.f);
                float gz1 = dd[3] + b1;
                float x0 = g.xin[(size_t)m * DD + u];
                float x1 = g.xin[(size_t)(m + 8) * DD + u];
                float s0g = 1.f / (1.f + expf(-gz0));
                float s1g = 1.f / (1.f + expf(-gz1));
                float y0 = s0g * x0 + (1.f - s0g) * nl0;
                float y1 = s1g * x1 + (1.f - s1g) * nl1;
                g.c[(size_t)m * g.lddc + u] = y0;
                g.c[(size_t)(m + 8) * g.lddc + u] = y1;
                if (g.dh) {
                    __nv_bfloat16 h, l;
                    split2(y0, h, l);
                    g.dh[(size_t)m * DD + u] = h; g.dl[(size_t)m * DD + u] = l;
                    split2(y1, h, l);
                    g.dh[(size_t)(m + 8) * DD + u] = h; g.dl[(size_t)(m + 8) * DD + u] = l;
                }
            }
    }
}

// ================= launch =================
extern "C" void kernel_launch(void* const* d_in, const int* in_sizes, int n_in,
                              void* d_out, int out_size)
{
    const float* x    = (const float*)d_in[0];
    const float* lW   = (const float*)d_in[1];
    const float* lb   = (const float*)d_in[2];
    const float* rW   = (const float*)d_in[3];
    const float* rb   = (const float*)d_in[4];
    const float* lpad = (const float*)d_in[5];
    const float* rpad = (const float*)d_in[6];
    const float* lw   = (const float*)d_in[7];
    const float* rw   = (const float*)d_in[8];
    const float* lhW  = (const float*)d_in[9];
    const float* lhb  = (const float*)d_in[10];
    const float* rhW  = (const float*)d_in[11];
    const float* rhb  = (const float*)d_in[12];
    float* out = (float*)d_out;

    cudaFuncSetAttribute(gemm3, cudaFuncAttributeMaxDynamicSharedMemorySize, GSMEM3);

    float *qkv, *bqkv, *bhw, *hx0, *hx1;
    __nv_bfloat16 *ninh, *ninl, *a0h, *a0l, *a1h, *a1l;
    __nv_bfloat16 *hx0h, *hx0l, *hx1h, *hx1l;
    __nv_bfloat16 *hy0h, *hy0l, *hy1h, *hy1l, *wth, *wtl;
    cudaGetSymbolAddress((void**)&qkv, g_qkv);
    cudaGetSymbolAddress((void**)&bqkv, g_bqkv);
    cudaGetSymbolAddress((void**)&bhw, g_bhw);
    cudaGetSymbolAddress((void**)&hx0, g_hx0); cudaGetSymbolAddress((void**)&hx1, g_hx1);
    cudaGetSymbolAddress((void**)&ninh, g_ninh); cudaGetSymbolAddress((void**)&ninl, g_ninl);
    cudaGetSymbolAddress((void**)&a0h, g_a0h); cudaGetSymbolAddress((void**)&a0l, g_a0l);
    cudaGetSymbolAddress((void**)&a1h, g_a1h); cudaGetSymbolAddress((void**)&a1l, g_a1l);
    cudaGetSymbolAddress((void**)&hx0h, g_hx0h); cudaGetSymbolAddress((void**)&hx0l, g_hx0l);
    cudaGetSymbolAddress((void**)&hx1h, g_hx1h); cudaGetSymbolAddress((void**)&hx1l, g_hx1l);
    cudaGetSymbolAddress((void**)&hy0h, g_hy0h); cudaGetSymbolAddress((void**)&hy0l, g_hy0l);
    cudaGetSymbolAddress((void**)&hy1h, g_hy1h); cudaGetSymbolAddress((void**)&hy1l, g_hy1l);
    cudaGetSymbolAddress((void**)&wth, g_wth); cudaGetSymbolAddress((void**)&wtl, g_wtl);

    // all prep in one launch
    prep_all<<<PREP_W + PREP_B + PREP_N, 256>>>(lW, rW, lhW, rhW, lb, rb, lhb, rhb,
                                                x, lpad, rpad);

    // fused QKV: M=8320, N=3072, K=512 (mode 0)
    {
        GArg a = {ninh, ninl, wth, wtl, bqkv, qkv,
                  nullptr, nullptr, nullptr, nullptr, 0, 0, 0};
        gemm3<<<dim3(24, 65, 1), 256, GSMEM3>>>(a, a, BB * S2S, 6 * DD);
    }

    // banded attention (both dirs)
    banded_attn_f<<<dim3((BB * SS * HH * 32) / 256, 1, 2), 256>>>(qkv, a0h, a0l, a1h, a1l);

    // output projections + fused rel-add (mode 2)
    {
        GArg p0 = {a0h, a0l, wth + 6 * (size_t)DW, wtl + 6 * (size_t)DW, lb + 3 * DD, hx0,
                   nullptr, lw, hx0h, hx0l, 2, 0, DD};
        GArg p1 = {a1h, a1l, wth + 7 * (size_t)DW, wtl + 7 * (size_t)DW, rb + 3 * DD, hx1,
                   nullptr, rw, hx1h, hx1l, 2, WW, DD};
        gemm3<<<dim3(4, 64, 2), 256, GSMEM3>>>(p0, p1, BB * SS, DD);
    }

    // highway layer 1 (mode 1, gate fused)
    {
        GArg h0 = {hx0h, hx0l, wth + HWO, wtl + HWO, bhw + 0, hx0,
                   hx0, nullptr, hy0h, hy0l, 1, 0, DD};
        GArg h1 = {hx1h, hx1l, wth + HWO + 2 * (size_t)DW2, wtl + HWO + 2 * (size_t)DW2, bhw + 2 * 2 * DD, hx1,
                   hx1, nullptr, hy1h, hy1l, 1, 0, DD};
        gemm3<<<dim3(8, 64, 2), 256, GSMEM3>>>(h0, h1, BB * SS, 2 * DD);
    }
    // highway layer 2 (mode 1) -> strided output
    {
        GArg h0 = {hy0h, hy0l, wth + HWO + (size_t)DW2, wtl + HWO + (size_t)DW2, bhw + 1 * 2 * DD, out + 0,
                   hx0, nullptr, nullptr, nullptr, 1, 0, 2 * DD};
        GArg h1 = {hy1h, hy1l, wth + HWO + 3 * (size_t)DW2, wtl + HWO + 3 * (size_t)DW2, bhw + 3 * 2 * DD, out + DD,
                   hx1, nullptr, nullptr, nullptr, 1, 0, 2 * DD};
        gemm3<<<dim3(8, 64, 2), 256, GSMEM3>>>(h0, h1, BB * SS, 2 * DD);
    }
}